// round 10
// baseline (speedup 1.0000x reference)
#include <cuda_runtime.h>
#include <cuda_bf16.h>
#include <cstdint>
#include <cstddef>

#define SEQ 1024
#define BATCH 8
#define TOK (BATCH*SEQ)
#define DMODEL 256
#define DI 512
#define NH 4
#define DHH 128
#define NL 4

// ---------------- scratch (device globals; no allocation allowed) ----------------
__device__ float g_h[TOK*DMODEL];
__device__ float g_up[TOK*1024];
__device__ float g_giT[BATCH*NH*SEQ];
__device__ float g_gfT[BATCH*NH*SEQ];
__device__ float g_Fc[BATCH*NH*SEQ];
__device__ float g_a[BATCH*NH*SEQ];
__device__ float g_m[BATCH*NH*SEQ];
__device__ float g_wcol[BATCH*NH*SEQ];
__device__ float g_amaxT[BATCH*NH*16];
__device__ float g_Wg[NL*1024*8];

__device__ __nv_bfloat16 g_hn_bf[TOK*DMODEL];
__device__ __nv_bfloat16 g_xc_bf[TOK*DI];
__device__ __nv_bfloat16 g_up_bf[TOK*DI];
__device__ __nv_bfloat16 g_q_bf[TOK*DI];
__device__ __nv_bfloat16 g_k_bf[TOK*DI];
__device__ __nv_bfloat16 g_v_bf[TOK*DI];
__device__ __nv_bfloat16 g_att2_bf[TOK*DI];
__device__ __nv_bfloat16 g_wup_bf[NL*DMODEL*1024];
__device__ __nv_bfloat16 g_wq_bf[NL*DI*DI];
__device__ __nv_bfloat16 g_wk_bf[NL*DI*DI];
__device__ __nv_bfloat16 g_wv_bf[NL*DI*DI];
__device__ __nv_bfloat16 g_wdn_bf[NL*DI*DMODEL];

__device__ __forceinline__ float warp_sum(float v){
    #pragma unroll
    for (int o=16;o;o>>=1) v += __shfl_xor_sync(0xffffffffu, v, o);
    return v;
}

__device__ __forceinline__ uint32_t bf2pack(float x, float y){
    __nv_bfloat162 t = __floats2bfloat162_rn(x, y);
    return *(uint32_t*)&t;
}

__device__ __forceinline__ void mma_bf16(float* c, const uint32_t* a, uint32_t b0, uint32_t b1){
    asm volatile(
      "mma.sync.aligned.m16n8k16.row.col.f32.bf16.bf16.f32 "
      "{%0,%1,%2,%3}, {%4,%5,%6,%7}, {%8,%9}, {%0,%1,%2,%3};\n"
      : "+f"(c[0]), "+f"(c[1]), "+f"(c[2]), "+f"(c[3])
      : "r"(a[0]), "r"(a[1]), "r"(a[2]), "r"(a[3]), "r"(b0), "r"(b1));
}

__device__ __forceinline__ uint32_t smaddr(const void* p){
    return (uint32_t)__cvta_generic_to_shared(p);
}
#define CPA16(dst,src) asm volatile("cp.async.cg.shared.global [%0], [%1], 16;\n"::"r"(dst),"l"(src))
#define CPCOMMIT() asm volatile("cp.async.commit_group;\n")
#define CPWAIT(n) asm volatile("cp.async.wait_group %0;\n"::"n"(n))

// ---------------- merged f32 -> bf16 convert for all 5 weight tensors ----------------
__global__ void f2bf5_kernel(const float* __restrict__ i0, __nv_bfloat16* __restrict__ o0, int n0,
                             const float* __restrict__ i1, __nv_bfloat16* __restrict__ o1, int n1,
                             const float* __restrict__ i2, __nv_bfloat16* __restrict__ o2, int n2,
                             const float* __restrict__ i3, __nv_bfloat16* __restrict__ o3, int n3,
                             const float* __restrict__ i4, __nv_bfloat16* __restrict__ o4, int n4){
    int i = (blockIdx.x*blockDim.x + threadIdx.x)*2;
    const float* in; __nv_bfloat16* out;
    if (i < n0){ in=i0; out=o0; }
    else if ((i-=n0) < n1){ in=i1; out=o1; }
    else if ((i-=n1) < n2){ in=i2; out=o2; }
    else if ((i-=n2) < n3){ in=i3; out=o3; }
    else if ((i-=n3) < n4){ in=i4; out=o4; }
    else return;
    float2 v = *(const float2*)(in+i);
    *(__nv_bfloat162*)(out+i) = __floats2bfloat162_rn(v.x, v.y);
}

// ---------------- composite gate weights: Wg = [Wq@Wif_i + Wk@Wif_k ; Wv@Wif_v] ----------------
__global__ void gatew_kernel(const float* __restrict__ Wq, const float* __restrict__ Wk,
                             const float* __restrict__ Wv, const float* __restrict__ Wif,
                             float* __restrict__ Wg){
    int idx = blockIdx.x*blockDim.x + threadIdx.x;   // NL*1024*8
    int l = idx >> 13; int r = idx & 8191;
    int c = r >> 3; int j = r & 7;
    const float* Wifl = Wif + (size_t)l*1536*8;
    float acc = 0.f;
    if (c < 512){
        const float* wq = Wq + ((size_t)l*512 + c)*512;
        const float* wk = Wk + ((size_t)l*512 + c)*512;
        #pragma unroll 4
        for (int i=0;i<512;i++)
            acc += wq[i]*Wifl[i*8+j] + wk[i]*Wifl[(512+i)*8+j];
    } else {
        const float* wv = Wv + ((size_t)l*512 + (c-512))*512;
        #pragma unroll 4
        for (int i=0;i<512;i++)
            acc += wv[i]*Wifl[(1024+i)*8+j];
    }
    Wg[(size_t)l*8192 + c*8 + j] = acc;
}

// ---------------- embed ----------------
__global__ void embed_kernel(const float* __restrict__ x, const float* __restrict__ tf,
                             const float* __restrict__ Wp, const float* __restrict__ bp,
                             float* __restrict__ h){
    int idx = blockIdx.x*blockDim.x + threadIdx.x;
    int j = idx & 255; int tok = idx >> 8;
    float acc = bp[j] + x[tok]*Wp[j];
    #pragma unroll
    for (int f=0; f<4; f++) acc += tf[tok*4+f]*Wp[(1+f)*256+j];
    h[idx] = acc;
}

// ---------------- layernorm, bf16 out ----------------
__global__ void ln_kernel(const float* __restrict__ x, const float* __restrict__ g,
                          const float* __restrict__ b, __nv_bfloat16* __restrict__ y){
    int row = blockIdx.x*8 + (threadIdx.x>>5);
    int lane = threadIdx.x & 31;
    const float* xr = x + (size_t)row*256;
    float4 v0 = *(const float4*)(xr + lane*4);
    float4 v1 = *(const float4*)(xr + 128 + lane*4);
    float s = v0.x+v0.y+v0.z+v0.w + v1.x+v1.y+v1.z+v1.w;
    s = warp_sum(s);
    float mu = s * (1.f/256.f);
    float d0x=v0.x-mu, d0y=v0.y-mu, d0z=v0.z-mu, d0w=v0.w-mu;
    float d1x=v1.x-mu, d1y=v1.y-mu, d1z=v1.z-mu, d1w=v1.w-mu;
    float sq = d0x*d0x+d0y*d0y+d0z*d0z+d0w*d0w + d1x*d1x+d1y*d1y+d1z*d1z+d1w*d1w;
    sq = warp_sum(sq);
    float is = rsqrtf(sq*(1.f/256.f) + 1e-5f);
    float4 g0 = *(const float4*)(g + lane*4);
    float4 g1 = *(const float4*)(g + 128 + lane*4);
    float4 b0 = *(const float4*)(b + lane*4);
    float4 b1 = *(const float4*)(b + 128 + lane*4);
    __nv_bfloat16* yr = y + (size_t)row*256;
    *(__nv_bfloat162*)&yr[lane*4]       = __floats2bfloat162_rn(d0x*is*g0.x + b0.x, d0y*is*g0.y + b0.y);
    *(__nv_bfloat162*)&yr[lane*4+2]     = __floats2bfloat162_rn(d0z*is*g0.z + b0.z, d0w*is*g0.w + b0.w);
    *(__nv_bfloat162*)&yr[128+lane*4]   = __floats2bfloat162_rn(d1x*is*g1.x + b1.x, d1y*is*g1.y + b1.y);
    *(__nv_bfloat162*)&yr[128+lane*4+2] = __floats2bfloat162_rn(d1z*is*g1.z + b1.z, d1w*is*g1.w + b1.w);
}

// ---------------- bf16 tensor-core GEMM, cp.async double-buffered ----------------
__global__ __launch_bounds__(256) void gemm_bf16(
    const __nv_bfloat16* __restrict__ A, int lda,
    const __nv_bfloat16* __restrict__ B, int ldb,
    float* __restrict__ C, int ldc,
    const float* __restrict__ bias,
    const float* __restrict__ resid,
    int K,
    __nv_bfloat16* __restrict__ Cbf, int bfcap,
    const __nv_bfloat16* __restrict__ A2,
    const __nv_bfloat16* __restrict__ B2,
    __nv_bfloat16* __restrict__ Cbf2,
    const __nv_bfloat16* __restrict__ B3,
    __nv_bfloat16* __restrict__ Cbf3)
{
    __shared__ __nv_bfloat16 As[2][128*64];
    __shared__ __nv_bfloat16 Bs[2][64*64];
    if (blockIdx.z == 1){ B = B2; Cbf = Cbf2; }
    else if (blockIdx.z == 2){ A = A2; B = B3; Cbf = Cbf3; }
    int tid = threadIdx.x, lane = tid&31, wid = tid>>5;
    int wm = wid>>1, wn = wid&1;
    int m0 = blockIdx.y*128, n0 = blockIdx.x*64;

    int ar = tid >> 1;
    int ac0 = (tid & 1) << 2;
    int br = tid >> 2;
    int bc0 = (tid & 3) << 1;
    const __nv_bfloat16* Ag = A + (size_t)(m0+ar)*lda;
    const __nv_bfloat16* Bg = B + (size_t)br*ldb + n0;

    int KC = K >> 6;
    {
        #pragma unroll
        for (int c=0;c<4;c++){
            int ch = ac0+c;
            CPA16(smaddr(&As[0][ar*64 + ((ch ^ (ar&7))<<3)]), Ag + (ch<<3));
        }
        #pragma unroll
        for (int c=0;c<2;c++){
            int ch = bc0+c;
            CPA16(smaddr(&Bs[0][br*64 + ((ch ^ (br&7))<<3)]), Bg + (ch<<3));
        }
        CPCOMMIT();
    }

    float acc[2][4][4] = {};
    int g = lane>>3, lr = lane&7;

    for (int kc=0; kc<KC; kc++){
        int cur = kc & 1;
        if (kc+1 < KC){
            int nb = (kc+1)&1, k0 = (kc+1)<<6;
            #pragma unroll
            for (int c=0;c<4;c++){
                int ch = ac0+c;
                CPA16(smaddr(&As[nb][ar*64 + ((ch ^ (ar&7))<<3)]), Ag + k0 + (ch<<3));
            }
            #pragma unroll
            for (int c=0;c<2;c++){
                int ch = bc0+c;
                CPA16(smaddr(&Bs[nb][br*64 + ((ch ^ (br&7))<<3)]), Bg + (size_t)k0*ldb + (ch<<3));
            }
            CPCOMMIT();
            CPWAIT(1);
        } else {
            CPWAIT(0);
        }
        __syncthreads();

        #pragma unroll
        for (int ks=0; ks<4; ks++){
            uint32_t af[2][4];
            #pragma unroll
            for (int mt=0; mt<2; mt++){
                int arow = wm*32 + mt*16 + lr + ((g&1)<<3);
                int ch = (ks<<1) + (g>>1);
                uint32_t addr = smaddr(&As[cur][arow*64 + ((ch ^ (arow&7))<<3)]);
                asm volatile("ldmatrix.sync.aligned.m8n8.x4.shared.b16 {%0,%1,%2,%3}, [%4];\n"
                    : "=r"(af[mt][0]),"=r"(af[mt][1]),"=r"(af[mt][2]),"=r"(af[mt][3]) : "r"(addr));
            }
            uint32_t bf[4][2];
            int krow = (ks<<4) + lr + ((g&1)<<3);
            #pragma unroll
            for (int nt=0; nt<4; nt++){
                int ch = wn*4 + nt;
                uint32_t addr = smaddr(&Bs[cur][krow*64 + ((ch ^ (krow&7))<<3)]);
                asm volatile("ldmatrix.sync.aligned.m8n8.x2.trans.shared.b16 {%0,%1}, [%2];\n"
                    : "=r"(bf[nt][0]),"=r"(bf[nt][1]) : "r"(addr));
            }
            #pragma unroll
            for (int mt=0;mt<2;mt++)
              #pragma unroll
              for (int nt=0;nt<4;nt++)
                mma_bf16(acc[mt][nt], af[mt], bf[nt][0], bf[nt][1]);
        }
        __syncthreads();
    }

    #pragma unroll
    for (int mt=0;mt<2;mt++){
        #pragma unroll
        for (int nt=0;nt<4;nt++){
            int row0 = m0 + wm*32 + mt*16 + (lane>>2);
            int col  = n0 + wn*32 + nt*8 + ((lane&3)<<1);
            float bx=0.f, by=0.f;
            if (bias){ bx = bias[col]; by = bias[col+1]; }
            float2 r0v = make_float2(0.f,0.f), r1v = make_float2(0.f,0.f);
            if (resid){
                r0v = *(const float2*)&resid[(size_t)row0*ldc + col];
                r1v = *(const float2*)&resid[(size_t)(row0+8)*ldc + col];
            }
            float v00 = acc[mt][nt][0]+bx+r0v.x, v01 = acc[mt][nt][1]+by+r0v.y;
            float v10 = acc[mt][nt][2]+bx+r1v.x, v11 = acc[mt][nt][3]+by+r1v.y;
            if (C){
                *(float2*)&C[(size_t)row0*ldc + col]     = make_float2(v00, v01);
                *(float2*)&C[(size_t)(row0+8)*ldc + col] = make_float2(v10, v11);
            }
            if (Cbf && col < bfcap){
                *(__nv_bfloat162*)&Cbf[(size_t)row0*bfcap + col]     = __floats2bfloat162_rn(v00, v01);
                *(__nv_bfloat162*)&Cbf[(size_t)(row0+8)*bfcap + col] = __floats2bfloat162_rn(v10, v11);
            }
        }
    }
}

// ---------------- fused causal conv + silu + composite gates ----------------
__global__ __launch_bounds__(256) void conv_gates_kernel(
    const float* __restrict__ up, const float* __restrict__ cw, const float* __restrict__ cb,
    const float* __restrict__ Wg, const float* __restrict__ bif,
    __nv_bfloat16* __restrict__ xcbf,
    float* __restrict__ giT, float* __restrict__ gfT)
{
    __shared__ float xcs[512], xms[512];
    int tok = blockIdx.x, tid = threadIdx.x;
    int t = tok & 1023;
    #pragma unroll
    for (int r=0;r<2;r++){
        int c = tid + (r<<8);
        float xm = up[(size_t)tok*1024 + c];
        float acc = cb[c] + cw[3*512+c]*xm;
        #pragma unroll
        for (int j=0;j<3;j++){
            int ts = t - 3 + j;
            if (ts >= 0) acc += cw[j*512+c]*up[(size_t)(tok-3+j)*1024 + c];
        }
        float sv = acc/(1.f+expf(-acc));
        xcs[c] = sv; xms[c] = xm;
        xcbf[(size_t)tok*512 + c] = __float2bfloat16(sv);
    }
    __syncthreads();
    int w = tid>>5, lane = tid&31;
    float acc = 0.f;
    for (int i=lane;i<512;i+=32) acc += xcs[i]*Wg[i*8+w] + xms[i]*Wg[(512+i)*8+w];
    acc = warp_sum(acc);
    if (!lane){
        float r = acc + bif[w];
        int b = tok >> 10, s = tok & 1023;
        if (w < 4) giT[(size_t)(b*4+w)*1024 + s] = r;
        else       gfT[(size_t)(b*4+w-4)*1024 + s] = r;
    }
}

// ---------------- gate scan + per-tile col weights ----------------
__global__ void scan_kernel4(const float* __restrict__ giT, const float* __restrict__ gfT,
                             float* __restrict__ Fc, float* __restrict__ a, float* __restrict__ m,
                             float* __restrict__ wcol, float* __restrict__ amaxT){
    __shared__ float ash[1024];
    int bh = blockIdx.x, lane = threadIdx.x;
    const float* gih = giT + (size_t)bh*1024;
    const float* gfh = gfT + (size_t)bh*1024;
    const float scale = 0.08838834764831845f;
    float cfc = 0.f, cmax = -1e30f;
    float ipc = gih[lane], fpc = gfh[lane];
    for (int c=0;c<32;c++){
        float ip = ipc, fp = fpc;
        if (c+1 < 32){ ipc = gih[(c+1)*32+lane]; fpc = gfh[(c+1)*32+lane]; }
        float lf = fminf(fp, 0.f) - log1pf(expf(-fabsf(fp)));
        float x = lf;
        #pragma unroll
        for (int o=1;o<32;o<<=1){ float y = __shfl_up_sync(0xffffffffu, x, o); if (lane>=o) x += y; }
        float fc = cfc + x;
        float av = ip - fc;
        float mx = av;
        #pragma unroll
        for (int o=1;o<32;o<<=1){ float y = __shfl_up_sync(0xffffffffu, mx, o); if (lane>=o) mx = fmaxf(mx, y); }
        float cm = fmaxf(cmax, mx);
        int off = bh*SEQ + c*32 + lane;
        Fc[off] = fc; a[off] = av; m[off] = fc + cm;
        ash[c*32 + lane] = av;
        cfc += __shfl_sync(0xffffffffu, x, 31);
        cmax = fmaxf(cmax, __shfl_sync(0xffffffffu, mx, 31));
    }
    __syncwarp();
    for (int tile=0;tile<16;tile++){
        float v0 = ash[tile*64 + lane];
        float v1 = ash[tile*64 + 32 + lane];
        float mx = fmaxf(v0, v1);
        #pragma unroll
        for (int o=16;o;o>>=1) mx = fmaxf(mx, __shfl_xor_sync(0xffffffffu, mx, o));
        if (lane == 0) amaxT[bh*16 + tile] = mx;
        wcol[bh*SEQ + tile*64 + lane]      = scale*__expf(v0 - mx);
        wcol[bh*SEQ + tile*64 + 32 + lane] = scale*__expf(v1 - mx);
    }
}

// ---------------- mLSTM attention: cp.async double-buffered K/V, fused epilogue ----------------
// smem (words): P 64*36 | K[2] 64*64 | V[2] 64*64 | fct 64 | mt 64 | as2 2*64 | den2 128
// Q A-fragments loaded directly gmem->regs. K/V XOR-swizzled stride-64.
#define PW 36
__global__ __launch_bounds__(256) void attn_bf16(
    const __nv_bfloat16* __restrict__ q, const __nv_bfloat16* __restrict__ k,
    const __nv_bfloat16* __restrict__ v,
    const float* __restrict__ Fcv, const float* __restrict__ av, const float* __restrict__ mv,
    const float* __restrict__ wcol, const float* __restrict__ amaxT,
    const __nv_bfloat16* __restrict__ xcbf, const float* __restrict__ up,
    const float* __restrict__ gng, const float* __restrict__ gnb,
    const float* __restrict__ skip,
    __nv_bfloat16* __restrict__ out)
{
    extern __shared__ uint32_t smu[];
    uint32_t* Ps  = smu;                 // 2304
    uint32_t* Ks0 = smu + 2304;          // 2 x 4096
    uint32_t* Vs0 = Ks0 + 8192;          // 2 x 4096
    float* fct  = (float*)(Vs0 + 8192);  // 64
    float* mt   = fct + 64;              // 64
    float* as2  = mt + 64;               // 2 x 64
    float* den2 = as2 + 128;             // 128

    int bh = blockIdx.x; int b = bh>>2, hh = bh&3;
    int it = (int)(gridDim.y - 1) - (int)blockIdx.y;
    int t0 = it<<6;
    int tid = threadIdx.x, lane = tid&31, wid = tid>>5;
    int wm = wid>>1, wn = wid&1;
    int ls = lane>>2, lk = lane&3;
    int g8 = lane>>3, lr = lane&7;
    const float scale = 0.08838834764831845f;

    const __nv_bfloat16* kgb = k + ((size_t)(b*SEQ))*512 + hh*128;
    const __nv_bfloat16* vgb = v + ((size_t)(b*SEQ))*512 + hh*128;

    // prologue: issue tile-0 K/V cp.async
    {
        uint32_t* Kb = Ks0; uint32_t* Vb = Vs0;
        #pragma unroll
        for (int r=0;r<4;r++){
            int idx = tid + (r<<8);
            int row = idx>>4, c16 = idx&15;
            int off = row*64 + ((c16 ^ (row&7))<<2);
            CPA16(smaddr(&Kb[off]), kgb + (size_t)row*512 + (c16<<3));
            CPA16(smaddr(&Vb[off]), vgb + (size_t)row*512 + (c16<<3));
        }
        CPCOMMIT();
    }
    if (tid < 64){
        int tg = bh*SEQ + t0 + tid;
        fct[tid] = Fcv[tg]; mt[tid] = mv[tg];
        as2[tid] = (it == 0) ? av[bh*SEQ + tid] : wcol[bh*SEQ + tid];
    }

    // Q A-fragments direct from gmem (4B words, fragment layout)
    int r0 = wm*16 + ls, r1 = r0 + 8;
    const __nv_bfloat16* qg = q + ((size_t)(b*SEQ + t0))*512 + hh*128;
    uint32_t qf[8][4];
    #pragma unroll
    for (int ks=0; ks<8; ks++){
        qf[ks][0] = *(const uint32_t*)(qg + (size_t)r0*512 + ((ks*8+lk)<<1));
        qf[ks][1] = *(const uint32_t*)(qg + (size_t)r1*512 + ((ks*8+lk)<<1));
        qf[ks][2] = *(const uint32_t*)(qg + (size_t)r0*512 + ((ks*8+lk+4)<<1));
        qf[ks][3] = *(const uint32_t*)(qg + (size_t)r1*512 + ((ks*8+lk+4)<<1));
    }

    float oacc[8][4];
    #pragma unroll
    for (int i=0;i<8;i++){ oacc[i][0]=0.f; oacc[i][1]=0.f; oacc[i][2]=0.f; oacc[i][3]=0.f; }
    float den0 = 0.f, den1 = 0.f;

    for (int js=0; js<=it; js++){
        int cur = js & 1;
        CPWAIT(0);
        __syncthreads();   // tile js staged everywhere; all prior smem reads retired

        // prefetch tile js+1 into the other buffer (overlaps with compute below)
        if (js < it){
            int s1 = (js+1)<<6;
            uint32_t* Kb = Ks0 + ((cur^1)<<12);
            uint32_t* Vb = Vs0 + ((cur^1)<<12);
            const __nv_bfloat16* kg = kgb + (size_t)s1*512;
            const __nv_bfloat16* vg = vgb + (size_t)s1*512;
            #pragma unroll
            for (int r=0;r<4;r++){
                int idx = tid + (r<<8);
                int row = idx>>4, c16 = idx&15;
                int off = row*64 + ((c16 ^ (row&7))<<2);
                CPA16(smaddr(&Kb[off]), kg + (size_t)row*512 + (c16<<3));
                CPA16(smaddr(&Vb[off]), vg + (size_t)row*512 + (c16<<3));
            }
            CPCOMMIT();
            if (tid < 64)
                as2[((cur^1)<<6) + tid] = (js+1 == it) ? av[bh*SEQ + s1 + tid]
                                                       : wcol[bh*SEQ + s1 + tid];
        }

        const uint32_t* Kb = Ks0 + (cur<<12);
        const float* asl = as2 + (cur<<6);
        bool diag = (js == it);

        // ---- S = Q @ K^T ----
        float sacc[4][4] = {};
        #pragma unroll
        for (int ks=0; ks<8; ks++){
            #pragma unroll
            for (int nt=0; nt<4; nt++){
                int sc = wn*32 + nt*8 + ls;
                uint32_t b0 = Kb[sc*64 + (((2*ks  )^(sc&7))<<2) + lk];
                uint32_t b1 = Kb[sc*64 + (((2*ks+1)^(sc&7))<<2) + lk];
                mma_bf16(sacc[nt], qf[ks], b0, b1);
            }
        }

        // ---- decay weighting + denominator + P (bf16x2) ----
        float f0 = fct[r0], mm0 = mt[r0], f1 = fct[r1], mm1 = mt[r1];
        if (!diag){
            float amx = amaxT[bh*16 + js];
            float w0 = __expf(f0 - mm0 + amx);
            float w1 = __expf(f1 - mm1 + amx);
            #pragma unroll
            for (int nt=0; nt<4; nt++){
                int c0 = wn*32 + nt*8 + (lk<<1);
                float wc0 = asl[c0], wc1 = asl[c0+1];
                float v00 = sacc[nt][0]*w0*wc0;
                float v01 = sacc[nt][1]*w0*wc1;
                float v10 = sacc[nt][2]*w1*wc0;
                float v11 = sacc[nt][3]*w1*wc1;
                den0 += v00 + v01;
                den1 += v10 + v11;
                int wcl = wn*16 + nt*4 + lk;
                Ps[r0*PW + wcl] = bf2pack(v00, v01);
                Ps[r1*PW + wcl] = bf2pack(v10, v11);
            }
        } else {
            #pragma unroll
            for (int nt=0; nt<4; nt++){
                int c0 = wn*32 + nt*8 + (lk<<1);
                int c1 = c0 + 1;
                float a0v = asl[c0], a1v = asl[c1];
                float v00 = sacc[nt][0]*scale*__expf(f0 + a0v - mm0);
                float v01 = sacc[nt][1]*scale*__expf(f0 + a1v - mm0);
                float v10 = sacc[nt][2]*scale*__expf(f1 + a0v - mm1);
                float v11 = sacc[nt][3]*scale*__expf(f1 + a1v - mm1);
                if (c0 > r0) v00 = 0.f;
                if (c1 > r0) v01 = 0.f;
                if (c0 > r1) v10 = 0.f;
                if (c1 > r1) v11 = 0.f;
                den0 += v00 + v01;
                den1 += v10 + v11;
                int wcl = wn*16 + nt*4 + lk;
                Ps[r0*PW + wcl] = bf2pack(v00, v01);
                Ps[r1*PW + wcl] = bf2pack(v10, v11);
            }
        }
        // P rows of this wm-pair shared only between wn=0/1 of same wm
        asm volatile("bar.sync %0, %1;" :: "r"(wm+1), "r"(64) : "memory");

        // ---- out += P @ V ----
        const uint32_t* Vb = Vs0 + (cur<<12);
        #pragma unroll
        for (int ks2=0; ks2<4; ks2++){
            uint32_t af[4];
            af[0] = Ps[r0*PW + ks2*8 + lk];
            af[1] = Ps[r1*PW + ks2*8 + lk];
            af[2] = Ps[r0*PW + ks2*8 + lk + 4];
            af[3] = Ps[r1*PW + ks2*8 + lk + 4];
            int krow = (ks2<<4) + lr + ((g8&1)<<3);
            #pragma unroll
            for (int nt=0; nt<8; nt++){
                int cd = wn*8 + nt;
                uint32_t addr = smaddr(&Vb[krow*64 + ((cd ^ (krow&7))<<2)]);
                uint32_t b0, b1;
                asm volatile("ldmatrix.sync.aligned.m8n8.x2.trans.shared.b16 {%0,%1}, [%2];\n"
                    : "=r"(b0),"=r"(b1) : "r"(addr));
                mma_bf16(oacc[nt], af, b0, b1);
            }
        }
    }

    // ---- denominator ----
    den0 += __shfl_xor_sync(0xffffffffu, den0, 1);
    den0 += __shfl_xor_sync(0xffffffffu, den0, 2);
    den1 += __shfl_xor_sync(0xffffffffu, den1, 1);
    den1 += __shfl_xor_sync(0xffffffffu, den1, 2);
    if (lk == 0){ den2[wn*64 + r0] = den0; den2[wn*64 + r1] = den1; }
    __syncthreads();
    float dt0 = den2[r0] + den2[64 + r0];
    float dt1 = den2[r1] + den2[64 + r1];
    float inv0 = 1.f / (fmaxf(fabsf(dt0), __expf(-mt[r0])) + 1e-6f);
    float inv1 = 1.f / (fmaxf(fabsf(dt1), __expf(-mt[r1])) + 1e-6f);

    float hv0[16], hv1[16];
    #pragma unroll
    for (int nt=0; nt<8; nt++){
        hv0[nt*2]   = oacc[nt][0]*inv0;
        hv0[nt*2+1] = oacc[nt][1]*inv0;
        hv1[nt*2]   = oacc[nt][2]*inv1;
        hv1[nt*2+1] = oacc[nt][3]*inv1;
    }

    // ---- fused GroupNorm over 128 head dims ----
    float s0 = 0.f, s1 = 0.f;
    #pragma unroll
    for (int i=0;i<16;i++){ s0 += hv0[i]; s1 += hv1[i]; }
    s0 += __shfl_xor_sync(0xffffffffu, s0, 1);
    s0 += __shfl_xor_sync(0xffffffffu, s0, 2);
    s1 += __shfl_xor_sync(0xffffffffu, s1, 1);
    s1 += __shfl_xor_sync(0xffffffffu, s1, 2);
    __syncthreads();
    if (lk == 0){ den2[wn*64 + r0] = s0; den2[wn*64 + r1] = s1; }
    __syncthreads();
    float mu0 = (den2[r0] + den2[64 + r0]) * (1.f/128.f);
    float mu1 = (den2[r1] + den2[64 + r1]) * (1.f/128.f);
    float q0 = 0.f, q1 = 0.f;
    #pragma unroll
    for (int i=0;i<16;i++){
        float d0 = hv0[i]-mu0; q0 += d0*d0;
        float d1 = hv1[i]-mu1; q1 += d1*d1;
    }
    q0 += __shfl_xor_sync(0xffffffffu, q0, 1);
    q0 += __shfl_xor_sync(0xffffffffu, q0, 2);
    q1 += __shfl_xor_sync(0xffffffffu, q1, 1);
    q1 += __shfl_xor_sync(0xffffffffu, q1, 2);
    __syncthreads();
    if (lk == 0){ den2[wn*64 + r0] = q0; den2[wn*64 + r1] = q1; }
    __syncthreads();
    float is0 = rsqrtf((den2[r0] + den2[64 + r0])*(1.f/128.f) + 1e-5f);
    float is1 = rsqrtf((den2[r1] + den2[64 + r1])*(1.f/128.f) + 1e-5f);

    // ---- gamma/beta + skip*xc + silu(z), bf16 store ----
    size_t tok0 = (size_t)(b*SEQ + t0 + r0), tok1 = (size_t)(b*SEQ + t0 + r1);
    #pragma unroll
    for (int nt=0; nt<8; nt++){
        int dc = wn*64 + nt*8 + (lk<<1);
        int c = hh*128 + dc;
        float2 gg = *(const float2*)&gng[c];
        float2 gb = *(const float2*)&gnb[c];
        float2 sk = *(const float2*)&skip[c];
        float2 x0 = __bfloat1622float2(*(const __nv_bfloat162*)&xcbf[tok0*512 + c]);
        float2 x1 = __bfloat1622float2(*(const __nv_bfloat162*)&xcbf[tok1*512 + c]);
        float2 z0 = *(const float2*)&up[tok0*1024 + 512 + c];
        float2 z1 = *(const float2*)&up[tok1*1024 + 512 + c];
        float y00 = (hv0[nt*2]  -mu0)*is0*gg.x + gb.x + sk.x*x0.x;
        float y01 = (hv0[nt*2+1]-mu0)*is0*gg.y + gb.y + sk.y*x0.y;
        float y10 = (hv1[nt*2]  -mu1)*is1*gg.x + gb.x + sk.x*x1.x;
        float y11 = (hv1[nt*2+1]-mu1)*is1*gg.y + gb.y + sk.y*x1.y;
        y00 *= z0.x / (1.f + expf(-z0.x));
        y01 *= z0.y / (1.f + expf(-z0.y));
        y10 *= z1.x / (1.f + expf(-z1.x));
        y11 *= z1.y / (1.f + expf(-z1.y));
        *(__nv_bfloat162*)&out[tok0*512 + c] = __floats2bfloat162_rn(y00, y01);
        *(__nv_bfloat162*)&out[tok1*512 + c] = __floats2bfloat162_rn(y10, y11);
    }
}

// ---------------- final ----------------
__global__ void final_kernel(const float* __restrict__ h, const float* __restrict__ g,
                             const float* __restrict__ b, const float* __restrict__ Wf,
                             const float* __restrict__ bf, float* __restrict__ out){
    __shared__ float sh[8];
    __shared__ float sv;
    int bb = blockIdx.x, tid = threadIdx.x;
    float vv = h[((size_t)(bb*SEQ + SEQ-1))*256 + tid];
    float s = warp_sum(vv);
    if (!(tid&31)) sh[tid>>5] = s;
    __syncthreads();
    if (tid==0){ float t=0; for(int i=0;i<8;i++) t+=sh[i]; sv = t*(1.f/256.f); }
    __syncthreads();
    float mu = sv;
    float d = vv - mu;
    float s2 = warp_sum(d*d);
    if (!(tid&31)) sh[tid>>5] = s2;
    __syncthreads();
    if (tid==0){ float t=0; for(int i=0;i<8;i++) t+=sh[i]; sv = t*(1.f/256.f); }
    __syncthreads();
    float yn = d*rsqrtf(sv + 1e-5f)*g[tid] + b[tid];
    float p = yn * Wf[tid];
    float s3 = warp_sum(p);
    __syncthreads();
    if (!(tid&31)) sh[tid>>5] = s3;
    __syncthreads();
    if (tid==0){ float t=0; for(int i=0;i<8;i++) t+=sh[i]; out[bb] = t + bf[0]; }
}

// ---------------- launch ----------------
extern "C" void kernel_launch(void* const* d_in, const int* in_sizes, int n_in,
                              void* d_out, int out_size){
    const float* x    = (const float*)d_in[0];
    const float* tf   = (const float*)d_in[1];
    const float* Wp   = (const float*)d_in[2];
    const float* bp   = (const float*)d_in[3];
    const float* ln_g = (const float*)d_in[4];
    const float* ln_b = (const float*)d_in[5];
    const float* Wup  = (const float*)d_in[6];
    const float* bup  = (const float*)d_in[7];
    const float* cw   = (const float*)d_in[8];
    const float* cb   = (const float*)d_in[9];
    const float* Wq   = (const float*)d_in[10];
    const float* Wk   = (const float*)d_in[11];
    const float* Wv   = (const float*)d_in[12];
    const float* Wif  = (const float*)d_in[13];
    const float* bif  = (const float*)d_in[14];
    const float* gng  = (const float*)d_in[15];
    const float* gnb  = (const float*)d_in[16];
    const float* skip = (const float*)d_in[17];
    const float* Wdn  = (const float*)d_in[18];
    const float* bdn  = (const float*)d_in[19];
    const float* lnfg = (const float*)d_in[20];
    const float* lnfb = (const float*)d_in[21];
    const float* Wf   = (const float*)d_in[22];
    const float* bf   = (const float*)d_in[23];

    float *h,*up,*giT,*gfT,*Fc,*a,*m,*wcol,*amaxT,*Wg;
    __nv_bfloat16 *hnbf,*xcbf,*upbf,*qbf,*kbf,*vbf,*att2bf,*wupbf,*wqbf,*wkbf,*wvbf,*wdnbf;
    cudaGetSymbolAddress((void**)&h,    g_h);
    cudaGetSymbolAddress((void**)&up,   g_up);
    cudaGetSymbolAddress((void**)&giT,  g_giT);
    cudaGetSymbolAddress((void**)&gfT,  g_gfT);
    cudaGetSymbolAddress((void**)&Fc,   g_Fc);
    cudaGetSymbolAddress((void**)&a,    g_a);
    cudaGetSymbolAddress((void**)&m,    g_m);
    cudaGetSymbolAddress((void**)&wcol, g_wcol);
    cudaGetSymbolAddress((void**)&amaxT,g_amaxT);
    cudaGetSymbolAddress((void**)&Wg,   g_Wg);
    cudaGetSymbolAddress((void**)&hnbf, g_hn_bf);
    cudaGetSymbolAddress((void**)&xcbf, g_xc_bf);
    cudaGetSymbolAddress((void**)&upbf, g_up_bf);
    cudaGetSymbolAddress((void**)&qbf,  g_q_bf);
    cudaGetSymbolAddress((void**)&kbf,  g_k_bf);
    cudaGetSymbolAddress((void**)&vbf,  g_v_bf);
    cudaGetSymbolAddress((void**)&att2bf, g_att2_bf);
    cudaGetSymbolAddress((void**)&wupbf, g_wup_bf);
    cudaGetSymbolAddress((void**)&wqbf,  g_wq_bf);
    cudaGetSymbolAddress((void**)&wkbf,  g_wk_bf);
    cudaGetSymbolAddress((void**)&wvbf,  g_wv_bf);
    cudaGetSymbolAddress((void**)&wdnbf, g_wdn_bf);

    int attn_smem = (2304 + 8192 + 8192 + 64 + 64 + 128 + 128) * 4;
    static int attr_set = 0;
    if (!attr_set){
        cudaFuncSetAttribute(attn_bf16, cudaFuncAttributeMaxDynamicSharedMemorySize, attn_smem);
        attr_set = 1;
    }

    int n0 = NL*DMODEL*1024, n1 = NL*DI*DI, n4 = NL*DI*DMODEL;
    int ntot = n0 + 3*n1 + n4;
    f2bf5_kernel<<<(ntot/2 + 255)/256, 256>>>(Wup, wupbf, n0,
                                              Wq, wqbf, n1,
                                              Wk, wkbf, n1,
                                              Wv, wvbf, n1,
                                              Wdn, wdnbf, n4);
    gatew_kernel<<<NL*1024*8/256, 256>>>(Wq, Wk, Wv, Wif, Wg);

    embed_kernel<<<TOK*256/256, 256>>>(x, tf, Wp, bp, h);

    for (int l=0; l<NL; l++){
        ln_kernel<<<TOK/8, 256>>>(h, ln_g + l*256, ln_b + l*256, hnbf);
        gemm_bf16<<<dim3(1024/64, TOK/128, 1), 256>>>(hnbf, 256, wupbf + (size_t)l*256*1024, 1024,
                                                   up, 1024, bup + l*1024, nullptr, 256,
                                                   upbf, 512, nullptr, nullptr, nullptr, nullptr, nullptr);
        conv_gates_kernel<<<TOK, 256>>>(up, cw + l*4*512, cb + l*512,
                                        Wg + (size_t)l*8192, bif + l*8,
                                        xcbf, giT, gfT);
        gemm_bf16<<<dim3(512/64, TOK/128, 3), 256>>>(xcbf, 512, wqbf + (size_t)l*512*512, 512,
                                                  nullptr, 512, nullptr, nullptr, 512, qbf, 512,
                                                  upbf,
                                                  wkbf + (size_t)l*512*512, kbf,
                                                  wvbf + (size_t)l*512*512, vbf);
        scan_kernel4<<<32, 32>>>(giT, gfT, Fc, a, m, wcol, amaxT);
        attn_bf16<<<dim3(BATCH*NH, SEQ/64), 256, attn_smem>>>(qbf, kbf, vbf, Fc, a, m,
                                                  wcol, amaxT,
                                                  xcbf, up, gng + l*512, gnb + l*512, skip + l*512,
                                                  att2bf);
        gemm_bf16<<<dim3(256/64, TOK/128, 1), 256>>>(att2bf, 512, wdnbf + (size_t)l*512*256, 256,
                                                  h, 256, bdn + l*256, h, 512,
                                                  nullptr, 0, nullptr, nullptr, nullptr, nullptr, nullptr);
    }
    final_kernel<<<BATCH, 256>>>(h, lnfg, lnfb, Wf, bf, (float*)d_out);
}

// round 11
// speedup vs baseline: 1.0043x; 1.0043x over previous
#include <cuda_runtime.h>
#include <cuda_bf16.h>
#include <cstdint>
#include <cstddef>

#define SEQ 1024
#define BATCH 8
#define TOK (BATCH*SEQ)
#define DMODEL 256
#define DI 512
#define NH 4
#define DHH 128
#define NL 4

// ---------------- scratch (device globals; no allocation allowed) ----------------
__device__ float g_h[TOK*DMODEL];
__device__ float g_up[TOK*1024];
__device__ float g_giT[BATCH*NH*SEQ];
__device__ float g_gfT[BATCH*NH*SEQ];
__device__ float g_Fc[BATCH*NH*SEQ];
__device__ float g_a[BATCH*NH*SEQ];
__device__ float g_m[BATCH*NH*SEQ];
__device__ float g_wcol[BATCH*NH*SEQ];
__device__ float g_amaxT[BATCH*NH*16];
__device__ float g_Wg[NL*1024*8];

__device__ __nv_bfloat16 g_hn_bf[TOK*DMODEL];
__device__ __nv_bfloat16 g_xc_bf[TOK*DI];
__device__ __nv_bfloat16 g_up_bf[TOK*DI];
__device__ __nv_bfloat16 g_q_bf[TOK*DI];
__device__ __nv_bfloat16 g_k_bf[TOK*DI];
__device__ __nv_bfloat16 g_v_bf[TOK*DI];
__device__ __nv_bfloat16 g_att2_bf[TOK*DI];
__device__ __nv_bfloat16 g_wup_bf[NL*DMODEL*1024];
__device__ __nv_bfloat16 g_wq_bf[NL*DI*DI];
__device__ __nv_bfloat16 g_wk_bf[NL*DI*DI];
__device__ __nv_bfloat16 g_wv_bf[NL*DI*DI];
__device__ __nv_bfloat16 g_wdn_bf[NL*DI*DMODEL];

__device__ __forceinline__ float warp_sum(float v){
    #pragma unroll
    for (int o=16;o;o>>=1) v += __shfl_xor_sync(0xffffffffu, v, o);
    return v;
}

__device__ __forceinline__ uint32_t bf2pack(float x, float y){
    __nv_bfloat162 t = __floats2bfloat162_rn(x, y);
    return *(uint32_t*)&t;
}

__device__ __forceinline__ void mma_bf16(float* c, const uint32_t* a, uint32_t b0, uint32_t b1){
    asm volatile(
      "mma.sync.aligned.m16n8k16.row.col.f32.bf16.bf16.f32 "
      "{%0,%1,%2,%3}, {%4,%5,%6,%7}, {%8,%9}, {%0,%1,%2,%3};\n"
      : "+f"(c[0]), "+f"(c[1]), "+f"(c[2]), "+f"(c[3])
      : "r"(a[0]), "r"(a[1]), "r"(a[2]), "r"(a[3]), "r"(b0), "r"(b1));
}

__device__ __forceinline__ uint32_t smaddr(const void* p){
    return (uint32_t)__cvta_generic_to_shared(p);
}
#define CPA16(dst,src) asm volatile("cp.async.cg.shared.global [%0], [%1], 16;\n"::"r"(dst),"l"(src))
#define CPCOMMIT() asm volatile("cp.async.commit_group;\n")
#define CPWAIT(n) asm volatile("cp.async.wait_group %0;\n"::"n"(n))

// ---------------- merged f32 -> bf16 convert for all 5 weight tensors ----------------
__global__ void f2bf5_kernel(const float* __restrict__ i0, __nv_bfloat16* __restrict__ o0, int n0,
                             const float* __restrict__ i1, __nv_bfloat16* __restrict__ o1, int n1,
                             const float* __restrict__ i2, __nv_bfloat16* __restrict__ o2, int n2,
                             const float* __restrict__ i3, __nv_bfloat16* __restrict__ o3, int n3,
                             const float* __restrict__ i4, __nv_bfloat16* __restrict__ o4, int n4){
    int i = (blockIdx.x*blockDim.x + threadIdx.x)*2;
    const float* in; __nv_bfloat16* out;
    if (i < n0){ in=i0; out=o0; }
    else if ((i-=n0) < n1){ in=i1; out=o1; }
    else if ((i-=n1) < n2){ in=i2; out=o2; }
    else if ((i-=n2) < n3){ in=i3; out=o3; }
    else if ((i-=n3) < n4){ in=i4; out=o4; }
    else return;
    float2 v = *(const float2*)(in+i);
    *(__nv_bfloat162*)(out+i) = __floats2bfloat162_rn(v.x, v.y);
}

// ---------------- composite gate weights: Wg = [Wq@Wif_i + Wk@Wif_k ; Wv@Wif_v] ----------------
__global__ void gatew_kernel(const float* __restrict__ Wq, const float* __restrict__ Wk,
                             const float* __restrict__ Wv, const float* __restrict__ Wif,
                             float* __restrict__ Wg){
    int idx = blockIdx.x*blockDim.x + threadIdx.x;   // NL*1024*8
    int l = idx >> 13; int r = idx & 8191;
    int c = r >> 3; int j = r & 7;
    const float* Wifl = Wif + (size_t)l*1536*8;
    float acc = 0.f;
    if (c < 512){
        const float* wq = Wq + ((size_t)l*512 + c)*512;
        const float* wk = Wk + ((size_t)l*512 + c)*512;
        #pragma unroll 4
        for (int i=0;i<512;i++)
            acc += wq[i]*Wifl[i*8+j] + wk[i]*Wifl[(512+i)*8+j];
    } else {
        const float* wv = Wv + ((size_t)l*512 + (c-512))*512;
        #pragma unroll 4
        for (int i=0;i<512;i++)
            acc += wv[i]*Wifl[(1024+i)*8+j];
    }
    Wg[(size_t)l*8192 + c*8 + j] = acc;
}

// ---------------- embed ----------------
__global__ void embed_kernel(const float* __restrict__ x, const float* __restrict__ tf,
                             const float* __restrict__ Wp, const float* __restrict__ bp,
                             float* __restrict__ h){
    int idx = blockIdx.x*blockDim.x + threadIdx.x;
    int j = idx & 255; int tok = idx >> 8;
    float acc = bp[j] + x[tok]*Wp[j];
    #pragma unroll
    for (int f=0; f<4; f++) acc += tf[tok*4+f]*Wp[(1+f)*256+j];
    h[idx] = acc;
}

// ---------------- layernorm, bf16 out ----------------
__global__ void ln_kernel(const float* __restrict__ x, const float* __restrict__ g,
                          const float* __restrict__ b, __nv_bfloat16* __restrict__ y){
    int row = blockIdx.x*8 + (threadIdx.x>>5);
    int lane = threadIdx.x & 31;
    const float* xr = x + (size_t)row*256;
    float4 v0 = *(const float4*)(xr + lane*4);
    float4 v1 = *(const float4*)(xr + 128 + lane*4);
    float s = v0.x+v0.y+v0.z+v0.w + v1.x+v1.y+v1.z+v1.w;
    s = warp_sum(s);
    float mu = s * (1.f/256.f);
    float d0x=v0.x-mu, d0y=v0.y-mu, d0z=v0.z-mu, d0w=v0.w-mu;
    float d1x=v1.x-mu, d1y=v1.y-mu, d1z=v1.z-mu, d1w=v1.w-mu;
    float sq = d0x*d0x+d0y*d0y+d0z*d0z+d0w*d0w + d1x*d1x+d1y*d1y+d1z*d1z+d1w*d1w;
    sq = warp_sum(sq);
    float is = rsqrtf(sq*(1.f/256.f) + 1e-5f);
    float4 g0 = *(const float4*)(g + lane*4);
    float4 g1 = *(const float4*)(g + 128 + lane*4);
    float4 b0 = *(const float4*)(b + lane*4);
    float4 b1 = *(const float4*)(b + 128 + lane*4);
    __nv_bfloat16* yr = y + (size_t)row*256;
    *(__nv_bfloat162*)&yr[lane*4]       = __floats2bfloat162_rn(d0x*is*g0.x + b0.x, d0y*is*g0.y + b0.y);
    *(__nv_bfloat162*)&yr[lane*4+2]     = __floats2bfloat162_rn(d0z*is*g0.z + b0.z, d0w*is*g0.w + b0.w);
    *(__nv_bfloat162*)&yr[128+lane*4]   = __floats2bfloat162_rn(d1x*is*g1.x + b1.x, d1y*is*g1.y + b1.y);
    *(__nv_bfloat162*)&yr[128+lane*4+2] = __floats2bfloat162_rn(d1z*is*g1.z + b1.z, d1w*is*g1.w + b1.w);
}

// ---------------- bf16 tensor-core GEMM, cp.async double-buffered ----------------
__global__ __launch_bounds__(256) void gemm_bf16(
    const __nv_bfloat16* __restrict__ A, int lda,
    const __nv_bfloat16* __restrict__ B, int ldb,
    float* __restrict__ C, int ldc,
    const float* __restrict__ bias,
    const float* __restrict__ resid,
    int K,
    __nv_bfloat16* __restrict__ Cbf, int bfcap,
    const __nv_bfloat16* __restrict__ A2,
    const __nv_bfloat16* __restrict__ B2,
    __nv_bfloat16* __restrict__ Cbf2,
    const __nv_bfloat16* __restrict__ B3,
    __nv_bfloat16* __restrict__ Cbf3)
{
    __shared__ __nv_bfloat16 As[2][128*64];
    __shared__ __nv_bfloat16 Bs[2][64*64];
    if (blockIdx.z == 1){ B = B2; Cbf = Cbf2; }
    else if (blockIdx.z == 2){ A = A2; B = B3; Cbf = Cbf3; }
    int tid = threadIdx.x, lane = tid&31, wid = tid>>5;
    int wm = wid>>1, wn = wid&1;
    int m0 = blockIdx.y*128, n0 = blockIdx.x*64;

    int ar = tid >> 1;
    int ac0 = (tid & 1) << 2;
    int br = tid >> 2;
    int bc0 = (tid & 3) << 1;
    const __nv_bfloat16* Ag = A + (size_t)(m0+ar)*lda;
    const __nv_bfloat16* Bg = B + (size_t)br*ldb + n0;

    int KC = K >> 6;
    {
        #pragma unroll
        for (int c=0;c<4;c++){
            int ch = ac0+c;
            CPA16(smaddr(&As[0][ar*64 + ((ch ^ (ar&7))<<3)]), Ag + (ch<<3));
        }
        #pragma unroll
        for (int c=0;c<2;c++){
            int ch = bc0+c;
            CPA16(smaddr(&Bs[0][br*64 + ((ch ^ (br&7))<<3)]), Bg + (ch<<3));
        }
        CPCOMMIT();
    }

    float acc[2][4][4] = {};
    int g = lane>>3, lr = lane&7;

    for (int kc=0; kc<KC; kc++){
        int cur = kc & 1;
        if (kc+1 < KC){
            int nb = (kc+1)&1, k0 = (kc+1)<<6;
            #pragma unroll
            for (int c=0;c<4;c++){
                int ch = ac0+c;
                CPA16(smaddr(&As[nb][ar*64 + ((ch ^ (ar&7))<<3)]), Ag + k0 + (ch<<3));
            }
            #pragma unroll
            for (int c=0;c<2;c++){
                int ch = bc0+c;
                CPA16(smaddr(&Bs[nb][br*64 + ((ch ^ (br&7))<<3)]), Bg + (size_t)k0*ldb + (ch<<3));
            }
            CPCOMMIT();
            CPWAIT(1);
        } else {
            CPWAIT(0);
        }
        __syncthreads();

        #pragma unroll
        for (int ks=0; ks<4; ks++){
            uint32_t af[2][4];
            #pragma unroll
            for (int mt=0; mt<2; mt++){
                int arow = wm*32 + mt*16 + lr + ((g&1)<<3);
                int ch = (ks<<1) + (g>>1);
                uint32_t addr = smaddr(&As[cur][arow*64 + ((ch ^ (arow&7))<<3)]);
                asm volatile("ldmatrix.sync.aligned.m8n8.x4.shared.b16 {%0,%1,%2,%3}, [%4];\n"
                    : "=r"(af[mt][0]),"=r"(af[mt][1]),"=r"(af[mt][2]),"=r"(af[mt][3]) : "r"(addr));
            }
            uint32_t bf[4][2];
            int krow = (ks<<4) + lr + ((g&1)<<3);
            #pragma unroll
            for (int nt=0; nt<4; nt++){
                int ch = wn*4 + nt;
                uint32_t addr = smaddr(&Bs[cur][krow*64 + ((ch ^ (krow&7))<<3)]);
                asm volatile("ldmatrix.sync.aligned.m8n8.x2.trans.shared.b16 {%0,%1}, [%2];\n"
                    : "=r"(bf[nt][0]),"=r"(bf[nt][1]) : "r"(addr));
            }
            #pragma unroll
            for (int mt=0;mt<2;mt++)
              #pragma unroll
              for (int nt=0;nt<4;nt++)
                mma_bf16(acc[mt][nt], af[mt], bf[nt][0], bf[nt][1]);
        }
        __syncthreads();
    }

    #pragma unroll
    for (int mt=0;mt<2;mt++){
        #pragma unroll
        for (int nt=0;nt<4;nt++){
            int row0 = m0 + wm*32 + mt*16 + (lane>>2);
            int col  = n0 + wn*32 + nt*8 + ((lane&3)<<1);
            float bx=0.f, by=0.f;
            if (bias){ bx = bias[col]; by = bias[col+1]; }
            float2 r0v = make_float2(0.f,0.f), r1v = make_float2(0.f,0.f);
            if (resid){
                r0v = *(const float2*)&resid[(size_t)row0*ldc + col];
                r1v = *(const float2*)&resid[(size_t)(row0+8)*ldc + col];
            }
            float v00 = acc[mt][nt][0]+bx+r0v.x, v01 = acc[mt][nt][1]+by+r0v.y;
            float v10 = acc[mt][nt][2]+bx+r1v.x, v11 = acc[mt][nt][3]+by+r1v.y;
            if (C){
                *(float2*)&C[(size_t)row0*ldc + col]     = make_float2(v00, v01);
                *(float2*)&C[(size_t)(row0+8)*ldc + col] = make_float2(v10, v11);
            }
            if (Cbf && col < bfcap){
                *(__nv_bfloat162*)&Cbf[(size_t)row0*bfcap + col]     = __floats2bfloat162_rn(v00, v01);
                *(__nv_bfloat162*)&Cbf[(size_t)(row0+8)*bfcap + col] = __floats2bfloat162_rn(v10, v11);
            }
        }
    }
}

// ---------------- fused causal conv + silu + composite gates ----------------
__global__ __launch_bounds__(256) void conv_gates_kernel(
    const float* __restrict__ up, const float* __restrict__ cw, const float* __restrict__ cb,
    const float* __restrict__ Wg, const float* __restrict__ bif,
    __nv_bfloat16* __restrict__ xcbf,
    float* __restrict__ giT, float* __restrict__ gfT)
{
    __shared__ float xcs[512], xms[512];
    int tok = blockIdx.x, tid = threadIdx.x;
    int t = tok & 1023;
    #pragma unroll
    for (int r=0;r<2;r++){
        int c = tid + (r<<8);
        float xm = up[(size_t)tok*1024 + c];
        float acc = cb[c] + cw[3*512+c]*xm;
        #pragma unroll
        for (int j=0;j<3;j++){
            int ts = t - 3 + j;
            if (ts >= 0) acc += cw[j*512+c]*up[(size_t)(tok-3+j)*1024 + c];
        }
        float sv = acc/(1.f+expf(-acc));
        xcs[c] = sv; xms[c] = xm;
        xcbf[(size_t)tok*512 + c] = __float2bfloat16(sv);
    }
    __syncthreads();
    int w = tid>>5, lane = tid&31;
    float acc = 0.f;
    for (int i=lane;i<512;i+=32) acc += xcs[i]*Wg[i*8+w] + xms[i]*Wg[(512+i)*8+w];
    acc = warp_sum(acc);
    if (!lane){
        float r = acc + bif[w];
        int b = tok >> 10, s = tok & 1023;
        if (w < 4) giT[(size_t)(b*4+w)*1024 + s] = r;
        else       gfT[(size_t)(b*4+w-4)*1024 + s] = r;
    }
}

// ---------------- gate scan + per-tile col weights ----------------
__global__ void scan_kernel4(const float* __restrict__ giT, const float* __restrict__ gfT,
                             float* __restrict__ Fc, float* __restrict__ a, float* __restrict__ m,
                             float* __restrict__ wcol, float* __restrict__ amaxT){
    __shared__ float ash[1024];
    int bh = blockIdx.x, lane = threadIdx.x;
    const float* gih = giT + (size_t)bh*1024;
    const float* gfh = gfT + (size_t)bh*1024;
    const float scale = 0.08838834764831845f;
    float cfc = 0.f, cmax = -1e30f;
    float ipc = gih[lane], fpc = gfh[lane];
    for (int c=0;c<32;c++){
        float ip = ipc, fp = fpc;
        if (c+1 < 32){ ipc = gih[(c+1)*32+lane]; fpc = gfh[(c+1)*32+lane]; }
        float lf = fminf(fp, 0.f) - log1pf(expf(-fabsf(fp)));
        float x = lf;
        #pragma unroll
        for (int o=1;o<32;o<<=1){ float y = __shfl_up_sync(0xffffffffu, x, o); if (lane>=o) x += y; }
        float fc = cfc + x;
        float av = ip - fc;
        float mx = av;
        #pragma unroll
        for (int o=1;o<32;o<<=1){ float y = __shfl_up_sync(0xffffffffu, mx, o); if (lane>=o) mx = fmaxf(mx, y); }
        float cm = fmaxf(cmax, mx);
        int off = bh*SEQ + c*32 + lane;
        Fc[off] = fc; a[off] = av; m[off] = fc + cm;
        ash[c*32 + lane] = av;
        cfc += __shfl_sync(0xffffffffu, x, 31);
        cmax = fmaxf(cmax, __shfl_sync(0xffffffffu, mx, 31));
    }
    __syncwarp();
    for (int tile=0;tile<16;tile++){
        float v0 = ash[tile*64 + lane];
        float v1 = ash[tile*64 + 32 + lane];
        float mx = fmaxf(v0, v1);
        #pragma unroll
        for (int o=16;o;o>>=1) mx = fmaxf(mx, __shfl_xor_sync(0xffffffffu, mx, o));
        if (lane == 0) amaxT[bh*16 + tile] = mx;
        wcol[bh*SEQ + tile*64 + lane]      = scale*__expf(v0 - mx);
        wcol[bh*SEQ + tile*64 + 32 + lane] = scale*__expf(v1 - mx);
    }
}

// ---------------- mLSTM attention: smem Q + cp.async double-buffered K/V ----------------
// smem (words): Q 64*68 (reused as P 64*36) | K[2] 64*64 | V[2] 64*64 | fct 64 | mt 64 | as2 128 | den2 128
#define QKW 68
#define PW  36
__global__ __launch_bounds__(256) void attn_bf16(
    const __nv_bfloat16* __restrict__ q, const __nv_bfloat16* __restrict__ k,
    const __nv_bfloat16* __restrict__ v,
    const float* __restrict__ Fcv, const float* __restrict__ av, const float* __restrict__ mv,
    const float* __restrict__ wcol, const float* __restrict__ amaxT,
    const __nv_bfloat16* __restrict__ xcbf, const float* __restrict__ up,
    const float* __restrict__ gng, const float* __restrict__ gnb,
    const float* __restrict__ skip,
    __nv_bfloat16* __restrict__ out)
{
    extern __shared__ uint32_t smu[];
    uint32_t* Qs  = smu;                  // 64*68; reused as P (64*36)
    uint32_t* Ks0 = smu + 64*QKW;         // 2 x 4096
    uint32_t* Vs0 = Ks0 + 8192;           // 2 x 4096
    float* fct  = (float*)(Vs0 + 8192);   // 64
    float* mt   = fct + 64;               // 64
    float* as2  = mt + 64;                // 2 x 64
    float* den2 = as2 + 128;              // 128

    int bh = blockIdx.x; int b = bh>>2, hh = bh&3;
    int it = (int)(gridDim.y - 1) - (int)blockIdx.y;
    int t0 = it<<6;
    int tid = threadIdx.x, lane = tid&31, wid = tid>>5;
    int wm = wid>>1, wn = wid&1;
    int ls = lane>>2, lk = lane&3;
    int g8 = lane>>3, lr = lane&7;
    const float scale = 0.08838834764831845f;

    const __nv_bfloat16* kgb = k + ((size_t)(b*SEQ))*512 + hh*128;
    const __nv_bfloat16* vgb = v + ((size_t)(b*SEQ))*512 + hh*128;

    // prologue: issue tile-0 K/V cp.async (overlaps with Q staging below)
    {
        #pragma unroll
        for (int r=0;r<4;r++){
            int idx = tid + (r<<8);
            int row = idx>>4, c16 = idx&15;
            int off = row*64 + ((c16 ^ (row&7))<<2);
            CPA16(smaddr(&Ks0[off]), kgb + (size_t)row*512 + (c16<<3));
            CPA16(smaddr(&Vs0[off]), vgb + (size_t)row*512 + (c16<<3));
        }
        CPCOMMIT();
    }

    // stage Q coalesced (uint4) into padded smem
    const __nv_bfloat16* qg = q + ((size_t)(b*SEQ + t0))*512 + hh*128;
    #pragma unroll
    for (int r=0;r<4;r++){
        int idx = tid + (r<<8);
        int row = idx>>4, c16 = idx&15;
        uint4 val = *(const uint4*)(qg + (size_t)row*512 + (c16<<3));
        *(uint4*)&Qs[row*QKW + (c16<<2)] = val;
    }
    if (tid < 64){
        int tg = bh*SEQ + t0 + tid;
        fct[tid] = Fcv[tg]; mt[tid] = mv[tg];
        as2[tid] = (it == 0) ? av[bh*SEQ + tid] : wcol[bh*SEQ + tid];
    }
    __syncthreads();

    // hoist Q A-fragments from smem (conflict-free: bank = 4*ls + lk pattern)
    uint32_t qf[8][4];
    int r0 = wm*16 + ls, r1 = r0 + 8;
    #pragma unroll
    for (int ks=0; ks<8; ks++){
        qf[ks][0] = Qs[r0*QKW + ks*8 + lk];
        qf[ks][1] = Qs[r1*QKW + ks*8 + lk];
        qf[ks][2] = Qs[r0*QKW + ks*8 + lk + 4];
        qf[ks][3] = Qs[r1*QKW + ks*8 + lk + 4];
    }

    float oacc[8][4];
    #pragma unroll
    for (int i=0;i<8;i++){ oacc[i][0]=0.f; oacc[i][1]=0.f; oacc[i][2]=0.f; oacc[i][3]=0.f; }
    float den0 = 0.f, den1 = 0.f;

    for (int js=0; js<=it; js++){
        int cur = js & 1;
        CPWAIT(0);
        __syncthreads();   // tile js staged everywhere; prior-iteration smem reads retired

        // prefetch tile js+1 into the other buffer (overlaps all compute below)
        if (js < it){
            int s1 = (js+1)<<6;
            uint32_t* Kb = Ks0 + ((cur^1)<<12);
            uint32_t* Vb = Vs0 + ((cur^1)<<12);
            const __nv_bfloat16* kg = kgb + (size_t)s1*512;
            const __nv_bfloat16* vg = vgb + (size_t)s1*512;
            #pragma unroll
            for (int r=0;r<4;r++){
                int idx = tid + (r<<8);
                int row = idx>>4, c16 = idx&15;
                int off = row*64 + ((c16 ^ (row&7))<<2);
                CPA16(smaddr(&Kb[off]), kg + (size_t)row*512 + (c16<<3));
                CPA16(smaddr(&Vb[off]), vg + (size_t)row*512 + (c16<<3));
            }
            CPCOMMIT();
            if (tid < 64)
                as2[((cur^1)<<6) + tid] = (js+1 == it) ? av[bh*SEQ + s1 + tid]
                                                       : wcol[bh*SEQ + s1 + tid];
        }

        const uint32_t* Kb = Ks0 + (cur<<12);
        const float* asl = as2 + (cur<<6);
        bool diag = (js == it);

        // ---- S = Q @ K^T (conflict-free: bank = ((ch^ls)<<2)+lk) ----
        float sacc[4][4] = {};
        #pragma unroll
        for (int ks=0; ks<8; ks++){
            #pragma unroll
            for (int nt=0; nt<4; nt++){
                int sc = wn*32 + nt*8 + ls;
                uint32_t b0 = Kb[sc*64 + (((2*ks  )^(sc&7))<<2) + lk];
                uint32_t b1 = Kb[sc*64 + (((2*ks+1)^(sc&7))<<2) + lk];
                mma_bf16(sacc[nt], qf[ks], b0, b1);
            }
        }

        // ---- decay weighting + denominator + P (bf16x2) ----
        float f0 = fct[r0], mm0 = mt[r0], f1 = fct[r1], mm1 = mt[r1];
        if (!diag){
            float amx = amaxT[bh*16 + js];
            float w0 = __expf(f0 - mm0 + amx);
            float w1 = __expf(f1 - mm1 + amx);
            #pragma unroll
            for (int nt=0; nt<4; nt++){
                int c0 = wn*32 + nt*8 + (lk<<1);
                float wc0 = asl[c0], wc1 = asl[c0+1];
                float v00 = sacc[nt][0]*w0*wc0;
                float v01 = sacc[nt][1]*w0*wc1;
                float v10 = sacc[nt][2]*w1*wc0;
                float v11 = sacc[nt][3]*w1*wc1;
                den0 += v00 + v01;
                den1 += v10 + v11;
                int wcl = wn*16 + nt*4 + lk;
                Qs[r0*PW + wcl] = bf2pack(v00, v01);
                Qs[r1*PW + wcl] = bf2pack(v10, v11);
            }
        } else {
            #pragma unroll
            for (int nt=0; nt<4; nt++){
                int c0 = wn*32 + nt*8 + (lk<<1);
                int c1 = c0 + 1;
                float a0v = asl[c0], a1v = asl[c1];
                float v00 = sacc[nt][0]*scale*__expf(f0 + a0v - mm0);
                float v01 = sacc[nt][1]*scale*__expf(f0 + a1v - mm0);
                float v10 = sacc[nt][2]*scale*__expf(f1 + a0v - mm1);
                float v11 = sacc[nt][3]*scale*__expf(f1 + a1v - mm1);
                if (c0 > r0) v00 = 0.f;
                if (c1 > r0) v01 = 0.f;
                if (c0 > r1) v10 = 0.f;
                if (c1 > r1) v11 = 0.f;
                den0 += v00 + v01;
                den1 += v10 + v11;
                int wcl = wn*16 + nt*4 + lk;
                Qs[r0*PW + wcl] = bf2pack(v00, v01);
                Qs[r1*PW + wcl] = bf2pack(v10, v11);
            }
        }
        // P rows of this wm-pair shared only between its wn=0/1 warps
        asm volatile("bar.sync %0, %1;" :: "r"(wm+1), "r"(64) : "memory");

        // ---- out += P @ V ----
        const uint32_t* Vb = Vs0 + (cur<<12);
        #pragma unroll
        for (int ks2=0; ks2<4; ks2++){
            uint32_t af[4];
            af[0] = Qs[r0*PW + ks2*8 + lk];
            af[1] = Qs[r1*PW + ks2*8 + lk];
            af[2] = Qs[r0*PW + ks2*8 + lk + 4];
            af[3] = Qs[r1*PW + ks2*8 + lk + 4];
            int krow = (ks2<<4) + lr + ((g8&1)<<3);
            #pragma unroll
            for (int nt=0; nt<8; nt++){
                int cd = wn*8 + nt;
                uint32_t addr = smaddr(&Vb[krow*64 + ((cd ^ (krow&7))<<2)]);
                uint32_t b0, b1;
                asm volatile("ldmatrix.sync.aligned.m8n8.x2.trans.shared.b16 {%0,%1}, [%2];\n"
                    : "=r"(b0),"=r"(b1) : "r"(addr));
                mma_bf16(oacc[nt], af, b0, b1);
            }
        }
    }

    // ---- denominator ----
    den0 += __shfl_xor_sync(0xffffffffu, den0, 1);
    den0 += __shfl_xor_sync(0xffffffffu, den0, 2);
    den1 += __shfl_xor_sync(0xffffffffu, den1, 1);
    den1 += __shfl_xor_sync(0xffffffffu, den1, 2);
    if (lk == 0){ den2[wn*64 + r0] = den0; den2[wn*64 + r1] = den1; }
    __syncthreads();
    float dt0 = den2[r0] + den2[64 + r0];
    float dt1 = den2[r1] + den2[64 + r1];
    float inv0 = 1.f / (fmaxf(fabsf(dt0), __expf(-mt[r0])) + 1e-6f);
    float inv1 = 1.f / (fmaxf(fabsf(dt1), __expf(-mt[r1])) + 1e-6f);

    float hv0[16], hv1[16];
    #pragma unroll
    for (int nt=0; nt<8; nt++){
        hv0[nt*2]   = oacc[nt][0]*inv0;
        hv0[nt*2+1] = oacc[nt][1]*inv0;
        hv1[nt*2]   = oacc[nt][2]*inv1;
        hv1[nt*2+1] = oacc[nt][3]*inv1;
    }

    // ---- fused GroupNorm over 128 head dims ----
    float s0 = 0.f, s1 = 0.f;
    #pragma unroll
    for (int i=0;i<16;i++){ s0 += hv0[i]; s1 += hv1[i]; }
    s0 += __shfl_xor_sync(0xffffffffu, s0, 1);
    s0 += __shfl_xor_sync(0xffffffffu, s0, 2);
    s1 += __shfl_xor_sync(0xffffffffu, s1, 1);
    s1 += __shfl_xor_sync(0xffffffffu, s1, 2);
    __syncthreads();
    if (lk == 0){ den2[wn*64 + r0] = s0; den2[wn*64 + r1] = s1; }
    __syncthreads();
    float mu0 = (den2[r0] + den2[64 + r0]) * (1.f/128.f);
    float mu1 = (den2[r1] + den2[64 + r1]) * (1.f/128.f);
    float q0 = 0.f, q1 = 0.f;
    #pragma unroll
    for (int i=0;i<16;i++){
        float d0 = hv0[i]-mu0; q0 += d0*d0;
        float d1 = hv1[i]-mu1; q1 += d1*d1;
    }
    q0 += __shfl_xor_sync(0xffffffffu, q0, 1);
    q0 += __shfl_xor_sync(0xffffffffu, q0, 2);
    q1 += __shfl_xor_sync(0xffffffffu, q1, 1);
    q1 += __shfl_xor_sync(0xffffffffu, q1, 2);
    __syncthreads();
    if (lk == 0){ den2[wn*64 + r0] = q0; den2[wn*64 + r1] = q1; }
    __syncthreads();
    float is0 = rsqrtf((den2[r0] + den2[64 + r0])*(1.f/128.f) + 1e-5f);
    float is1 = rsqrtf((den2[r1] + den2[64 + r1])*(1.f/128.f) + 1e-5f);

    // ---- gamma/beta + skip*xc + silu(z), bf16 store ----
    size_t tok0 = (size_t)(b*SEQ + t0 + r0), tok1 = (size_t)(b*SEQ + t0 + r1);
    #pragma unroll
    for (int nt=0; nt<8; nt++){
        int dc = wn*64 + nt*8 + (lk<<1);
        int c = hh*128 + dc;
        float2 gg = *(const float2*)&gng[c];
        float2 gb = *(const float2*)&gnb[c];
        float2 sk = *(const float2*)&skip[c];
        float2 x0 = __bfloat1622float2(*(const __nv_bfloat162*)&xcbf[tok0*512 + c]);
        float2 x1 = __bfloat1622float2(*(const __nv_bfloat162*)&xcbf[tok1*512 + c]);
        float2 z0 = *(const float2*)&up[tok0*1024 + 512 + c];
        float2 z1 = *(const float2*)&up[tok1*1024 + 512 + c];
        float y00 = (hv0[nt*2]  -mu0)*is0*gg.x + gb.x + sk.x*x0.x;
        float y01 = (hv0[nt*2+1]-mu0)*is0*gg.y + gb.y + sk.y*x0.y;
        float y10 = (hv1[nt*2]  -mu1)*is1*gg.x + gb.x + sk.x*x1.x;
        float y11 = (hv1[nt*2+1]-mu1)*is1*gg.y + gb.y + sk.y*x1.y;
        y00 *= z0.x / (1.f + expf(-z0.x));
        y01 *= z0.y / (1.f + expf(-z0.y));
        y10 *= z1.x / (1.f + expf(-z1.x));
        y11 *= z1.y / (1.f + expf(-z1.y));
        *(__nv_bfloat162*)&out[tok0*512 + c] = __floats2bfloat162_rn(y00, y01);
        *(__nv_bfloat162*)&out[tok1*512 + c] = __floats2bfloat162_rn(y10, y11);
    }
}

// ---------------- final ----------------
__global__ void final_kernel(const float* __restrict__ h, const float* __restrict__ g,
                             const float* __restrict__ b, const float* __restrict__ Wf,
                             const float* __restrict__ bf, float* __restrict__ out){
    __shared__ float sh[8];
    __shared__ float sv;
    int bb = blockIdx.x, tid = threadIdx.x;
    float vv = h[((size_t)(bb*SEQ + SEQ-1))*256 + tid];
    float s = warp_sum(vv);
    if (!(tid&31)) sh[tid>>5] = s;
    __syncthreads();
    if (tid==0){ float t=0; for(int i=0;i<8;i++) t+=sh[i]; sv = t*(1.f/256.f); }
    __syncthreads();
    float mu = sv;
    float d = vv - mu;
    float s2 = warp_sum(d*d);
    if (!(tid&31)) sh[tid>>5] = s2;
    __syncthreads();
    if (tid==0){ float t=0; for(int i=0;i<8;i++) t+=sh[i]; sv = t*(1.f/256.f); }
    __syncthreads();
    float yn = d*rsqrtf(sv + 1e-5f)*g[tid] + b[tid];
    float p = yn * Wf[tid];
    float s3 = warp_sum(p);
    __syncthreads();
    if (!(tid&31)) sh[tid>>5] = s3;
    __syncthreads();
    if (tid==0){ float t=0; for(int i=0;i<8;i++) t+=sh[i]; out[bb] = t + bf[0]; }
}

// ---------------- launch ----------------
extern "C" void kernel_launch(void* const* d_in, const int* in_sizes, int n_in,
                              void* d_out, int out_size){
    const float* x    = (const float*)d_in[0];
    const float* tf   = (const float*)d_in[1];
    const float* Wp   = (const float*)d_in[2];
    const float* bp   = (const float*)d_in[3];
    const float* ln_g = (const float*)d_in[4];
    const float* ln_b = (const float*)d_in[5];
    const float* Wup  = (const float*)d_in[6];
    const float* bup  = (const float*)d_in[7];
    const float* cw   = (const float*)d_in[8];
    const float* cb   = (const float*)d_in[9];
    const float* Wq   = (const float*)d_in[10];
    const float* Wk   = (const float*)d_in[11];
    const float* Wv   = (const float*)d_in[12];
    const float* Wif  = (const float*)d_in[13];
    const float* bif  = (const float*)d_in[14];
    const float* gng  = (const float*)d_in[15];
    const float* gnb  = (const float*)d_in[16];
    const float* skip = (const float*)d_in[17];
    const float* Wdn  = (const float*)d_in[18];
    const float* bdn  = (const float*)d_in[19];
    const float* lnfg = (const float*)d_in[20];
    const float* lnfb = (const float*)d_in[21];
    const float* Wf   = (const float*)d_in[22];
    const float* bf   = (const float*)d_in[23];

    float *h,*up,*giT,*gfT,*Fc,*a,*m,*wcol,*amaxT,*Wg;
    __nv_bfloat16 *hnbf,*xcbf,*upbf,*qbf,*kbf,*vbf,*att2bf,*wupbf,*wqbf,*wkbf,*wvbf,*wdnbf;
    cudaGetSymbolAddress((void**)&h,    g_h);
    cudaGetSymbolAddress((void**)&up,   g_up);
    cudaGetSymbolAddress((void**)&giT,  g_giT);
    cudaGetSymbolAddress((void**)&gfT,  g_gfT);
    cudaGetSymbolAddress((void**)&Fc,   g_Fc);
    cudaGetSymbolAddress((void**)&a,    g_a);
    cudaGetSymbolAddress((void**)&m,    g_m);
    cudaGetSymbolAddress((void**)&wcol, g_wcol);
    cudaGetSymbolAddress((void**)&amaxT,g_amaxT);
    cudaGetSymbolAddress((void**)&Wg,   g_Wg);
    cudaGetSymbolAddress((void**)&hnbf, g_hn_bf);
    cudaGetSymbolAddress((void**)&xcbf, g_xc_bf);
    cudaGetSymbolAddress((void**)&upbf, g_up_bf);
    cudaGetSymbolAddress((void**)&qbf,  g_q_bf);
    cudaGetSymbolAddress((void**)&kbf,  g_k_bf);
    cudaGetSymbolAddress((void**)&vbf,  g_v_bf);
    cudaGetSymbolAddress((void**)&att2bf, g_att2_bf);
    cudaGetSymbolAddress((void**)&wupbf, g_wup_bf);
    cudaGetSymbolAddress((void**)&wqbf,  g_wq_bf);
    cudaGetSymbolAddress((void**)&wkbf,  g_wk_bf);
    cudaGetSymbolAddress((void**)&wvbf,  g_wv_bf);
    cudaGetSymbolAddress((void**)&wdnbf, g_wdn_bf);

    int attn_smem = (64*QKW + 8192 + 8192 + 64 + 64 + 128 + 128) * 4;
    static int attr_set = 0;
    if (!attr_set){
        cudaFuncSetAttribute(attn_bf16, cudaFuncAttributeMaxDynamicSharedMemorySize, attn_smem);
        attr_set = 1;
    }

    int n0 = NL*DMODEL*1024, n1 = NL*DI*DI, n4 = NL*DI*DMODEL;
    int ntot = n0 + 3*n1 + n4;
    f2bf5_kernel<<<(ntot/2 + 255)/256, 256>>>(Wup, wupbf, n0,
                                              Wq, wqbf, n1,
                                              Wk, wkbf, n1,
                                              Wv, wvbf, n1,
                                              Wdn, wdnbf, n4);
    gatew_kernel<<<NL*1024*8/256, 256>>>(Wq, Wk, Wv, Wif, Wg);

    embed_kernel<<<TOK*256/256, 256>>>(x, tf, Wp, bp, h);

    for (int l=0; l<NL; l++){
        ln_kernel<<<TOK/8, 256>>>(h, ln_g + l*256, ln_b + l*256, hnbf);
        gemm_bf16<<<dim3(1024/64, TOK/128, 1), 256>>>(hnbf, 256, wupbf + (size_t)l*256*1024, 1024,
                                                   up, 1024, bup + l*1024, nullptr, 256,
                                                   upbf, 512, nullptr, nullptr, nullptr, nullptr, nullptr);
        conv_gates_kernel<<<TOK, 256>>>(up, cw + l*4*512, cb + l*512,
                                        Wg + (size_t)l*8192, bif + l*8,
                                        xcbf, giT, gfT);
        gemm_bf16<<<dim3(512/64, TOK/128, 3), 256>>>(xcbf, 512, wqbf + (size_t)l*512*512, 512,
                                                  nullptr, 512, nullptr, nullptr, 512, qbf, 512,
                                                  upbf,
                                                  wkbf + (size_t)l*512*512, kbf,
                                                  wvbf + (size_t)l*512*512, vbf);
        scan_kernel4<<<32, 32>>>(giT, gfT, Fc, a, m, wcol, amaxT);
        attn_bf16<<<dim3(BATCH*NH, SEQ/64), 256, attn_smem>>>(qbf, kbf, vbf, Fc, a, m,
                                                  wcol, amaxT,
                                                  xcbf, up, gng + l*512, gnb + l*512, skip + l*512,
                                                  att2bf);
        gemm_bf16<<<dim3(256/64, TOK/128, 1), 256>>>(att2bf, 512, wdnbf + (size_t)l*512*256, 256,
                                                  h, 256, bdn + l*256, h, 512,
                                                  nullptr, 0, nullptr, nullptr, nullptr, nullptr, nullptr);
    }
    final_kernel<<<BATCH, 256>>>(h, lnfg, lnfb, Wf, bf, (float*)d_out);
}

// round 12
// speedup vs baseline: 1.0177x; 1.0133x over previous
#include <cuda_runtime.h>
#include <cuda_bf16.h>
#include <cstdint>
#include <cstddef>

#define SEQ 1024
#define BATCH 8
#define TOK (BATCH*SEQ)
#define DMODEL 256
#define DI 512
#define NH 4
#define DHH 128
#define NL 4

// ---------------- scratch (device globals; no allocation allowed) ----------------
__device__ float g_h[TOK*DMODEL];
__device__ float g_up[TOK*1024];
__device__ float g_xc[TOK*DI];
__device__ float g_giT[BATCH*NH*SEQ];
__device__ float g_gfT[BATCH*NH*SEQ];
__device__ float g_Fc[BATCH*NH*SEQ];
__device__ float g_a[BATCH*NH*SEQ];
__device__ float g_m[BATCH*NH*SEQ];
__device__ float g_wcol[BATCH*NH*SEQ];
__device__ float g_amaxT[BATCH*NH*16];
__device__ float g_Wg[NL*1024*8];

__device__ __nv_bfloat16 g_hn_bf[TOK*DMODEL];
__device__ __nv_bfloat16 g_xc_bf[TOK*DI];
__device__ __nv_bfloat16 g_up_bf[TOK*DI];
__device__ __nv_bfloat16 g_q_bf[TOK*DI];
__device__ __nv_bfloat16 g_k_bf[TOK*DI];
__device__ __nv_bfloat16 g_v_bf[TOK*DI];
__device__ __nv_bfloat16 g_att2_bf[TOK*DI];
__device__ __nv_bfloat16 g_wup_bf[NL*DMODEL*1024];
__device__ __nv_bfloat16 g_wq_bf[NL*DI*DI];
__device__ __nv_bfloat16 g_wk_bf[NL*DI*DI];
__device__ __nv_bfloat16 g_wv_bf[NL*DI*DI];
__device__ __nv_bfloat16 g_wdn_bf[NL*DI*DMODEL];

__device__ __forceinline__ float warp_sum(float v){
    #pragma unroll
    for (int o=16;o;o>>=1) v += __shfl_xor_sync(0xffffffffu, v, o);
    return v;
}

__device__ __forceinline__ uint32_t bf2pack(float x, float y){
    __nv_bfloat162 t = __floats2bfloat162_rn(x, y);
    return *(uint32_t*)&t;
}

__device__ __forceinline__ void mma_bf16(float* c, const uint32_t* a, uint32_t b0, uint32_t b1){
    asm volatile(
      "mma.sync.aligned.m16n8k16.row.col.f32.bf16.bf16.f32 "
      "{%0,%1,%2,%3}, {%4,%5,%6,%7}, {%8,%9}, {%0,%1,%2,%3};\n"
      : "+f"(c[0]), "+f"(c[1]), "+f"(c[2]), "+f"(c[3])
      : "r"(a[0]), "r"(a[1]), "r"(a[2]), "r"(a[3]), "r"(b0), "r"(b1));
}

__device__ __forceinline__ uint32_t smaddr(const void* p){
    return (uint32_t)__cvta_generic_to_shared(p);
}
#define CPA16(dst,src) asm volatile("cp.async.cg.shared.global [%0], [%1], 16;\n"::"r"(dst),"l"(src))
#define CPCOMMIT() asm volatile("cp.async.commit_group;\n")
#define CPWAIT(n) asm volatile("cp.async.wait_group %0;\n"::"n"(n))

// ---------------- merged f32 -> bf16 convert for all 5 weight tensors ----------------
__global__ void f2bf5_kernel(const float* __restrict__ i0, __nv_bfloat16* __restrict__ o0, int n0,
                             const float* __restrict__ i1, __nv_bfloat16* __restrict__ o1, int n1,
                             const float* __restrict__ i2, __nv_bfloat16* __restrict__ o2, int n2,
                             const float* __restrict__ i3, __nv_bfloat16* __restrict__ o3, int n3,
                             const float* __restrict__ i4, __nv_bfloat16* __restrict__ o4, int n4){
    int i = (blockIdx.x*blockDim.x + threadIdx.x)*2;
    const float* in; __nv_bfloat16* out;
    if (i < n0){ in=i0; out=o0; }
    else if ((i-=n0) < n1){ in=i1; out=o1; }
    else if ((i-=n1) < n2){ in=i2; out=o2; }
    else if ((i-=n2) < n3){ in=i3; out=o3; }
    else if ((i-=n3) < n4){ in=i4; out=o4; }
    else return;
    float2 v = *(const float2*)(in+i);
    *(__nv_bfloat162*)(out+i) = __floats2bfloat162_rn(v.x, v.y);
}

// ---------------- composite gate weights: Wg = [Wq@Wif_i + Wk@Wif_k ; Wv@Wif_v] ----------------
__global__ void gatew_kernel(const float* __restrict__ Wq, const float* __restrict__ Wk,
                             const float* __restrict__ Wv, const float* __restrict__ Wif,
                             float* __restrict__ Wg){
    int idx = blockIdx.x*blockDim.x + threadIdx.x;   // NL*1024*8
    int l = idx >> 13; int r = idx & 8191;
    int c = r >> 3; int j = r & 7;
    const float* Wifl = Wif + (size_t)l*1536*8;
    float acc = 0.f;
    if (c < 512){
        const float* wq = Wq + ((size_t)l*512 + c)*512;
        const float* wk = Wk + ((size_t)l*512 + c)*512;
        #pragma unroll 4
        for (int i=0;i<512;i++)
            acc += wq[i]*Wifl[i*8+j] + wk[i]*Wifl[(512+i)*8+j];
    } else {
        const float* wv = Wv + ((size_t)l*512 + (c-512))*512;
        #pragma unroll 4
        for (int i=0;i<512;i++)
            acc += wv[i]*Wifl[(1024+i)*8+j];
    }
    Wg[(size_t)l*8192 + c*8 + j] = acc;
}

// ---------------- embed ----------------
__global__ void embed_kernel(const float* __restrict__ x, const float* __restrict__ tf,
                             const float* __restrict__ Wp, const float* __restrict__ bp,
                             float* __restrict__ h){
    int idx = blockIdx.x*blockDim.x + threadIdx.x;
    int j = idx & 255; int tok = idx >> 8;
    float acc = bp[j] + x[tok]*Wp[j];
    #pragma unroll
    for (int f=0; f<4; f++) acc += tf[tok*4+f]*Wp[(1+f)*256+j];
    h[idx] = acc;
}

// ---------------- layernorm, bf16 out (fused E[x^2] variance, one reduction round) ----------------
__global__ void ln_kernel(const float* __restrict__ x, const float* __restrict__ g,
                          const float* __restrict__ b, __nv_bfloat16* __restrict__ y){
    int row = blockIdx.x*8 + (threadIdx.x>>5);
    int lane = threadIdx.x & 31;
    const float* xr = x + (size_t)row*256;
    float4 v0 = *(const float4*)(xr + lane*4);
    float4 v1 = *(const float4*)(xr + 128 + lane*4);
    float s  = v0.x+v0.y+v0.z+v0.w + v1.x+v1.y+v1.z+v1.w;
    float sq = v0.x*v0.x+v0.y*v0.y+v0.z*v0.z+v0.w*v0.w
             + v1.x*v1.x+v1.y*v1.y+v1.z*v1.z+v1.w*v1.w;
    #pragma unroll
    for (int o=16;o;o>>=1){
        s  += __shfl_xor_sync(0xffffffffu, s,  o);
        sq += __shfl_xor_sync(0xffffffffu, sq, o);
    }
    float mu = s * (1.f/256.f);
    float var = sq * (1.f/256.f) - mu*mu;
    float is = rsqrtf(var + 1e-5f);
    float4 g0 = *(const float4*)(g + lane*4);
    float4 g1 = *(const float4*)(g + 128 + lane*4);
    float4 b0 = *(const float4*)(b + lane*4);
    float4 b1 = *(const float4*)(b + 128 + lane*4);
    __nv_bfloat16* yr = y + (size_t)row*256;
    *(__nv_bfloat162*)&yr[lane*4]       = __floats2bfloat162_rn((v0.x-mu)*is*g0.x + b0.x, (v0.y-mu)*is*g0.y + b0.y);
    *(__nv_bfloat162*)&yr[lane*4+2]     = __floats2bfloat162_rn((v0.z-mu)*is*g0.z + b0.z, (v0.w-mu)*is*g0.w + b0.w);
    *(__nv_bfloat162*)&yr[128+lane*4]   = __floats2bfloat162_rn((v1.x-mu)*is*g1.x + b1.x, (v1.y-mu)*is*g1.y + b1.y);
    *(__nv_bfloat162*)&yr[128+lane*4+2] = __floats2bfloat162_rn((v1.z-mu)*is*g1.z + b1.z, (v1.w-mu)*is*g1.w + b1.w);
}

// ---------------- bf16 tensor-core GEMM, cp.async double-buffered ----------------
__global__ __launch_bounds__(256) void gemm_bf16(
    const __nv_bfloat16* __restrict__ A, int lda,
    const __nv_bfloat16* __restrict__ B, int ldb,
    float* __restrict__ C, int ldc,
    const float* __restrict__ bias,
    const float* __restrict__ resid,
    int K,
    __nv_bfloat16* __restrict__ Cbf, int bfcap,
    const __nv_bfloat16* __restrict__ A2,
    const __nv_bfloat16* __restrict__ B2,
    __nv_bfloat16* __restrict__ Cbf2,
    const __nv_bfloat16* __restrict__ B3,
    __nv_bfloat16* __restrict__ Cbf3)
{
    __shared__ __nv_bfloat16 As[2][128*64];
    __shared__ __nv_bfloat16 Bs[2][64*64];
    if (blockIdx.z == 1){ B = B2; Cbf = Cbf2; }
    else if (blockIdx.z == 2){ A = A2; B = B3; Cbf = Cbf3; }
    int tid = threadIdx.x, lane = tid&31, wid = tid>>5;
    int wm = wid>>1, wn = wid&1;
    int m0 = blockIdx.y*128, n0 = blockIdx.x*64;

    int ar = tid >> 1;
    int ac0 = (tid & 1) << 2;
    int br = tid >> 2;
    int bc0 = (tid & 3) << 1;
    const __nv_bfloat16* Ag = A + (size_t)(m0+ar)*lda;
    const __nv_bfloat16* Bg = B + (size_t)br*ldb + n0;

    int KC = K >> 6;
    {
        #pragma unroll
        for (int c=0;c<4;c++){
            int ch = ac0+c;
            CPA16(smaddr(&As[0][ar*64 + ((ch ^ (ar&7))<<3)]), Ag + (ch<<3));
        }
        #pragma unroll
        for (int c=0;c<2;c++){
            int ch = bc0+c;
            CPA16(smaddr(&Bs[0][br*64 + ((ch ^ (br&7))<<3)]), Bg + (ch<<3));
        }
        CPCOMMIT();
    }

    float acc[2][4][4] = {};
    int g = lane>>3, lr = lane&7;

    for (int kc=0; kc<KC; kc++){
        int cur = kc & 1;
        if (kc+1 < KC){
            int nb = (kc+1)&1, k0 = (kc+1)<<6;
            #pragma unroll
            for (int c=0;c<4;c++){
                int ch = ac0+c;
                CPA16(smaddr(&As[nb][ar*64 + ((ch ^ (ar&7))<<3)]), Ag + k0 + (ch<<3));
            }
            #pragma unroll
            for (int c=0;c<2;c++){
                int ch = bc0+c;
                CPA16(smaddr(&Bs[nb][br*64 + ((ch ^ (br&7))<<3)]), Bg + (size_t)k0*ldb + (ch<<3));
            }
            CPCOMMIT();
            CPWAIT(1);
        } else {
            CPWAIT(0);
        }
        __syncthreads();

        #pragma unroll
        for (int ks=0; ks<4; ks++){
            uint32_t af[2][4];
            #pragma unroll
            for (int mt=0; mt<2; mt++){
                int arow = wm*32 + mt*16 + lr + ((g&1)<<3);
                int ch = (ks<<1) + (g>>1);
                uint32_t addr = smaddr(&As[cur][arow*64 + ((ch ^ (arow&7))<<3)]);
                asm volatile("ldmatrix.sync.aligned.m8n8.x4.shared.b16 {%0,%1,%2,%3}, [%4];\n"
                    : "=r"(af[mt][0]),"=r"(af[mt][1]),"=r"(af[mt][2]),"=r"(af[mt][3]) : "r"(addr));
            }
            uint32_t bf[4][2];
            int krow = (ks<<4) + lr + ((g&1)<<3);
            #pragma unroll
            for (int nt=0; nt<4; nt++){
                int ch = wn*4 + nt;
                uint32_t addr = smaddr(&Bs[cur][krow*64 + ((ch ^ (krow&7))<<3)]);
                asm volatile("ldmatrix.sync.aligned.m8n8.x2.trans.shared.b16 {%0,%1}, [%2];\n"
                    : "=r"(bf[nt][0]),"=r"(bf[nt][1]) : "r"(addr));
            }
            #pragma unroll
            for (int mt=0;mt<2;mt++)
              #pragma unroll
              for (int nt=0;nt<4;nt++)
                mma_bf16(acc[mt][nt], af[mt], bf[nt][0], bf[nt][1]);
        }
        __syncthreads();
    }

    #pragma unroll
    for (int mt=0;mt<2;mt++){
        #pragma unroll
        for (int nt=0;nt<4;nt++){
            int row0 = m0 + wm*32 + mt*16 + (lane>>2);
            int col  = n0 + wn*32 + nt*8 + ((lane&3)<<1);
            float bx=0.f, by=0.f;
            if (bias){ bx = bias[col]; by = bias[col+1]; }
            float2 r0v = make_float2(0.f,0.f), r1v = make_float2(0.f,0.f);
            if (resid){
                r0v = *(const float2*)&resid[(size_t)row0*ldc + col];
                r1v = *(const float2*)&resid[(size_t)(row0+8)*ldc + col];
            }
            float v00 = acc[mt][nt][0]+bx+r0v.x, v01 = acc[mt][nt][1]+by+r0v.y;
            float v10 = acc[mt][nt][2]+bx+r1v.x, v11 = acc[mt][nt][3]+by+r1v.y;
            if (C){
                *(float2*)&C[(size_t)row0*ldc + col]     = make_float2(v00, v01);
                *(float2*)&C[(size_t)(row0+8)*ldc + col] = make_float2(v10, v11);
            }
            if (Cbf && col < bfcap){
                *(__nv_bfloat162*)&Cbf[(size_t)row0*bfcap + col]     = __floats2bfloat162_rn(v00, v01);
                *(__nv_bfloat162*)&Cbf[(size_t)(row0+8)*bfcap + col] = __floats2bfloat162_rn(v10, v11);
            }
        }
    }
}

// ---------------- fused causal conv + silu + composite gates ----------------
__global__ __launch_bounds__(256) void conv_gates_kernel(
    const float* __restrict__ up, const float* __restrict__ cw, const float* __restrict__ cb,
    const float* __restrict__ Wg, const float* __restrict__ bif,
    float* __restrict__ xc, __nv_bfloat16* __restrict__ xcbf,
    float* __restrict__ giT, float* __restrict__ gfT)
{
    __shared__ float xcs[512], xms[512];
    int tok = blockIdx.x, tid = threadIdx.x;
    int t = tok & 1023;
    #pragma unroll
    for (int r=0;r<2;r++){
        int c = tid + (r<<8);
        float xm = up[(size_t)tok*1024 + c];
        float acc = cb[c] + cw[3*512+c]*xm;
        #pragma unroll
        for (int j=0;j<3;j++){
            int ts = t - 3 + j;
            if (ts >= 0) acc += cw[j*512+c]*up[(size_t)(tok-3+j)*1024 + c];
        }
        float sv = acc/(1.f+expf(-acc));
        xcs[c] = sv; xms[c] = xm;
        xc[(size_t)tok*512 + c] = sv;
        xcbf[(size_t)tok*512 + c] = __float2bfloat16(sv);
    }
    __syncthreads();
    int w = tid>>5, lane = tid&31;
    float acc = 0.f;
    for (int i=lane;i<512;i+=32) acc += xcs[i]*Wg[i*8+w] + xms[i]*Wg[(512+i)*8+w];
    acc = warp_sum(acc);
    if (!lane){
        float r = acc + bif[w];
        int b = tok >> 10, s = tok & 1023;
        if (w < 4) giT[(size_t)(b*4+w)*1024 + s] = r;
        else       gfT[(size_t)(b*4+w-4)*1024 + s] = r;
    }
}

// ---------------- gate scan + per-tile col weights ----------------
__global__ void scan_kernel4(const float* __restrict__ giT, const float* __restrict__ gfT,
                             float* __restrict__ Fc, float* __restrict__ a, float* __restrict__ m,
                             float* __restrict__ wcol, float* __restrict__ amaxT){
    __shared__ float ash[1024];
    int bh = blockIdx.x, lane = threadIdx.x;
    const float* gih = giT + (size_t)bh*1024;
    const float* gfh = gfT + (size_t)bh*1024;
    const float scale = 0.08838834764831845f;
    float cfc = 0.f, cmax = -1e30f;
    float ipc = gih[lane], fpc = gfh[lane];
    for (int c=0;c<32;c++){
        float ip = ipc, fp = fpc;
        if (c+1 < 32){ ipc = gih[(c+1)*32+lane]; fpc = gfh[(c+1)*32+lane]; }
        float lf = fminf(fp, 0.f) - log1pf(expf(-fabsf(fp)));
        float x = lf;
        #pragma unroll
        for (int o=1;o<32;o<<=1){ float y = __shfl_up_sync(0xffffffffu, x, o); if (lane>=o) x += y; }
        float fc = cfc + x;
        float av = ip - fc;
        float mx = av;
        #pragma unroll
        for (int o=1;o<32;o<<=1){ float y = __shfl_up_sync(0xffffffffu, mx, o); if (lane>=o) mx = fmaxf(mx, y); }
        float cm = fmaxf(cmax, mx);
        int off = bh*SEQ + c*32 + lane;
        Fc[off] = fc; a[off] = av; m[off] = fc + cm;
        ash[c*32 + lane] = av;
        cfc += __shfl_sync(0xffffffffu, x, 31);
        cmax = fmaxf(cmax, __shfl_sync(0xffffffffu, mx, 31));
    }
    __syncwarp();
    for (int tile=0;tile<16;tile++){
        float v0 = ash[tile*64 + lane];
        float v1 = ash[tile*64 + 32 + lane];
        float mx = fmaxf(v0, v1);
        #pragma unroll
        for (int o=16;o;o>>=1) mx = fmaxf(mx, __shfl_xor_sync(0xffffffffu, mx, o));
        if (lane == 0) amaxT[bh*16 + tile] = mx;
        wcol[bh*SEQ + tile*64 + lane]      = scale*__expf(v0 - mx);
        wcol[bh*SEQ + tile*64 + 32 + lane] = scale*__expf(v1 - mx);
    }
}

// ---------------- mLSTM attention + fused GN/skip/silu-gate epilogue (R9 structure) ----------------
#define QKW 68
#define VW  64
#define PW  36
__global__ __launch_bounds__(256) void attn_bf16(
    const __nv_bfloat16* __restrict__ q, const __nv_bfloat16* __restrict__ k,
    const __nv_bfloat16* __restrict__ v,
    const float* __restrict__ Fcv, const float* __restrict__ av, const float* __restrict__ mv,
    const float* __restrict__ wcol, const float* __restrict__ amaxT,
    const float* __restrict__ xc, const float* __restrict__ up,
    const float* __restrict__ gng, const float* __restrict__ gnb,
    const float* __restrict__ skip,
    __nv_bfloat16* __restrict__ out)
{
    extern __shared__ uint32_t smu[];
    uint32_t* Qs = smu;                  // 64*68 words; reused as P (64*36)
    uint32_t* Ks = Qs + 64*QKW;
    uint32_t* Vs = Ks + 64*QKW;          // 64*64 words
    float* fct  = (float*)(Vs + 64*VW);  // 64
    float* mt   = fct + 64;              // 64
    float* as_  = mt + 64;               // 64 (wcol off-diag / raw a on diag)
    float* den2 = as_ + 64;              // 128
    float* dsq  = den2 + 128;            // 128

    int bh = blockIdx.x; int b = bh>>2, hh = bh&3;
    int it = (int)(gridDim.y - 1) - (int)blockIdx.y;
    int t0 = it<<6;
    int tid = threadIdx.x, lane = tid&31, wid = tid>>5;
    int wm = wid>>1, wn = wid&1;
    int ls = lane>>2, lk = lane&3;
    int g8 = lane>>3, lr = lane&7;
    const float scale = 0.08838834764831845f;

    const __nv_bfloat16* qg = q + ((size_t)(b*SEQ + t0))*512 + hh*128;
    #pragma unroll
    for (int r=0;r<4;r++){
        int idx = tid + (r<<8);
        int row = idx>>4, c16 = idx&15;
        uint4 val = *(const uint4*)(qg + (size_t)row*512 + (c16<<3));
        *(uint4*)&Qs[row*QKW + (c16<<2)] = val;
    }
    if (tid < 64){ int tg = bh*SEQ + t0 + tid; fct[tid] = Fcv[tg]; mt[tid] = mv[tg]; }
    __syncthreads();

    uint32_t qf[8][4];
    int r0 = wm*16 + ls, r1 = r0 + 8;
    #pragma unroll
    for (int ks=0; ks<8; ks++){
        qf[ks][0] = Qs[r0*QKW + ks*8 + lk];
        qf[ks][1] = Qs[r1*QKW + ks*8 + lk];
        qf[ks][2] = Qs[r0*QKW + ks*8 + lk + 4];
        qf[ks][3] = Qs[r1*QKW + ks*8 + lk + 4];
    }

    float oacc[8][4];
    #pragma unroll
    for (int i=0;i<8;i++){ oacc[i][0]=0.f; oacc[i][1]=0.f; oacc[i][2]=0.f; oacc[i][3]=0.f; }
    float den0 = 0.f, den1 = 0.f;

    for (int js=0; js<=it; js++){
        int s0 = js<<6;
        bool diag = (js == it);
        __syncthreads();
        const __nv_bfloat16* kg = k + ((size_t)(b*SEQ + s0))*512 + hh*128;
        const __nv_bfloat16* vg = v + ((size_t)(b*SEQ + s0))*512 + hh*128;
        #pragma unroll
        for (int r=0;r<4;r++){
            int idx = tid + (r<<8);
            int row = idx>>4, c16 = idx&15;
            uint4 kv = *(const uint4*)(kg + (size_t)row*512 + (c16<<3));
            uint4 vv = *(const uint4*)(vg + (size_t)row*512 + (c16<<3));
            *(uint4*)&Ks[row*QKW + (c16<<2)] = kv;
            *(uint4*)&Vs[row*VW + ((c16 ^ (row&7))<<2)] = vv;
        }
        if (tid < 64)
            as_[tid] = diag ? av[bh*SEQ + s0 + tid] : wcol[bh*SEQ + s0 + tid];
        __syncthreads();

        float sacc[4][4] = {};
        #pragma unroll
        for (int ks=0; ks<8; ks++){
            #pragma unroll
            for (int nt=0; nt<4; nt++){
                int sc = wn*32 + nt*8 + ls;
                uint32_t b0 = Ks[sc*QKW + ks*8 + lk];
                uint32_t b1 = Ks[sc*QKW + ks*8 + lk + 4];
                mma_bf16(sacc[nt], qf[ks], b0, b1);
            }
        }

        float f0 = fct[r0], mm0 = mt[r0], f1 = fct[r1], mm1 = mt[r1];
        if (!diag){
            float amx = amaxT[bh*16 + js];
            float w0 = __expf(f0 - mm0 + amx);
            float w1 = __expf(f1 - mm1 + amx);
            #pragma unroll
            for (int nt=0; nt<4; nt++){
                int c0 = wn*32 + nt*8 + (lk<<1);
                float wc0 = as_[c0], wc1 = as_[c0+1];
                float v00 = sacc[nt][0]*w0*wc0;
                float v01 = sacc[nt][1]*w0*wc1;
                float v10 = sacc[nt][2]*w1*wc0;
                float v11 = sacc[nt][3]*w1*wc1;
                den0 += v00 + v01;
                den1 += v10 + v11;
                int wcl = wn*16 + nt*4 + lk;
                Qs[r0*PW + wcl] = bf2pack(v00, v01);
                Qs[r1*PW + wcl] = bf2pack(v10, v11);
            }
        } else {
            #pragma unroll
            for (int nt=0; nt<4; nt++){
                int c0 = wn*32 + nt*8 + (lk<<1);
                int c1 = c0 + 1;
                float a0v = as_[c0], a1v = as_[c1];
                float v00 = sacc[nt][0]*scale*__expf(f0 + a0v - mm0);
                float v01 = sacc[nt][1]*scale*__expf(f0 + a1v - mm0);
                float v10 = sacc[nt][2]*scale*__expf(f1 + a0v - mm1);
                float v11 = sacc[nt][3]*scale*__expf(f1 + a1v - mm1);
                if (c0 > r0) v00 = 0.f;
                if (c1 > r0) v01 = 0.f;
                if (c0 > r1) v10 = 0.f;
                if (c1 > r1) v11 = 0.f;
                den0 += v00 + v01;
                den1 += v10 + v11;
                int wcl = wn*16 + nt*4 + lk;
                Qs[r0*PW + wcl] = bf2pack(v00, v01);
                Qs[r1*PW + wcl] = bf2pack(v10, v11);
            }
        }
        __syncthreads();

        #pragma unroll
        for (int ks2=0; ks2<4; ks2++){
            uint32_t af[4];
            af[0] = Qs[r0*PW + ks2*8 + lk];
            af[1] = Qs[r1*PW + ks2*8 + lk];
            af[2] = Qs[r0*PW + ks2*8 + lk + 4];
            af[3] = Qs[r1*PW + ks2*8 + lk + 4];
            int krow = (ks2<<4) + lr + ((g8&1)<<3);
            #pragma unroll
            for (int nt=0; nt<8; nt++){
                int cd = wn*8 + nt;
                uint32_t addr = smaddr(&Vs[krow*VW + ((cd ^ (krow&7))<<2)]);
                uint32_t b0, b1;
                asm volatile("ldmatrix.sync.aligned.m8n8.x2.trans.shared.b16 {%0,%1}, [%2];\n"
                    : "=r"(b0),"=r"(b1) : "r"(addr));
                mma_bf16(oacc[nt], af, b0, b1);
            }
        }
    }

    // ---- denominator ----
    den0 += __shfl_xor_sync(0xffffffffu, den0, 1);
    den0 += __shfl_xor_sync(0xffffffffu, den0, 2);
    den1 += __shfl_xor_sync(0xffffffffu, den1, 1);
    den1 += __shfl_xor_sync(0xffffffffu, den1, 2);
    if (lk == 0){ den2[wn*64 + r0] = den0; den2[wn*64 + r1] = den1; }
    __syncthreads();
    float dt0 = den2[r0] + den2[64 + r0];
    float dt1 = den2[r1] + den2[64 + r1];
    float inv0 = 1.f / (fmaxf(fabsf(dt0), __expf(-mt[r0])) + 1e-6f);
    float inv1 = 1.f / (fmaxf(fabsf(dt1), __expf(-mt[r1])) + 1e-6f);

    float hv0[16], hv1[16];
    #pragma unroll
    for (int nt=0; nt<8; nt++){
        hv0[nt*2]   = oacc[nt][0]*inv0;
        hv0[nt*2+1] = oacc[nt][1]*inv0;
        hv1[nt*2]   = oacc[nt][2]*inv1;
        hv1[nt*2+1] = oacc[nt][3]*inv1;
    }

    // ---- fused GroupNorm via E[x^2] (single reduction round) ----
    float s0 = 0.f, s1 = 0.f, q0 = 0.f, q1 = 0.f;
    #pragma unroll
    for (int i=0;i<16;i++){
        s0 += hv0[i]; q0 += hv0[i]*hv0[i];
        s1 += hv1[i]; q1 += hv1[i]*hv1[i];
    }
    #pragma unroll
    for (int o=1;o<4;o<<=1){
        s0 += __shfl_xor_sync(0xffffffffu, s0, o);
        q0 += __shfl_xor_sync(0xffffffffu, q0, o);
        s1 += __shfl_xor_sync(0xffffffffu, s1, o);
        q1 += __shfl_xor_sync(0xffffffffu, q1, o);
    }
    __syncthreads();   // den2 free from denominator use
    if (lk == 0){
        den2[wn*64 + r0] = s0; den2[wn*64 + r1] = s1;
        dsq[wn*64 + r0]  = q0; dsq[wn*64 + r1]  = q1;
    }
    __syncthreads();
    float mu0 = (den2[r0] + den2[64 + r0]) * (1.f/128.f);
    float mu1 = (den2[r1] + den2[64 + r1]) * (1.f/128.f);
    float e20 = (dsq[r0] + dsq[64 + r0]) * (1.f/128.f);
    float e21 = (dsq[r1] + dsq[64 + r1]) * (1.f/128.f);
    float is0 = rsqrtf(e20 - mu0*mu0 + 1e-5f);
    float is1 = rsqrtf(e21 - mu1*mu1 + 1e-5f);

    // ---- gamma/beta + skip*xc + silu(z), bf16 store ----
    size_t tok0 = (size_t)(b*SEQ + t0 + r0), tok1 = (size_t)(b*SEQ + t0 + r1);
    #pragma unroll
    for (int nt=0; nt<8; nt++){
        int dc = wn*64 + nt*8 + (lk<<1);
        int c = hh*128 + dc;
        float2 gg = *(const float2*)&gng[c];
        float2 gb = *(const float2*)&gnb[c];
        float2 sk = *(const float2*)&skip[c];
        float2 x0 = *(const float2*)&xc[tok0*512 + c];
        float2 x1 = *(const float2*)&xc[tok1*512 + c];
        float2 z0 = *(const float2*)&up[tok0*1024 + 512 + c];
        float2 z1 = *(const float2*)&up[tok1*1024 + 512 + c];
        float y00 = (hv0[nt*2]  -mu0)*is0*gg.x + gb.x + sk.x*x0.x;
        float y01 = (hv0[nt*2+1]-mu0)*is0*gg.y + gb.y + sk.y*x0.y;
        float y10 = (hv1[nt*2]  -mu1)*is1*gg.x + gb.x + sk.x*x1.x;
        float y11 = (hv1[nt*2+1]-mu1)*is1*gg.y + gb.y + sk.y*x1.y;
        y00 *= z0.x / (1.f + expf(-z0.x));
        y01 *= z0.y / (1.f + expf(-z0.y));
        y10 *= z1.x / (1.f + expf(-z1.x));
        y11 *= z1.y / (1.f + expf(-z1.y));
        *(__nv_bfloat162*)&out[tok0*512 + c] = __floats2bfloat162_rn(y00, y01);
        *(__nv_bfloat162*)&out[tok1*512 + c] = __floats2bfloat162_rn(y10, y11);
    }
}

// ---------------- final ----------------
__global__ void final_kernel(const float* __restrict__ h, const float* __restrict__ g,
                             const float* __restrict__ b, const float* __restrict__ Wf,
                             const float* __restrict__ bf, float* __restrict__ out){
    __shared__ float sh[8];
    __shared__ float sv;
    int bb = blockIdx.x, tid = threadIdx.x;
    float vv = h[((size_t)(bb*SEQ + SEQ-1))*256 + tid];
    float s = warp_sum(vv);
    if (!(tid&31)) sh[tid>>5] = s;
    __syncthreads();
    if (tid==0){ float t=0; for(int i=0;i<8;i++) t+=sh[i]; sv = t*(1.f/256.f); }
    __syncthreads();
    float mu = sv;
    float d = vv - mu;
    float s2 = warp_sum(d*d);
    if (!(tid&31)) sh[tid>>5] = s2;
    __syncthreads();
    if (tid==0){ float t=0; for(int i=0;i<8;i++) t+=sh[i]; sv = t*(1.f/256.f); }
    __syncthreads();
    float yn = d*rsqrtf(sv + 1e-5f)*g[tid] + b[tid];
    float p = yn * Wf[tid];
    float s3 = warp_sum(p);
    __syncthreads();
    if (!(tid&31)) sh[tid>>5] = s3;
    __syncthreads();
    if (tid==0){ float t=0; for(int i=0;i<8;i++) t+=sh[i]; out[bb] = t + bf[0]; }
}

// ---------------- launch ----------------
extern "C" void kernel_launch(void* const* d_in, const int* in_sizes, int n_in,
                              void* d_out, int out_size){
    const float* x    = (const float*)d_in[0];
    const float* tf   = (const float*)d_in[1];
    const float* Wp   = (const float*)d_in[2];
    const float* bp   = (const float*)d_in[3];
    const float* ln_g = (const float*)d_in[4];
    const float* ln_b = (const float*)d_in[5];
    const float* Wup  = (const float*)d_in[6];
    const float* bup  = (const float*)d_in[7];
    const float* cw   = (const float*)d_in[8];
    const float* cb   = (const float*)d_in[9];
    const float* Wq   = (const float*)d_in[10];
    const float* Wk   = (const float*)d_in[11];
    const float* Wv   = (const float*)d_in[12];
    const float* Wif  = (const float*)d_in[13];
    const float* bif  = (const float*)d_in[14];
    const float* gng  = (const float*)d_in[15];
    const float* gnb  = (const float*)d_in[16];
    const float* skip = (const float*)d_in[17];
    const float* Wdn  = (const float*)d_in[18];
    const float* bdn  = (const float*)d_in[19];
    const float* lnfg = (const float*)d_in[20];
    const float* lnfb = (const float*)d_in[21];
    const float* Wf   = (const float*)d_in[22];
    const float* bf   = (const float*)d_in[23];

    float *h,*up,*xc,*giT,*gfT,*Fc,*a,*m,*wcol,*amaxT,*Wg;
    __nv_bfloat16 *hnbf,*xcbf,*upbf,*qbf,*kbf,*vbf,*att2bf,*wupbf,*wqbf,*wkbf,*wvbf,*wdnbf;
    cudaGetSymbolAddress((void**)&h,    g_h);
    cudaGetSymbolAddress((void**)&up,   g_up);
    cudaGetSymbolAddress((void**)&xc,   g_xc);
    cudaGetSymbolAddress((void**)&giT,  g_giT);
    cudaGetSymbolAddress((void**)&gfT,  g_gfT);
    cudaGetSymbolAddress((void**)&Fc,   g_Fc);
    cudaGetSymbolAddress((void**)&a,    g_a);
    cudaGetSymbolAddress((void**)&m,    g_m);
    cudaGetSymbolAddress((void**)&wcol, g_wcol);
    cudaGetSymbolAddress((void**)&amaxT,g_amaxT);
    cudaGetSymbolAddress((void**)&Wg,   g_Wg);
    cudaGetSymbolAddress((void**)&hnbf, g_hn_bf);
    cudaGetSymbolAddress((void**)&xcbf, g_xc_bf);
    cudaGetSymbolAddress((void**)&upbf, g_up_bf);
    cudaGetSymbolAddress((void**)&qbf,  g_q_bf);
    cudaGetSymbolAddress((void**)&kbf,  g_k_bf);
    cudaGetSymbolAddress((void**)&vbf,  g_v_bf);
    cudaGetSymbolAddress((void**)&att2bf, g_att2_bf);
    cudaGetSymbolAddress((void**)&wupbf, g_wup_bf);
    cudaGetSymbolAddress((void**)&wqbf,  g_wq_bf);
    cudaGetSymbolAddress((void**)&wkbf,  g_wk_bf);
    cudaGetSymbolAddress((void**)&wvbf,  g_wv_bf);
    cudaGetSymbolAddress((void**)&wdnbf, g_wdn_bf);

    int attn_smem = (64*QKW + 64*QKW + 64*VW + 64 + 64 + 64 + 128 + 128) * 4;
    static int attr_set = 0;
    if (!attr_set){
        cudaFuncSetAttribute(attn_bf16, cudaFuncAttributeMaxDynamicSharedMemorySize, attn_smem);
        attr_set = 1;
    }

    int n0 = NL*DMODEL*1024, n1 = NL*DI*DI, n4 = NL*DI*DMODEL;
    int ntot = n0 + 3*n1 + n4;
    f2bf5_kernel<<<(ntot/2 + 255)/256, 256>>>(Wup, wupbf, n0,
                                              Wq, wqbf, n1,
                                              Wk, wkbf, n1,
                                              Wv, wvbf, n1,
                                              Wdn, wdnbf, n4);
    gatew_kernel<<<NL*1024*8/256, 256>>>(Wq, Wk, Wv, Wif, Wg);

    embed_kernel<<<TOK*256/256, 256>>>(x, tf, Wp, bp, h);

    for (int l=0; l<NL; l++){
        ln_kernel<<<TOK/8, 256>>>(h, ln_g + l*256, ln_b + l*256, hnbf);
        gemm_bf16<<<dim3(1024/64, TOK/128, 1), 256>>>(hnbf, 256, wupbf + (size_t)l*256*1024, 1024,
                                                   up, 1024, bup + l*1024, nullptr, 256,
                                                   upbf, 512, nullptr, nullptr, nullptr, nullptr, nullptr);
        conv_gates_kernel<<<TOK, 256>>>(up, cw + l*4*512, cb + l*512,
                                        Wg + (size_t)l*8192, bif + l*8,
                                        xc, xcbf, giT, gfT);
        gemm_bf16<<<dim3(512/64, TOK/128, 3), 256>>>(xcbf, 512, wqbf + (size_t)l*512*512, 512,
                                                  nullptr, 512, nullptr, nullptr, 512, qbf, 512,
                                                  upbf,
                                                  wkbf + (size_t)l*512*512, kbf,
                                                  wvbf + (size_t)l*512*512, vbf);
        scan_kernel4<<<32, 32>>>(giT, gfT, Fc, a, m, wcol, amaxT);
        attn_bf16<<<dim3(BATCH*NH, SEQ/64), 256, attn_smem>>>(qbf, kbf, vbf, Fc, a, m,
                                                  wcol, amaxT,
                                                  xc, up, gng + l*512, gnb + l*512, skip + l*512,
                                                  att2bf);
        gemm_bf16<<<dim3(256/64, TOK/128, 1), 256>>>(att2bf, 512, wdnbf + (size_t)l*512*256, 256,
                                                  h, 256, bdn + l*256, h, 512,
                                                  nullptr, 0, nullptr, nullptr, nullptr, nullptr, nullptr);
    }
    final_kernel<<<BATCH, 256>>>(h, lnfg, lnfb, Wf, bf, (float*)d_out);
}

// round 13
// speedup vs baseline: 1.0897x; 1.0708x over previous
#include <cuda_runtime.h>
#include <cuda_bf16.h>
#include <cstdint>
#include <cstddef>

#define SEQ 1024
#define BATCH 8
#define TOK (BATCH*SEQ)
#define DMODEL 256
#define DI 512
#define NH 4
#define DHH 128
#define NL 4

// ---------------- scratch (device globals; no allocation allowed) ----------------
__device__ float g_h[TOK*DMODEL];
__device__ float g_up[TOK*1024];
__device__ float g_xc[TOK*DI];
__device__ float g_giT[BATCH*NH*SEQ];
__device__ float g_gfT[BATCH*NH*SEQ];
__device__ float g_Fc[BATCH*NH*SEQ];
__device__ float g_a[BATCH*NH*SEQ];
__device__ float g_m[BATCH*NH*SEQ];
__device__ float g_wcol[BATCH*NH*SEQ];
__device__ float g_amaxT[BATCH*NH*16];
__device__ float g_Wg[NL*1024*8];

__device__ __nv_bfloat16 g_hn_bf[TOK*DMODEL];
__device__ __nv_bfloat16 g_xc_bf[TOK*DI];
__device__ __nv_bfloat16 g_up_bf[TOK*DI];
__device__ __nv_bfloat16 g_q_bf[TOK*DI];
__device__ __nv_bfloat16 g_k_bf[TOK*DI];
__device__ __nv_bfloat16 g_v_bf[TOK*DI];
__device__ __nv_bfloat16 g_att2_bf[TOK*DI];
__device__ __nv_bfloat16 g_wup_bf[NL*DMODEL*1024];
__device__ __nv_bfloat16 g_wq_bf[NL*DI*DI];
__device__ __nv_bfloat16 g_wk_bf[NL*DI*DI];
__device__ __nv_bfloat16 g_wv_bf[NL*DI*DI];
__device__ __nv_bfloat16 g_wdn_bf[NL*DI*DMODEL];

__device__ __forceinline__ float warp_sum(float v){
    #pragma unroll
    for (int o=16;o;o>>=1) v += __shfl_xor_sync(0xffffffffu, v, o);
    return v;
}

__device__ __forceinline__ uint32_t bf2pack(float x, float y){
    __nv_bfloat162 t = __floats2bfloat162_rn(x, y);
    return *(uint32_t*)&t;
}

__device__ __forceinline__ void mma_bf16(float* c, const uint32_t* a, uint32_t b0, uint32_t b1){
    asm volatile(
      "mma.sync.aligned.m16n8k16.row.col.f32.bf16.bf16.f32 "
      "{%0,%1,%2,%3}, {%4,%5,%6,%7}, {%8,%9}, {%0,%1,%2,%3};\n"
      : "+f"(c[0]), "+f"(c[1]), "+f"(c[2]), "+f"(c[3])
      : "r"(a[0]), "r"(a[1]), "r"(a[2]), "r"(a[3]), "r"(b0), "r"(b1));
}

__device__ __forceinline__ uint32_t smaddr(const void* p){
    return (uint32_t)__cvta_generic_to_shared(p);
}
#define CPA16(dst,src) asm volatile("cp.async.cg.shared.global [%0], [%1], 16;\n"::"r"(dst),"l"(src))
#define CPCOMMIT() asm volatile("cp.async.commit_group;\n")
#define CPWAIT(n) asm volatile("cp.async.wait_group %0;\n"::"n"(n))

// ---------------- merged f32 -> bf16 convert for all 5 weight tensors ----------------
__global__ void f2bf5_kernel(const float* __restrict__ i0, __nv_bfloat16* __restrict__ o0, int n0,
                             const float* __restrict__ i1, __nv_bfloat16* __restrict__ o1, int n1,
                             const float* __restrict__ i2, __nv_bfloat16* __restrict__ o2, int n2,
                             const float* __restrict__ i3, __nv_bfloat16* __restrict__ o3, int n3,
                             const float* __restrict__ i4, __nv_bfloat16* __restrict__ o4, int n4){
    int i = (blockIdx.x*blockDim.x + threadIdx.x)*2;
    const float* in; __nv_bfloat16* out;
    if (i < n0){ in=i0; out=o0; }
    else if ((i-=n0) < n1){ in=i1; out=o1; }
    else if ((i-=n1) < n2){ in=i2; out=o2; }
    else if ((i-=n2) < n3){ in=i3; out=o3; }
    else if ((i-=n3) < n4){ in=i4; out=o4; }
    else return;
    float2 v = *(const float2*)(in+i);
    *(__nv_bfloat162*)(out+i) = __floats2bfloat162_rn(v.x, v.y);
}

// ---------------- composite gate weights: Wg = [Wq@Wif_i + Wk@Wif_k ; Wv@Wif_v] ----------------
__global__ void gatew_kernel(const float* __restrict__ Wq, const float* __restrict__ Wk,
                             const float* __restrict__ Wv, const float* __restrict__ Wif,
                             float* __restrict__ Wg){
    int idx = blockIdx.x*blockDim.x + threadIdx.x;   // NL*1024*8
    int l = idx >> 13; int r = idx & 8191;
    int c = r >> 3; int j = r & 7;
    const float* Wifl = Wif + (size_t)l*1536*8;
    float acc = 0.f;
    if (c < 512){
        const float* wq = Wq + ((size_t)l*512 + c)*512;
        const float* wk = Wk + ((size_t)l*512 + c)*512;
        #pragma unroll 4
        for (int i=0;i<512;i++)
            acc += wq[i]*Wifl[i*8+j] + wk[i]*Wifl[(512+i)*8+j];
    } else {
        const float* wv = Wv + ((size_t)l*512 + (c-512))*512;
        #pragma unroll 4
        for (int i=0;i<512;i++)
            acc += wv[i]*Wifl[(1024+i)*8+j];
    }
    Wg[(size_t)l*8192 + c*8 + j] = acc;
}

// ---------------- embed ----------------
__global__ void embed_kernel(const float* __restrict__ x, const float* __restrict__ tf,
                             const float* __restrict__ Wp, const float* __restrict__ bp,
                             float* __restrict__ h){
    int idx = blockIdx.x*blockDim.x + threadIdx.x;
    int j = idx & 255; int tok = idx >> 8;
    float acc = bp[j] + x[tok]*Wp[j];
    #pragma unroll
    for (int f=0; f<4; f++) acc += tf[tok*4+f]*Wp[(1+f)*256+j];
    h[idx] = acc;
}

// ---------------- layernorm, bf16 out (fused E[x^2] variance) ----------------
__global__ void ln_kernel(const float* __restrict__ x, const float* __restrict__ g,
                          const float* __restrict__ b, __nv_bfloat16* __restrict__ y){
    int row = blockIdx.x*8 + (threadIdx.x>>5);
    int lane = threadIdx.x & 31;
    const float* xr = x + (size_t)row*256;
    float4 v0 = *(const float4*)(xr + lane*4);
    float4 v1 = *(const float4*)(xr + 128 + lane*4);
    float s  = v0.x+v0.y+v0.z+v0.w + v1.x+v1.y+v1.z+v1.w;
    float sq = v0.x*v0.x+v0.y*v0.y+v0.z*v0.z+v0.w*v0.w
             + v1.x*v1.x+v1.y*v1.y+v1.z*v1.z+v1.w*v1.w;
    #pragma unroll
    for (int o=16;o;o>>=1){
        s  += __shfl_xor_sync(0xffffffffu, s,  o);
        sq += __shfl_xor_sync(0xffffffffu, sq, o);
    }
    float mu = s * (1.f/256.f);
    float var = sq * (1.f/256.f) - mu*mu;
    float is = rsqrtf(var + 1e-5f);
    float4 g0 = *(const float4*)(g + lane*4);
    float4 g1 = *(const float4*)(g + 128 + lane*4);
    float4 b0 = *(const float4*)(b + lane*4);
    float4 b1 = *(const float4*)(b + 128 + lane*4);
    __nv_bfloat16* yr = y + (size_t)row*256;
    *(__nv_bfloat162*)&yr[lane*4]       = __floats2bfloat162_rn((v0.x-mu)*is*g0.x + b0.x, (v0.y-mu)*is*g0.y + b0.y);
    *(__nv_bfloat162*)&yr[lane*4+2]     = __floats2bfloat162_rn((v0.z-mu)*is*g0.z + b0.z, (v0.w-mu)*is*g0.w + b0.w);
    *(__nv_bfloat162*)&yr[128+lane*4]   = __floats2bfloat162_rn((v1.x-mu)*is*g1.x + b1.x, (v1.y-mu)*is*g1.y + b1.y);
    *(__nv_bfloat162*)&yr[128+lane*4+2] = __floats2bfloat162_rn((v1.z-mu)*is*g1.z + b1.z, (v1.w-mu)*is*g1.w + b1.w);
}

// ---------------- bf16 tensor-core GEMM: CTA 128x128x64, 8 warps 2x4, dyn smem ----------------
// B stored as two independent 64-col halves, each with the verified XOR-chunk scheme.
// z=0: (A,B,Cbf); z=1: (A,B2,Cbf2); z=2: (A2,B3,Cbf3). C fp32 optional.
__global__ __launch_bounds__(256, 2) void gemm_bf16(
    const __nv_bfloat16* __restrict__ A, int lda,
    const __nv_bfloat16* __restrict__ B, int ldb,
    float* __restrict__ C, int ldc,
    const float* __restrict__ bias,
    const float* __restrict__ resid,
    int K,
    __nv_bfloat16* __restrict__ Cbf, int bfcap,
    const __nv_bfloat16* __restrict__ A2,
    const __nv_bfloat16* __restrict__ B2,
    __nv_bfloat16* __restrict__ Cbf2,
    const __nv_bfloat16* __restrict__ B3,
    __nv_bfloat16* __restrict__ Cbf3)
{
    extern __shared__ __nv_bfloat16 sm[];
    __nv_bfloat16* As = sm;            // 2 x 128 x 64
    __nv_bfloat16* Bs = sm + 16384;    // 2 bufs x 2 halves x 64 x 64
    if (blockIdx.z == 1){ B = B2; Cbf = Cbf2; }
    else if (blockIdx.z == 2){ A = A2; B = B3; Cbf = Cbf3; }
    int tid = threadIdx.x, lane = tid&31, wid = tid>>5;
    int wm = wid>>2, wn = wid&3;       // 2 x 4
    int m0 = blockIdx.y*128, n0 = blockIdx.x*128;

    int ar = tid >> 1;
    int ac0 = (tid & 1) << 2;
    int br = tid >> 2;
    int bc0 = (tid & 3) << 1;
    const __nv_bfloat16* Ag = A + (size_t)(m0+ar)*lda;
    const __nv_bfloat16* Bg = B + (size_t)br*ldb + n0;

    int KC = K >> 6;
    {
        #pragma unroll
        for (int c=0;c<4;c++){
            int ch = ac0+c;
            CPA16(smaddr(&As[ar*64 + ((ch ^ (ar&7))<<3)]), Ag + (ch<<3));
        }
        #pragma unroll
        for (int hf=0; hf<2; hf++)
          #pragma unroll
          for (int c=0;c<2;c++){
            int ch = bc0+c;
            CPA16(smaddr(&Bs[hf*4096 + br*64 + ((ch ^ (br&7))<<3)]), Bg + hf*64 + (ch<<3));
        }
        CPCOMMIT();
    }

    float acc[4][4][4] = {};
    int g = lane>>3, lr = lane&7;
    int bhalf = wn>>1, bco = (wn&1)<<2;

    for (int kc=0; kc<KC; kc++){
        int cur = kc & 1;
        if (kc+1 < KC){
            int nb = (kc+1)&1, k0 = (kc+1)<<6;
            #pragma unroll
            for (int c=0;c<4;c++){
                int ch = ac0+c;
                CPA16(smaddr(&As[nb*8192 + ar*64 + ((ch ^ (ar&7))<<3)]), Ag + k0 + (ch<<3));
            }
            #pragma unroll
            for (int hf=0; hf<2; hf++)
              #pragma unroll
              for (int c=0;c<2;c++){
                int ch = bc0+c;
                CPA16(smaddr(&Bs[nb*8192 + hf*4096 + br*64 + ((ch ^ (br&7))<<3)]),
                      Bg + (size_t)k0*ldb + hf*64 + (ch<<3));
            }
            CPCOMMIT();
            CPWAIT(1);
        } else {
            CPWAIT(0);
        }
        __syncthreads();

        const __nv_bfloat16* Ab = As + cur*8192;
        const __nv_bfloat16* Bb = Bs + cur*8192 + bhalf*4096;
        #pragma unroll
        for (int ks=0; ks<4; ks++){
            uint32_t af[4][4];
            #pragma unroll
            for (int mt=0; mt<4; mt++){
                int arow = wm*64 + mt*16 + lr + ((g&1)<<3);
                int ch = (ks<<1) + (g>>1);
                uint32_t addr = smaddr(&Ab[arow*64 + ((ch ^ (arow&7))<<3)]);
                asm volatile("ldmatrix.sync.aligned.m8n8.x4.shared.b16 {%0,%1,%2,%3}, [%4];\n"
                    : "=r"(af[mt][0]),"=r"(af[mt][1]),"=r"(af[mt][2]),"=r"(af[mt][3]) : "r"(addr));
            }
            uint32_t bf[4][2];
            int krow = (ks<<4) + lr + ((g&1)<<3);
            #pragma unroll
            for (int nt=0; nt<4; nt++){
                int ch = bco + nt;
                uint32_t addr = smaddr(&Bb[krow*64 + ((ch ^ (krow&7))<<3)]);
                asm volatile("ldmatrix.sync.aligned.m8n8.x2.trans.shared.b16 {%0,%1}, [%2];\n"
                    : "=r"(bf[nt][0]),"=r"(bf[nt][1]) : "r"(addr));
            }
            #pragma unroll
            for (int mt=0;mt<4;mt++)
              #pragma unroll
              for (int nt=0;nt<4;nt++)
                mma_bf16(acc[mt][nt], af[mt], bf[nt][0], bf[nt][1]);
        }
        __syncthreads();
    }

    #pragma unroll
    for (int mt=0;mt<4;mt++){
        #pragma unroll
        for (int nt=0;nt<4;nt++){
            int row0 = m0 + wm*64 + mt*16 + (lane>>2);
            int col  = n0 + wn*32 + nt*8 + ((lane&3)<<1);
            float bx=0.f, by=0.f;
            if (bias){ bx = bias[col]; by = bias[col+1]; }
            float2 r0v = make_float2(0.f,0.f), r1v = make_float2(0.f,0.f);
            if (resid){
                r0v = *(const float2*)&resid[(size_t)row0*ldc + col];
                r1v = *(const float2*)&resid[(size_t)(row0+8)*ldc + col];
            }
            float v00 = acc[mt][nt][0]+bx+r0v.x, v01 = acc[mt][nt][1]+by+r0v.y;
            float v10 = acc[mt][nt][2]+bx+r1v.x, v11 = acc[mt][nt][3]+by+r1v.y;
            if (C){
                *(float2*)&C[(size_t)row0*ldc + col]     = make_float2(v00, v01);
                *(float2*)&C[(size_t)(row0+8)*ldc + col] = make_float2(v10, v11);
            }
            if (Cbf && col < bfcap){
                *(__nv_bfloat162*)&Cbf[(size_t)row0*bfcap + col]     = __floats2bfloat162_rn(v00, v01);
                *(__nv_bfloat162*)&Cbf[(size_t)(row0+8)*bfcap + col] = __floats2bfloat162_rn(v10, v11);
            }
        }
    }
}

// ---------------- fused causal conv + silu + composite gates ----------------
__global__ __launch_bounds__(256) void conv_gates_kernel(
    const float* __restrict__ up, const float* __restrict__ cw, const float* __restrict__ cb,
    const float* __restrict__ Wg, const float* __restrict__ bif,
    float* __restrict__ xc, __nv_bfloat16* __restrict__ xcbf,
    float* __restrict__ giT, float* __restrict__ gfT)
{
    __shared__ float xcs[512], xms[512];
    int tok = blockIdx.x, tid = threadIdx.x;
    int t = tok & 1023;
    #pragma unroll
    for (int r=0;r<2;r++){
        int c = tid + (r<<8);
        float xm = up[(size_t)tok*1024 + c];
        float acc = cb[c] + cw[3*512+c]*xm;
        #pragma unroll
        for (int j=0;j<3;j++){
            int ts = t - 3 + j;
            if (ts >= 0) acc += cw[j*512+c]*up[(size_t)(tok-3+j)*1024 + c];
        }
        float sv = acc/(1.f+expf(-acc));
        xcs[c] = sv; xms[c] = xm;
        xc[(size_t)tok*512 + c] = sv;
        xcbf[(size_t)tok*512 + c] = __float2bfloat16(sv);
    }
    __syncthreads();
    int w = tid>>5, lane = tid&31;
    float acc = 0.f;
    for (int i=lane;i<512;i+=32) acc += xcs[i]*Wg[i*8+w] + xms[i]*Wg[(512+i)*8+w];
    acc = warp_sum(acc);
    if (!lane){
        float r = acc + bif[w];
        int b = tok >> 10, s = tok & 1023;
        if (w < 4) giT[(size_t)(b*4+w)*1024 + s] = r;
        else       gfT[(size_t)(b*4+w-4)*1024 + s] = r;
    }
}

// ---------------- gate scan + per-tile col weights ----------------
__global__ void scan_kernel4(const float* __restrict__ giT, const float* __restrict__ gfT,
                             float* __restrict__ Fc, float* __restrict__ a, float* __restrict__ m,
                             float* __restrict__ wcol, float* __restrict__ amaxT){
    __shared__ float ash[1024];
    int bh = blockIdx.x, lane = threadIdx.x;
    const float* gih = giT + (size_t)bh*1024;
    const float* gfh = gfT + (size_t)bh*1024;
    const float scale = 0.08838834764831845f;
    float cfc = 0.f, cmax = -1e30f;
    float ipc = gih[lane], fpc = gfh[lane];
    for (int c=0;c<32;c++){
        float ip = ipc, fp = fpc;
        if (c+1 < 32){ ipc = gih[(c+1)*32+lane]; fpc = gfh[(c+1)*32+lane]; }
        float lf = fminf(fp, 0.f) - log1pf(expf(-fabsf(fp)));
        float x = lf;
        #pragma unroll
        for (int o=1;o<32;o<<=1){ float y = __shfl_up_sync(0xffffffffu, x, o); if (lane>=o) x += y; }
        float fc = cfc + x;
        float av = ip - fc;
        float mx = av;
        #pragma unroll
        for (int o=1;o<32;o<<=1){ float y = __shfl_up_sync(0xffffffffu, mx, o); if (lane>=o) mx = fmaxf(mx, y); }
        float cm = fmaxf(cmax, mx);
        int off = bh*SEQ + c*32 + lane;
        Fc[off] = fc; a[off] = av; m[off] = fc + cm;
        ash[c*32 + lane] = av;
        cfc += __shfl_sync(0xffffffffu, x, 31);
        cmax = fmaxf(cmax, __shfl_sync(0xffffffffu, mx, 31));
    }
    __syncwarp();
    for (int tile=0;tile<16;tile++){
        float v0 = ash[tile*64 + lane];
        float v1 = ash[tile*64 + 32 + lane];
        float mx = fmaxf(v0, v1);
        #pragma unroll
        for (int o=16;o;o>>=1) mx = fmaxf(mx, __shfl_xor_sync(0xffffffffu, mx, o));
        if (lane == 0) amaxT[bh*16 + tile] = mx;
        wcol[bh*SEQ + tile*64 + lane]      = scale*__expf(v0 - mx);
        wcol[bh*SEQ + tile*64 + 32 + lane] = scale*__expf(v1 - mx);
    }
}

// ---------------- mLSTM attention + fused GN/skip/silu-gate epilogue ----------------
#define QKW 68
#define VW  64
#define PW  36
__global__ __launch_bounds__(256) void attn_bf16(
    const __nv_bfloat16* __restrict__ q, const __nv_bfloat16* __restrict__ k,
    const __nv_bfloat16* __restrict__ v,
    const float* __restrict__ Fcv, const float* __restrict__ av, const float* __restrict__ mv,
    const float* __restrict__ wcol, const float* __restrict__ amaxT,
    const float* __restrict__ xc, const float* __restrict__ up,
    const float* __restrict__ gng, const float* __restrict__ gnb,
    const float* __restrict__ skip,
    __nv_bfloat16* __restrict__ out)
{
    extern __shared__ uint32_t smu[];
    uint32_t* Qs = smu;                  // 64*68 words; reused as P (64*36)
    uint32_t* Ks = Qs + 64*QKW;
    uint32_t* Vs = Ks + 64*QKW;          // 64*64 words
    float* fct  = (float*)(Vs + 64*VW);  // 64
    float* mt   = fct + 64;              // 64
    float* as_  = mt + 64;               // 64
    float* den2 = as_ + 64;              // 128
    float* dsq  = den2 + 128;            // 128

    int bh = blockIdx.x; int b = bh>>2, hh = bh&3;
    int it = (int)(gridDim.y - 1) - (int)blockIdx.y;
    int t0 = it<<6;
    int tid = threadIdx.x, lane = tid&31, wid = tid>>5;
    int wm = wid>>1, wn = wid&1;
    int ls = lane>>2, lk = lane&3;
    int g8 = lane>>3, lr = lane&7;
    const float scale = 0.08838834764831845f;

    const __nv_bfloat16* qg = q + ((size_t)(b*SEQ + t0))*512 + hh*128;
    #pragma unroll
    for (int r=0;r<4;r++){
        int idx = tid + (r<<8);
        int row = idx>>4, c16 = idx&15;
        uint4 val = *(const uint4*)(qg + (size_t)row*512 + (c16<<3));
        *(uint4*)&Qs[row*QKW + (c16<<2)] = val;
    }
    if (tid < 64){ int tg = bh*SEQ + t0 + tid; fct[tid] = Fcv[tg]; mt[tid] = mv[tg]; }
    __syncthreads();

    uint32_t qf[8][4];
    int r0 = wm*16 + ls, r1 = r0 + 8;
    #pragma unroll
    for (int ks=0; ks<8; ks++){
        qf[ks][0] = Qs[r0*QKW + ks*8 + lk];
        qf[ks][1] = Qs[r1*QKW + ks*8 + lk];
        qf[ks][2] = Qs[r0*QKW + ks*8 + lk + 4];
        qf[ks][3] = Qs[r1*QKW + ks*8 + lk + 4];
    }

    float oacc[8][4];
    #pragma unroll
    for (int i=0;i<8;i++){ oacc[i][0]=0.f; oacc[i][1]=0.f; oacc[i][2]=0.f; oacc[i][3]=0.f; }
    float den0 = 0.f, den1 = 0.f;

    for (int js=0; js<=it; js++){
        int s0 = js<<6;
        bool diag = (js == it);
        __syncthreads();
        const __nv_bfloat16* kg = k + ((size_t)(b*SEQ + s0))*512 + hh*128;
        const __nv_bfloat16* vg = v + ((size_t)(b*SEQ + s0))*512 + hh*128;
        #pragma unroll
        for (int r=0;r<4;r++){
            int idx = tid + (r<<8);
            int row = idx>>4, c16 = idx&15;
            uint4 kv = *(const uint4*)(kg + (size_t)row*512 + (c16<<3));
            uint4 vv = *(const uint4*)(vg + (size_t)row*512 + (c16<<3));
            *(uint4*)&Ks[row*QKW + (c16<<2)] = kv;
            *(uint4*)&Vs[row*VW + ((c16 ^ (row&7))<<2)] = vv;
        }
        if (tid < 64)
            as_[tid] = diag ? av[bh*SEQ + s0 + tid] : wcol[bh*SEQ + s0 + tid];
        __syncthreads();

        float sacc[4][4] = {};
        #pragma unroll
        for (int ks=0; ks<8; ks++){
            #pragma unroll
            for (int nt=0; nt<4; nt++){
                int sc = wn*32 + nt*8 + ls;
                uint32_t b0 = Ks[sc*QKW + ks*8 + lk];
                uint32_t b1 = Ks[sc*QKW + ks*8 + lk + 4];
                mma_bf16(sacc[nt], qf[ks], b0, b1);
            }
        }

        float f0 = fct[r0], mm0 = mt[r0], f1 = fct[r1], mm1 = mt[r1];
        if (!diag){
            float amx = amaxT[bh*16 + js];
            float w0 = __expf(f0 - mm0 + amx);
            float w1 = __expf(f1 - mm1 + amx);
            #pragma unroll
            for (int nt=0; nt<4; nt++){
                int c0 = wn*32 + nt*8 + (lk<<1);
                float wc0 = as_[c0], wc1 = as_[c0+1];
                float v00 = sacc[nt][0]*w0*wc0;
                float v01 = sacc[nt][1]*w0*wc1;
                float v10 = sacc[nt][2]*w1*wc0;
                float v11 = sacc[nt][3]*w1*wc1;
                den0 += v00 + v01;
                den1 += v10 + v11;
                int wcl = wn*16 + nt*4 + lk;
                Qs[r0*PW + wcl] = bf2pack(v00, v01);
                Qs[r1*PW + wcl] = bf2pack(v10, v11);
            }
        } else {
            #pragma unroll
            for (int nt=0; nt<4; nt++){
                int c0 = wn*32 + nt*8 + (lk<<1);
                int c1 = c0 + 1;
                float a0v = as_[c0], a1v = as_[c1];
                float v00 = sacc[nt][0]*scale*__expf(f0 + a0v - mm0);
                float v01 = sacc[nt][1]*scale*__expf(f0 + a1v - mm0);
                float v10 = sacc[nt][2]*scale*__expf(f1 + a0v - mm1);
                float v11 = sacc[nt][3]*scale*__expf(f1 + a1v - mm1);
                if (c0 > r0) v00 = 0.f;
                if (c1 > r0) v01 = 0.f;
                if (c0 > r1) v10 = 0.f;
                if (c1 > r1) v11 = 0.f;
                den0 += v00 + v01;
                den1 += v10 + v11;
                int wcl = wn*16 + nt*4 + lk;
                Qs[r0*PW + wcl] = bf2pack(v00, v01);
                Qs[r1*PW + wcl] = bf2pack(v10, v11);
            }
        }
        __syncthreads();

        #pragma unroll
        for (int ks2=0; ks2<4; ks2++){
            uint32_t af[4];
            af[0] = Qs[r0*PW + ks2*8 + lk];
            af[1] = Qs[r1*PW + ks2*8 + lk];
            af[2] = Qs[r0*PW + ks2*8 + lk + 4];
            af[3] = Qs[r1*PW + ks2*8 + lk + 4];
            int krow = (ks2<<4) + lr + ((g8&1)<<3);
            #pragma unroll
            for (int nt=0; nt<8; nt++){
                int cd = wn*8 + nt;
                uint32_t addr = smaddr(&Vs[krow*VW + ((cd ^ (krow&7))<<2)]);
                uint32_t b0, b1;
                asm volatile("ldmatrix.sync.aligned.m8n8.x2.trans.shared.b16 {%0,%1}, [%2];\n"
                    : "=r"(b0),"=r"(b1) : "r"(addr));
                mma_bf16(oacc[nt], af, b0, b1);
            }
        }
    }

    // ---- denominator ----
    den0 += __shfl_xor_sync(0xffffffffu, den0, 1);
    den0 += __shfl_xor_sync(0xffffffffu, den0, 2);
    den1 += __shfl_xor_sync(0xffffffffu, den1, 1);
    den1 += __shfl_xor_sync(0xffffffffu, den1, 2);
    if (lk == 0){ den2[wn*64 + r0] = den0; den2[wn*64 + r1] = den1; }
    __syncthreads();
    float dt0 = den2[r0] + den2[64 + r0];
    float dt1 = den2[r1] + den2[64 + r1];
    float inv0 = 1.f / (fmaxf(fabsf(dt0), __expf(-mt[r0])) + 1e-6f);
    float inv1 = 1.f / (fmaxf(fabsf(dt1), __expf(-mt[r1])) + 1e-6f);

    float hv0[16], hv1[16];
    #pragma unroll
    for (int nt=0; nt<8; nt++){
        hv0[nt*2]   = oacc[nt][0]*inv0;
        hv0[nt*2+1] = oacc[nt][1]*inv0;
        hv1[nt*2]   = oacc[nt][2]*inv1;
        hv1[nt*2+1] = oacc[nt][3]*inv1;
    }

    // ---- fused GroupNorm via E[x^2] ----
    float s0 = 0.f, s1 = 0.f, q0 = 0.f, q1 = 0.f;
    #pragma unroll
    for (int i=0;i<16;i++){
        s0 += hv0[i]; q0 += hv0[i]*hv0[i];
        s1 += hv1[i]; q1 += hv1[i]*hv1[i];
    }
    #pragma unroll
    for (int o=1;o<4;o<<=1){
        s0 += __shfl_xor_sync(0xffffffffu, s0, o);
        q0 += __shfl_xor_sync(0xffffffffu, q0, o);
        s1 += __shfl_xor_sync(0xffffffffu, s1, o);
        q1 += __shfl_xor_sync(0xffffffffu, q1, o);
    }
    __syncthreads();
    if (lk == 0){
        den2[wn*64 + r0] = s0; den2[wn*64 + r1] = s1;
        dsq[wn*64 + r0]  = q0; dsq[wn*64 + r1]  = q1;
    }
    __syncthreads();
    float mu0 = (den2[r0] + den2[64 + r0]) * (1.f/128.f);
    float mu1 = (den2[r1] + den2[64 + r1]) * (1.f/128.f);
    float e20 = (dsq[r0] + dsq[64 + r0]) * (1.f/128.f);
    float e21 = (dsq[r1] + dsq[64 + r1]) * (1.f/128.f);
    float is0 = rsqrtf(e20 - mu0*mu0 + 1e-5f);
    float is1 = rsqrtf(e21 - mu1*mu1 + 1e-5f);

    // ---- gamma/beta + skip*xc + silu(z), bf16 store ----
    size_t tok0 = (size_t)(b*SEQ + t0 + r0), tok1 = (size_t)(b*SEQ + t0 + r1);
    #pragma unroll
    for (int nt=0; nt<8; nt++){
        int dc = wn*64 + nt*8 + (lk<<1);
        int c = hh*128 + dc;
        float2 gg = *(const float2*)&gng[c];
        float2 gb = *(const float2*)&gnb[c];
        float2 sk = *(const float2*)&skip[c];
        float2 x0 = *(const float2*)&xc[tok0*512 + c];
        float2 x1 = *(const float2*)&xc[tok1*512 + c];
        float2 z0 = *(const float2*)&up[tok0*1024 + 512 + c];
        float2 z1 = *(const float2*)&up[tok1*1024 + 512 + c];
        float y00 = (hv0[nt*2]  -mu0)*is0*gg.x + gb.x + sk.x*x0.x;
        float y01 = (hv0[nt*2+1]-mu0)*is0*gg.y + gb.y + sk.y*x0.y;
        float y10 = (hv1[nt*2]  -mu1)*is1*gg.x + gb.x + sk.x*x1.x;
        float y11 = (hv1[nt*2+1]-mu1)*is1*gg.y + gb.y + sk.y*x1.y;
        y00 *= z0.x / (1.f + expf(-z0.x));
        y01 *= z0.y / (1.f + expf(-z0.y));
        y10 *= z1.x / (1.f + expf(-z1.x));
        y11 *= z1.y / (1.f + expf(-z1.y));
        *(__nv_bfloat162*)&out[tok0*512 + c] = __floats2bfloat162_rn(y00, y01);
        *(__nv_bfloat162*)&out[tok1*512 + c] = __floats2bfloat162_rn(y10, y11);
    }
}

// ---------------- final ----------------
__global__ void final_kernel(const float* __restrict__ h, const float* __restrict__ g,
                             const float* __restrict__ b, const float* __restrict__ Wf,
                             const float* __restrict__ bf, float* __restrict__ out){
    __shared__ float sh[8];
    __shared__ float sv;
    int bb = blockIdx.x, tid = threadIdx.x;
    float vv = h[((size_t)(bb*SEQ + SEQ-1))*256 + tid];
    float s = warp_sum(vv);
    if (!(tid&31)) sh[tid>>5] = s;
    __syncthreads();
    if (tid==0){ float t=0; for(int i=0;i<8;i++) t+=sh[i]; sv = t*(1.f/256.f); }
    __syncthreads();
    float mu = sv;
    float d = vv - mu;
    float s2 = warp_sum(d*d);
    if (!(tid&31)) sh[tid>>5] = s2;
    __syncthreads();
    if (tid==0){ float t=0; for(int i=0;i<8;i++) t+=sh[i]; sv = t*(1.f/256.f); }
    __syncthreads();
    float yn = d*rsqrtf(sv + 1e-5f)*g[tid] + b[tid];
    float p = yn * Wf[tid];
    float s3 = warp_sum(p);
    __syncthreads();
    if (!(tid&31)) sh[tid>>5] = s3;
    __syncthreads();
    if (tid==0){ float t=0; for(int i=0;i<8;i++) t+=sh[i]; out[bb] = t + bf[0]; }
}

// ---------------- launch ----------------
extern "C" void kernel_launch(void* const* d_in, const int* in_sizes, int n_in,
                              void* d_out, int out_size){
    const float* x    = (const float*)d_in[0];
    const float* tf   = (const float*)d_in[1];
    const float* Wp   = (const float*)d_in[2];
    const float* bp   = (const float*)d_in[3];
    const float* ln_g = (const float*)d_in[4];
    const float* ln_b = (const float*)d_in[5];
    const float* Wup  = (const float*)d_in[6];
    const float* bup  = (const float*)d_in[7];
    const float* cw   = (const float*)d_in[8];
    const float* cb   = (const float*)d_in[9];
    const float* Wq   = (const float*)d_in[10];
    const float* Wk   = (const float*)d_in[11];
    const float* Wv   = (const float*)d_in[12];
    const float* Wif  = (const float*)d_in[13];
    const float* bif  = (const float*)d_in[14];
    const float* gng  = (const float*)d_in[15];
    const float* gnb  = (const float*)d_in[16];
    const float* skip = (const float*)d_in[17];
    const float* Wdn  = (const float*)d_in[18];
    const float* bdn  = (const float*)d_in[19];
    const float* lnfg = (const float*)d_in[20];
    const float* lnfb = (const float*)d_in[21];
    const float* Wf   = (const float*)d_in[22];
    const float* bf   = (const float*)d_in[23];

    float *h,*up,*xc,*giT,*gfT,*Fc,*a,*m,*wcol,*amaxT,*Wg;
    __nv_bfloat16 *hnbf,*xcbf,*upbf,*qbf,*kbf,*vbf,*att2bf,*wupbf,*wqbf,*wkbf,*wvbf,*wdnbf;
    cudaGetSymbolAddress((void**)&h,    g_h);
    cudaGetSymbolAddress((void**)&up,   g_up);
    cudaGetSymbolAddress((void**)&xc,   g_xc);
    cudaGetSymbolAddress((void**)&giT,  g_giT);
    cudaGetSymbolAddress((void**)&gfT,  g_gfT);
    cudaGetSymbolAddress((void**)&Fc,   g_Fc);
    cudaGetSymbolAddress((void**)&a,    g_a);
    cudaGetSymbolAddress((void**)&m,    g_m);
    cudaGetSymbolAddress((void**)&wcol, g_wcol);
    cudaGetSymbolAddress((void**)&amaxT,g_amaxT);
    cudaGetSymbolAddress((void**)&Wg,   g_Wg);
    cudaGetSymbolAddress((void**)&hnbf, g_hn_bf);
    cudaGetSymbolAddress((void**)&xcbf, g_xc_bf);
    cudaGetSymbolAddress((void**)&upbf, g_up_bf);
    cudaGetSymbolAddress((void**)&qbf,  g_q_bf);
    cudaGetSymbolAddress((void**)&kbf,  g_k_bf);
    cudaGetSymbolAddress((void**)&vbf,  g_v_bf);
    cudaGetSymbolAddress((void**)&att2bf, g_att2_bf);
    cudaGetSymbolAddress((void**)&wupbf, g_wup_bf);
    cudaGetSymbolAddress((void**)&wqbf,  g_wq_bf);
    cudaGetSymbolAddress((void**)&wkbf,  g_wk_bf);
    cudaGetSymbolAddress((void**)&wvbf,  g_wv_bf);
    cudaGetSymbolAddress((void**)&wdnbf, g_wdn_bf);

    int attn_smem = (64*QKW + 64*QKW + 64*VW + 64 + 64 + 64 + 128 + 128) * 4;
    int gemm_smem = 65536;
    static int attr_set = 0;
    if (!attr_set){
        cudaFuncSetAttribute(attn_bf16, cudaFuncAttributeMaxDynamicSharedMemorySize, attn_smem);
        cudaFuncSetAttribute(gemm_bf16, cudaFuncAttributeMaxDynamicSharedMemorySize, gemm_smem);
        attr_set = 1;
    }

    int n0 = NL*DMODEL*1024, n1 = NL*DI*DI, n4 = NL*DI*DMODEL;
    int ntot = n0 + 3*n1 + n4;
    f2bf5_kernel<<<(ntot/2 + 255)/256, 256>>>(Wup, wupbf, n0,
                                              Wq, wqbf, n1,
                                              Wk, wkbf, n1,
                                              Wv, wvbf, n1,
                                              Wdn, wdnbf, n4);
    gatew_kernel<<<NL*1024*8/256, 256>>>(Wq, Wk, Wv, Wif, Wg);

    embed_kernel<<<TOK*256/256, 256>>>(x, tf, Wp, bp, h);

    for (int l=0; l<NL; l++){
        ln_kernel<<<TOK/8, 256>>>(h, ln_g + l*256, ln_b + l*256, hnbf);
        gemm_bf16<<<dim3(1024/128, TOK/128, 1), 256, gemm_smem>>>(
            hnbf, 256, wupbf + (size_t)l*256*1024, 1024,
            up, 1024, bup + l*1024, nullptr, 256,
            upbf, 512, nullptr, nullptr, nullptr, nullptr, nullptr);
        conv_gates_kernel<<<TOK, 256>>>(up, cw + l*4*512, cb + l*512,
                                        Wg + (size_t)l*8192, bif + l*8,
                                        xc, xcbf, giT, gfT);
        gemm_bf16<<<dim3(512/128, TOK/128, 3), 256, gemm_smem>>>(
            xcbf, 512, wqbf + (size_t)l*512*512, 512,
            nullptr, 512, nullptr, nullptr, 512, qbf, 512,
            upbf,
            wkbf + (size_t)l*512*512, kbf,
            wvbf + (size_t)l*512*512, vbf);
        scan_kernel4<<<32, 32>>>(giT, gfT, Fc, a, m, wcol, amaxT);
        attn_bf16<<<dim3(BATCH*NH, SEQ/64), 256, attn_smem>>>(qbf, kbf, vbf, Fc, a, m,
                                                  wcol, amaxT,
                                                  xc, up, gng + l*512, gnb + l*512, skip + l*512,
                                                  att2bf);
        gemm_bf16<<<dim3(256/128, TOK/128, 1), 256, gemm_smem>>>(
            att2bf, 512, wdnbf + (size_t)l*512*256, 256,
            h, 256, bdn + l*256, h, 512,
            nullptr, 0, nullptr, nullptr, nullptr, nullptr, nullptr);
    }
    final_kernel<<<BATCH, 256>>>(h, lnfg, lnfb, Wf, bf, (float*)d_out);
}

// round 14
// speedup vs baseline: 1.3091x; 1.2013x over previous
#include <cuda_runtime.h>
#include <cuda_bf16.h>
#include <cstdint>
#include <cstddef>

#define SEQ 1024
#define BATCH 8
#define TOK (BATCH*SEQ)
#define DMODEL 256
#define DI 512
#define NH 4
#define DHH 128
#define NL 4

// ---------------- scratch (device globals; no allocation allowed) ----------------
__device__ float g_h[TOK*DMODEL];
__device__ float g_up[TOK*1024];
__device__ float g_xc[TOK*DI];
__device__ float g_giT[BATCH*NH*SEQ];
__device__ float g_gfT[BATCH*NH*SEQ];
__device__ float g_Fc[BATCH*NH*SEQ];
__device__ float g_a[BATCH*NH*SEQ];
__device__ float g_m[BATCH*NH*SEQ];
__device__ float g_wcol[BATCH*NH*SEQ];
__device__ float g_amaxT[BATCH*NH*16];
__device__ float g_Wg[NL*1024*8];

__device__ __nv_bfloat16 g_hn_bf[TOK*DMODEL];
__device__ __nv_bfloat16 g_xc_bf[TOK*DI];
__device__ __nv_bfloat16 g_up_bf[TOK*DI];
__device__ __nv_bfloat16 g_q_bf[TOK*DI];
__device__ __nv_bfloat16 g_k_bf[TOK*DI];
__device__ __nv_bfloat16 g_v_bf[TOK*DI];
__device__ __nv_bfloat16 g_att2_bf[TOK*DI];
__device__ __nv_bfloat16 g_wup_bf[NL*DMODEL*1024];
__device__ __nv_bfloat16 g_wq_bf[NL*DI*DI];
__device__ __nv_bfloat16 g_wk_bf[NL*DI*DI];
__device__ __nv_bfloat16 g_wv_bf[NL*DI*DI];
__device__ __nv_bfloat16 g_wdn_bf[NL*DI*DMODEL];

__device__ __forceinline__ float warp_sum(float v){
    #pragma unroll
    for (int o=16;o;o>>=1) v += __shfl_xor_sync(0xffffffffu, v, o);
    return v;
}

__device__ __forceinline__ uint32_t bf2pack(float x, float y){
    __nv_bfloat162 t = __floats2bfloat162_rn(x, y);
    return *(uint32_t*)&t;
}

__device__ __forceinline__ void mma_bf16(float* c, const uint32_t* a, uint32_t b0, uint32_t b1){
    asm volatile(
      "mma.sync.aligned.m16n8k16.row.col.f32.bf16.bf16.f32 "
      "{%0,%1,%2,%3}, {%4,%5,%6,%7}, {%8,%9}, {%0,%1,%2,%3};\n"
      : "+f"(c[0]), "+f"(c[1]), "+f"(c[2]), "+f"(c[3])
      : "r"(a[0]), "r"(a[1]), "r"(a[2]), "r"(a[3]), "r"(b0), "r"(b1));
}

__device__ __forceinline__ uint32_t smaddr(const void* p){
    return (uint32_t)__cvta_generic_to_shared(p);
}
#define CPA16(dst,src) asm volatile("cp.async.cg.shared.global [%0], [%1], 16;\n"::"r"(dst),"l"(src))
#define CPCOMMIT() asm volatile("cp.async.commit_group;\n")
#define CPWAIT(n) asm volatile("cp.async.wait_group %0;\n"::"n"(n))

// ---------------- merged f32 -> bf16 convert for all 5 weight tensors ----------------
__global__ void f2bf5_kernel(const float* __restrict__ i0, __nv_bfloat16* __restrict__ o0, int n0,
                             const float* __restrict__ i1, __nv_bfloat16* __restrict__ o1, int n1,
                             const float* __restrict__ i2, __nv_bfloat16* __restrict__ o2, int n2,
                             const float* __restrict__ i3, __nv_bfloat16* __restrict__ o3, int n3,
                             const float* __restrict__ i4, __nv_bfloat16* __restrict__ o4, int n4){
    int i = (blockIdx.x*blockDim.x + threadIdx.x)*2;
    const float* in; __nv_bfloat16* out;
    if (i < n0){ in=i0; out=o0; }
    else if ((i-=n0) < n1){ in=i1; out=o1; }
    else if ((i-=n1) < n2){ in=i2; out=o2; }
    else if ((i-=n2) < n3){ in=i3; out=o3; }
    else if ((i-=n3) < n4){ in=i4; out=o4; }
    else return;
    float2 v = *(const float2*)(in+i);
    *(__nv_bfloat162*)(out+i) = __floats2bfloat162_rn(v.x, v.y);
}

// ---------------- composite gate weights ----------------
__global__ void gatew_kernel(const float* __restrict__ Wq, const float* __restrict__ Wk,
                             const float* __restrict__ Wv, const float* __restrict__ Wif,
                             float* __restrict__ Wg){
    int idx = blockIdx.x*blockDim.x + threadIdx.x;
    int l = idx >> 13; int r = idx & 8191;
    int c = r >> 3; int j = r & 7;
    const float* Wifl = Wif + (size_t)l*1536*8;
    float acc = 0.f;
    if (c < 512){
        const float* wq = Wq + ((size_t)l*512 + c)*512;
        const float* wk = Wk + ((size_t)l*512 + c)*512;
        #pragma unroll 4
        for (int i=0;i<512;i++)
            acc += wq[i]*Wifl[i*8+j] + wk[i]*Wifl[(512+i)*8+j];
    } else {
        const float* wv = Wv + ((size_t)l*512 + (c-512))*512;
        #pragma unroll 4
        for (int i=0;i<512;i++)
            acc += wv[i]*Wifl[(1024+i)*8+j];
    }
    Wg[(size_t)l*8192 + c*8 + j] = acc;
}

// ---------------- embed ----------------
__global__ void embed_kernel(const float* __restrict__ x, const float* __restrict__ tf,
                             const float* __restrict__ Wp, const float* __restrict__ bp,
                             float* __restrict__ h){
    int idx = blockIdx.x*blockDim.x + threadIdx.x;
    int j = idx & 255; int tok = idx >> 8;
    float acc = bp[j] + x[tok]*Wp[j];
    #pragma unroll
    for (int f=0; f<4; f++) acc += tf[tok*4+f]*Wp[(1+f)*256+j];
    h[idx] = acc;
}

// ---------------- layernorm, bf16 out ----------------
__global__ void ln_kernel(const float* __restrict__ x, const float* __restrict__ g,
                          const float* __restrict__ b, __nv_bfloat16* __restrict__ y){
    int row = blockIdx.x*8 + (threadIdx.x>>5);
    int lane = threadIdx.x & 31;
    const float* xr = x + (size_t)row*256;
    float4 v0 = *(const float4*)(xr + lane*4);
    float4 v1 = *(const float4*)(xr + 128 + lane*4);
    float s  = v0.x+v0.y+v0.z+v0.w + v1.x+v1.y+v1.z+v1.w;
    float sq = v0.x*v0.x+v0.y*v0.y+v0.z*v0.z+v0.w*v0.w
             + v1.x*v1.x+v1.y*v1.y+v1.z*v1.z+v1.w*v1.w;
    #pragma unroll
    for (int o=16;o;o>>=1){
        s  += __shfl_xor_sync(0xffffffffu, s,  o);
        sq += __shfl_xor_sync(0xffffffffu, sq, o);
    }
    float mu = s * (1.f/256.f);
    float var = sq * (1.f/256.f) - mu*mu;
    float is = rsqrtf(var + 1e-5f);
    float4 g0 = *(const float4*)(g + lane*4);
    float4 g1 = *(const float4*)(g + 128 + lane*4);
    float4 b0 = *(const float4*)(b + lane*4);
    float4 b1 = *(const float4*)(b + 128 + lane*4);
    __nv_bfloat16* yr = y + (size_t)row*256;
    *(__nv_bfloat162*)&yr[lane*4]       = __floats2bfloat162_rn((v0.x-mu)*is*g0.x + b0.x, (v0.y-mu)*is*g0.y + b0.y);
    *(__nv_bfloat162*)&yr[lane*4+2]     = __floats2bfloat162_rn((v0.z-mu)*is*g0.z + b0.z, (v0.w-mu)*is*g0.w + b0.w);
    *(__nv_bfloat162*)&yr[128+lane*4]   = __floats2bfloat162_rn((v1.x-mu)*is*g1.x + b1.x, (v1.y-mu)*is*g1.y + b1.y);
    *(__nv_bfloat162*)&yr[128+lane*4+2] = __floats2bfloat162_rn((v1.z-mu)*is*g1.z + b1.z, (v1.w-mu)*is*g1.w + b1.w);
}

// ---------------- bf16 tensor-core GEMM: CTA 128x128x64, 8 warps 2x4 ----------------
__global__ __launch_bounds__(256, 2) void gemm_bf16(
    const __nv_bfloat16* __restrict__ A, int lda,
    const __nv_bfloat16* __restrict__ B, int ldb,
    float* __restrict__ C, int ldc,
    const float* __restrict__ bias,
    const float* __restrict__ resid,
    int K,
    __nv_bfloat16* __restrict__ Cbf, int bfcap,
    const __nv_bfloat16* __restrict__ A2,
    const __nv_bfloat16* __restrict__ B2,
    __nv_bfloat16* __restrict__ Cbf2,
    const __nv_bfloat16* __restrict__ B3,
    __nv_bfloat16* __restrict__ Cbf3)
{
    extern __shared__ __nv_bfloat16 sm[];
    __nv_bfloat16* As = sm;            // 2 x 128 x 64
    __nv_bfloat16* Bs = sm + 16384;    // 2 bufs x 2 halves x 64 x 64
    if (blockIdx.z == 1){ B = B2; Cbf = Cbf2; }
    else if (blockIdx.z == 2){ A = A2; B = B3; Cbf = Cbf3; }
    int tid = threadIdx.x, lane = tid&31, wid = tid>>5;
    int wm = wid>>2, wn = wid&3;
    int m0 = blockIdx.y*128, n0 = blockIdx.x*128;

    int ar = tid >> 1;
    int ac0 = (tid & 1) << 2;
    int br = tid >> 2;
    int bc0 = (tid & 3) << 1;
    const __nv_bfloat16* Ag = A + (size_t)(m0+ar)*lda;
    const __nv_bfloat16* Bg = B + (size_t)br*ldb + n0;

    int KC = K >> 6;
    {
        #pragma unroll
        for (int c=0;c<4;c++){
            int ch = ac0+c;
            CPA16(smaddr(&As[ar*64 + ((ch ^ (ar&7))<<3)]), Ag + (ch<<3));
        }
        #pragma unroll
        for (int hf=0; hf<2; hf++)
          #pragma unroll
          for (int c=0;c<2;c++){
            int ch = bc0+c;
            CPA16(smaddr(&Bs[hf*4096 + br*64 + ((ch ^ (br&7))<<3)]), Bg + hf*64 + (ch<<3));
        }
        CPCOMMIT();
    }

    float acc[4][4][4] = {};
    int g = lane>>3, lr = lane&7;
    int bhalf = wn>>1, bco = (wn&1)<<2;

    for (int kc=0; kc<KC; kc++){
        int cur = kc & 1;
        if (kc+1 < KC){
            int nb = (kc+1)&1, k0 = (kc+1)<<6;
            #pragma unroll
            for (int c=0;c<4;c++){
                int ch = ac0+c;
                CPA16(smaddr(&As[nb*8192 + ar*64 + ((ch ^ (ar&7))<<3)]), Ag + k0 + (ch<<3));
            }
            #pragma unroll
            for (int hf=0; hf<2; hf++)
              #pragma unroll
              for (int c=0;c<2;c++){
                int ch = bc0+c;
                CPA16(smaddr(&Bs[nb*8192 + hf*4096 + br*64 + ((ch ^ (br&7))<<3)]),
                      Bg + (size_t)k0*ldb + hf*64 + (ch<<3));
            }
            CPCOMMIT();
            CPWAIT(1);
        } else {
            CPWAIT(0);
        }
        __syncthreads();

        const __nv_bfloat16* Ab = As + cur*8192;
        const __nv_bfloat16* Bb = Bs + cur*8192 + bhalf*4096;
        #pragma unroll
        for (int ks=0; ks<4; ks++){
            uint32_t af[4][4];
            #pragma unroll
            for (int mt=0; mt<4; mt++){
                int arow = wm*64 + mt*16 + lr + ((g&1)<<3);
                int ch = (ks<<1) + (g>>1);
                uint32_t addr = smaddr(&Ab[arow*64 + ((ch ^ (arow&7))<<3)]);
                asm volatile("ldmatrix.sync.aligned.m8n8.x4.shared.b16 {%0,%1,%2,%3}, [%4];\n"
                    : "=r"(af[mt][0]),"=r"(af[mt][1]),"=r"(af[mt][2]),"=r"(af[mt][3]) : "r"(addr));
            }
            uint32_t bf[4][2];
            int krow = (ks<<4) + lr + ((g&1)<<3);
            #pragma unroll
            for (int nt=0; nt<4; nt++){
                int ch = bco + nt;
                uint32_t addr = smaddr(&Bb[krow*64 + ((ch ^ (krow&7))<<3)]);
                asm volatile("ldmatrix.sync.aligned.m8n8.x2.trans.shared.b16 {%0,%1}, [%2];\n"
                    : "=r"(bf[nt][0]),"=r"(bf[nt][1]) : "r"(addr));
            }
            #pragma unroll
            for (int mt=0;mt<4;mt++)
              #pragma unroll
              for (int nt=0;nt<4;nt++)
                mma_bf16(acc[mt][nt], af[mt], bf[nt][0], bf[nt][1]);
        }
        __syncthreads();
    }

    #pragma unroll
    for (int mt=0;mt<4;mt++){
        #pragma unroll
        for (int nt=0;nt<4;nt++){
            int row0 = m0 + wm*64 + mt*16 + (lane>>2);
            int col  = n0 + wn*32 + nt*8 + ((lane&3)<<1);
            float bx=0.f, by=0.f;
            if (bias){ bx = bias[col]; by = bias[col+1]; }
            float2 r0v = make_float2(0.f,0.f), r1v = make_float2(0.f,0.f);
            if (resid){
                r0v = *(const float2*)&resid[(size_t)row0*ldc + col];
                r1v = *(const float2*)&resid[(size_t)(row0+8)*ldc + col];
            }
            float v00 = acc[mt][nt][0]+bx+r0v.x, v01 = acc[mt][nt][1]+by+r0v.y;
            float v10 = acc[mt][nt][2]+bx+r1v.x, v11 = acc[mt][nt][3]+by+r1v.y;
            if (C){
                *(float2*)&C[(size_t)row0*ldc + col]     = make_float2(v00, v01);
                *(float2*)&C[(size_t)(row0+8)*ldc + col] = make_float2(v10, v11);
            }
            if (Cbf && col < bfcap){
                *(__nv_bfloat162*)&Cbf[(size_t)row0*bfcap + col]     = __floats2bfloat162_rn(v00, v01);
                *(__nv_bfloat162*)&Cbf[(size_t)(row0+8)*bfcap + col] = __floats2bfloat162_rn(v10, v11);
            }
        }
    }
}

// ---------------- bf16 GEMM, CTA 64x128x64 (for small-N down-GEMM; better grid fill) ----------------
__global__ __launch_bounds__(256, 2) void gemm_bf16_m64(
    const __nv_bfloat16* __restrict__ A, int lda,
    const __nv_bfloat16* __restrict__ B, int ldb,
    float* __restrict__ C, int ldc,
    const float* __restrict__ bias,
    const float* __restrict__ resid,
    int K)
{
    extern __shared__ __nv_bfloat16 sm[];
    __nv_bfloat16* As = sm;            // 2 x 64 x 64
    __nv_bfloat16* Bs = sm + 8192;     // 2 bufs x 2 halves x 64 x 64
    int tid = threadIdx.x, lane = tid&31, wid = tid>>5;
    int wm = wid>>2, wn = wid&3;       // 2 x 4
    int m0 = blockIdx.y*64, n0 = blockIdx.x*128;

    int ar = tid >> 2;                 // 0..63
    int ac0 = (tid & 3) << 1;          // 2 chunks each
    const __nv_bfloat16* Ag = A + (size_t)(m0+ar)*lda;
    const __nv_bfloat16* Bg = B + (size_t)ar*ldb + n0;

    int KC = K >> 6;
    {
        #pragma unroll
        for (int c=0;c<2;c++){
            int ch = ac0+c;
            CPA16(smaddr(&As[ar*64 + ((ch ^ (ar&7))<<3)]), Ag + (ch<<3));
        }
        #pragma unroll
        for (int hf=0; hf<2; hf++)
          #pragma unroll
          for (int c=0;c<2;c++){
            int ch = ac0+c;
            CPA16(smaddr(&Bs[hf*4096 + ar*64 + ((ch ^ (ar&7))<<3)]), Bg + hf*64 + (ch<<3));
        }
        CPCOMMIT();
    }

    float acc[2][4][4] = {};
    int g = lane>>3, lr = lane&7;
    int bhalf = wn>>1, bco = (wn&1)<<2;

    for (int kc=0; kc<KC; kc++){
        int cur = kc & 1;
        if (kc+1 < KC){
            int nb = (kc+1)&1, k0 = (kc+1)<<6;
            #pragma unroll
            for (int c=0;c<2;c++){
                int ch = ac0+c;
                CPA16(smaddr(&As[nb*4096 + ar*64 + ((ch ^ (ar&7))<<3)]), Ag + k0 + (ch<<3));
            }
            #pragma unroll
            for (int hf=0; hf<2; hf++)
              #pragma unroll
              for (int c=0;c<2;c++){
                int ch = ac0+c;
                CPA16(smaddr(&Bs[nb*8192 + hf*4096 + ar*64 + ((ch ^ (ar&7))<<3)]),
                      Bg + (size_t)k0*ldb + hf*64 + (ch<<3));
            }
            CPCOMMIT();
            CPWAIT(1);
        } else {
            CPWAIT(0);
        }
        __syncthreads();

        const __nv_bfloat16* Ab = As + cur*4096;
        const __nv_bfloat16* Bb = Bs + cur*8192 + bhalf*4096;
        #pragma unroll
        for (int ks=0; ks<4; ks++){
            uint32_t af[2][4];
            #pragma unroll
            for (int mt=0; mt<2; mt++){
                int arow = wm*32 + mt*16 + lr + ((g&1)<<3);
                int ch = (ks<<1) + (g>>1);
                uint32_t addr = smaddr(&Ab[arow*64 + ((ch ^ (arow&7))<<3)]);
                asm volatile("ldmatrix.sync.aligned.m8n8.x4.shared.b16 {%0,%1,%2,%3}, [%4];\n"
                    : "=r"(af[mt][0]),"=r"(af[mt][1]),"=r"(af[mt][2]),"=r"(af[mt][3]) : "r"(addr));
            }
            uint32_t bf[4][2];
            int krow = (ks<<4) + lr + ((g&1)<<3);
            #pragma unroll
            for (int nt=0; nt<4; nt++){
                int ch = bco + nt;
                uint32_t addr = smaddr(&Bb[krow*64 + ((ch ^ (krow&7))<<3)]);
                asm volatile("ldmatrix.sync.aligned.m8n8.x2.trans.shared.b16 {%0,%1}, [%2];\n"
                    : "=r"(bf[nt][0]),"=r"(bf[nt][1]) : "r"(addr));
            }
            #pragma unroll
            for (int mt=0;mt<2;mt++)
              #pragma unroll
              for (int nt=0;nt<4;nt++)
                mma_bf16(acc[mt][nt], af[mt], bf[nt][0], bf[nt][1]);
        }
        __syncthreads();
    }

    #pragma unroll
    for (int mt=0;mt<2;mt++){
        #pragma unroll
        for (int nt=0;nt<4;nt++){
            int row0 = m0 + wm*32 + mt*16 + (lane>>2);
            int col  = n0 + wn*32 + nt*8 + ((lane&3)<<1);
            float bx=0.f, by=0.f;
            if (bias){ bx = bias[col]; by = bias[col+1]; }
            float2 r0v = make_float2(0.f,0.f), r1v = make_float2(0.f,0.f);
            if (resid){
                r0v = *(const float2*)&resid[(size_t)row0*ldc + col];
                r1v = *(const float2*)&resid[(size_t)(row0+8)*ldc + col];
            }
            *(float2*)&C[(size_t)row0*ldc + col] =
                make_float2(acc[mt][nt][0]+bx+r0v.x, acc[mt][nt][1]+by+r0v.y);
            *(float2*)&C[(size_t)(row0+8)*ldc + col] =
                make_float2(acc[mt][nt][2]+bx+r1v.x, acc[mt][nt][3]+by+r1v.y);
        }
    }
}

// ---------------- fused causal conv + silu + composite gates, 8 tokens/block ----------------
// Stages 11 shared up-rows once; Wg read once per block (8x less L2 traffic).
__global__ __launch_bounds__(256) void conv_gates8_kernel(
    const float* __restrict__ up, const float* __restrict__ cw, const float* __restrict__ cb,
    const float* __restrict__ Wg, const float* __restrict__ bif,
    float* __restrict__ xc, __nv_bfloat16* __restrict__ xcbf,
    float* __restrict__ giT, float* __restrict__ gfT)
{
    __shared__ float ups[11][512];
    __shared__ float xcs[8][512];
    int tok0 = blockIdx.x << 3;
    int t0 = tok0 & 1023;
    int tid = threadIdx.x;

    // stage up rows tok0-3 .. tok0+7 (first channel half only: xm = up[:,0:512])
    for (int idx = tid; idx < 11*512; idx += 256){
        int r = idx >> 9, c = idx & 511;
        int tt = t0 - 3 + r;
        float v = 0.f;
        if (tt >= 0) v = up[(size_t)(tok0 - 3 + r)*1024 + c];
        ups[r][c] = v;
    }
    __syncthreads();

    // conv + silu: 8 tokens x 512 channels
    for (int idx = tid; idx < 8*512; idx += 256){
        int j = idx >> 9, c = idx & 511;
        float acc = cb[c]
                  + cw[c]*ups[j][c] + cw[512+c]*ups[j+1][c]
                  + cw[1024+c]*ups[j+2][c] + cw[1536+c]*ups[j+3][c];
        float sv = acc/(1.f+expf(-acc));
        xcs[j][c] = sv;
        xc[(size_t)(tok0+j)*512 + c] = sv;
        xcbf[(size_t)(tok0+j)*512 + c] = __float2bfloat16(sv);
    }
    __syncthreads();

    // gates: warp j -> token tok0+j; coalesced Wg reads (32B per lane per i)
    int wj = tid>>5, lane = tid&31;
    float acc[8] = {};
    for (int i = lane; i < 512; i += 32){
        float xcv = xcs[wj][i];
        float xmv = ups[wj+3][i];
        float4 w0 = *(const float4*)&Wg[i*8];
        float4 w1 = *(const float4*)&Wg[i*8+4];
        float4 w2 = *(const float4*)&Wg[(512+i)*8];
        float4 w3 = *(const float4*)&Wg[(512+i)*8+4];
        acc[0] += xcv*w0.x + xmv*w2.x;
        acc[1] += xcv*w0.y + xmv*w2.y;
        acc[2] += xcv*w0.z + xmv*w2.z;
        acc[3] += xcv*w0.w + xmv*w2.w;
        acc[4] += xcv*w1.x + xmv*w3.x;
        acc[5] += xcv*w1.y + xmv*w3.y;
        acc[6] += xcv*w1.z + xmv*w3.z;
        acc[7] += xcv*w1.w + xmv*w3.w;
    }
    #pragma unroll
    for (int w=0;w<8;w++) acc[w] = warp_sum(acc[w]);
    if (!lane){
        int tok = tok0 + wj;
        int b = tok >> 10, s = tok & 1023;
        #pragma unroll
        for (int w=0;w<4;w++) giT[(size_t)(b*4+w)*1024 + s] = acc[w] + bif[w];
        #pragma unroll
        for (int w=4;w<8;w++) gfT[(size_t)(b*4+w-4)*1024 + s] = acc[w] + bif[w];
    }
}

// ---------------- gate scan + per-tile col weights ----------------
__global__ void scan_kernel4(const float* __restrict__ giT, const float* __restrict__ gfT,
                             float* __restrict__ Fc, float* __restrict__ a, float* __restrict__ m,
                             float* __restrict__ wcol, float* __restrict__ amaxT){
    __shared__ float ash[1024];
    int bh = blockIdx.x, lane = threadIdx.x;
    const float* gih = giT + (size_t)bh*1024;
    const float* gfh = gfT + (size_t)bh*1024;
    const float scale = 0.08838834764831845f;
    float cfc = 0.f, cmax = -1e30f;
    float ipc = gih[lane], fpc = gfh[lane];
    for (int c=0;c<32;c++){
        float ip = ipc, fp = fpc;
        if (c+1 < 32){ ipc = gih[(c+1)*32+lane]; fpc = gfh[(c+1)*32+lane]; }
        float lf = fminf(fp, 0.f) - log1pf(expf(-fabsf(fp)));
        float x = lf;
        #pragma unroll
        for (int o=1;o<32;o<<=1){ float y = __shfl_up_sync(0xffffffffu, x, o); if (lane>=o) x += y; }
        float fc = cfc + x;
        float av = ip - fc;
        float mx = av;
        #pragma unroll
        for (int o=1;o<32;o<<=1){ float y = __shfl_up_sync(0xffffffffu, mx, o); if (lane>=o) mx = fmaxf(mx, y); }
        float cm = fmaxf(cmax, mx);
        int off = bh*SEQ + c*32 + lane;
        Fc[off] = fc; a[off] = av; m[off] = fc + cm;
        ash[c*32 + lane] = av;
        cfc += __shfl_sync(0xffffffffu, x, 31);
        cmax = fmaxf(cmax, __shfl_sync(0xffffffffu, mx, 31));
    }
    __syncwarp();
    for (int tile=0;tile<16;tile++){
        float v0 = ash[tile*64 + lane];
        float v1 = ash[tile*64 + 32 + lane];
        float mx = fmaxf(v0, v1);
        #pragma unroll
        for (int o=16;o;o>>=1) mx = fmaxf(mx, __shfl_xor_sync(0xffffffffu, mx, o));
        if (lane == 0) amaxT[bh*16 + tile] = mx;
        wcol[bh*SEQ + tile*64 + lane]      = scale*__expf(v0 - mx);
        wcol[bh*SEQ + tile*64 + 32 + lane] = scale*__expf(v1 - mx);
    }
}

// ---------------- mLSTM attention + fused GN/skip/silu-gate epilogue ----------------
#define QKW 68
#define VW  64
#define PW  36
__global__ __launch_bounds__(256) void attn_bf16(
    const __nv_bfloat16* __restrict__ q, const __nv_bfloat16* __restrict__ k,
    const __nv_bfloat16* __restrict__ v,
    const float* __restrict__ Fcv, const float* __restrict__ av, const float* __restrict__ mv,
    const float* __restrict__ wcol, const float* __restrict__ amaxT,
    const float* __restrict__ xc, const float* __restrict__ up,
    const float* __restrict__ gng, const float* __restrict__ gnb,
    const float* __restrict__ skip,
    __nv_bfloat16* __restrict__ out)
{
    extern __shared__ uint32_t smu[];
    uint32_t* Qs = smu;
    uint32_t* Ks = Qs + 64*QKW;
    uint32_t* Vs = Ks + 64*QKW;
    float* fct  = (float*)(Vs + 64*VW);
    float* mt   = fct + 64;
    float* as_  = mt + 64;
    float* den2 = as_ + 64;
    float* dsq  = den2 + 128;

    int bh = blockIdx.x; int b = bh>>2, hh = bh&3;
    int it = (int)(gridDim.y - 1) - (int)blockIdx.y;
    int t0 = it<<6;
    int tid = threadIdx.x, lane = tid&31, wid = tid>>5;
    int wm = wid>>1, wn = wid&1;
    int ls = lane>>2, lk = lane&3;
    int g8 = lane>>3, lr = lane&7;
    const float scale = 0.08838834764831845f;

    const __nv_bfloat16* qg = q + ((size_t)(b*SEQ + t0))*512 + hh*128;
    #pragma unroll
    for (int r=0;r<4;r++){
        int idx = tid + (r<<8);
        int row = idx>>4, c16 = idx&15;
        uint4 val = *(const uint4*)(qg + (size_t)row*512 + (c16<<3));
        *(uint4*)&Qs[row*QKW + (c16<<2)] = val;
    }
    if (tid < 64){ int tg = bh*SEQ + t0 + tid; fct[tid] = Fcv[tg]; mt[tid] = mv[tg]; }
    __syncthreads();

    uint32_t qf[8][4];
    int r0 = wm*16 + ls, r1 = r0 + 8;
    #pragma unroll
    for (int ks=0; ks<8; ks++){
        qf[ks][0] = Qs[r0*QKW + ks*8 + lk];
        qf[ks][1] = Qs[r1*QKW + ks*8 + lk];
        qf[ks][2] = Qs[r0*QKW + ks*8 + lk + 4];
        qf[ks][3] = Qs[r1*QKW + ks*8 + lk + 4];
    }

    float oacc[8][4];
    #pragma unroll
    for (int i=0;i<8;i++){ oacc[i][0]=0.f; oacc[i][1]=0.f; oacc[i][2]=0.f; oacc[i][3]=0.f; }
    float den0 = 0.f, den1 = 0.f;

    for (int js=0; js<=it; js++){
        int s0 = js<<6;
        bool diag = (js == it);
        __syncthreads();
        const __nv_bfloat16* kg = k + ((size_t)(b*SEQ + s0))*512 + hh*128;
        const __nv_bfloat16* vg = v + ((size_t)(b*SEQ + s0))*512 + hh*128;
        #pragma unroll
        for (int r=0;r<4;r++){
            int idx = tid + (r<<8);
            int row = idx>>4, c16 = idx&15;
            uint4 kv = *(const uint4*)(kg + (size_t)row*512 + (c16<<3));
            uint4 vv = *(const uint4*)(vg + (size_t)row*512 + (c16<<3));
            *(uint4*)&Ks[row*QKW + (c16<<2)] = kv;
            *(uint4*)&Vs[row*VW + ((c16 ^ (row&7))<<2)] = vv;
        }
        if (tid < 64)
            as_[tid] = diag ? av[bh*SEQ + s0 + tid] : wcol[bh*SEQ + s0 + tid];
        __syncthreads();

        float sacc[4][4] = {};
        #pragma unroll
        for (int ks=0; ks<8; ks++){
            #pragma unroll
            for (int nt=0; nt<4; nt++){
                int sc = wn*32 + nt*8 + ls;
                uint32_t b0 = Ks[sc*QKW + ks*8 + lk];
                uint32_t b1 = Ks[sc*QKW + ks*8 + lk + 4];
                mma_bf16(sacc[nt], qf[ks], b0, b1);
            }
        }

        float f0 = fct[r0], mm0 = mt[r0], f1 = fct[r1], mm1 = mt[r1];
        if (!diag){
            float amx = amaxT[bh*16 + js];
            float w0 = __expf(f0 - mm0 + amx);
            float w1 = __expf(f1 - mm1 + amx);
            #pragma unroll
            for (int nt=0; nt<4; nt++){
                int c0 = wn*32 + nt*8 + (lk<<1);
                float wc0 = as_[c0], wc1 = as_[c0+1];
                float v00 = sacc[nt][0]*w0*wc0;
                float v01 = sacc[nt][1]*w0*wc1;
                float v10 = sacc[nt][2]*w1*wc0;
                float v11 = sacc[nt][3]*w1*wc1;
                den0 += v00 + v01;
                den1 += v10 + v11;
                int wcl = wn*16 + nt*4 + lk;
                Qs[r0*PW + wcl] = bf2pack(v00, v01);
                Qs[r1*PW + wcl] = bf2pack(v10, v11);
            }
        } else {
            #pragma unroll
            for (int nt=0; nt<4; nt++){
                int c0 = wn*32 + nt*8 + (lk<<1);
                int c1 = c0 + 1;
                float a0v = as_[c0], a1v = as_[c1];
                float v00 = sacc[nt][0]*scale*__expf(f0 + a0v - mm0);
                float v01 = sacc[nt][1]*scale*__expf(f0 + a1v - mm0);
                float v10 = sacc[nt][2]*scale*__expf(f1 + a0v - mm1);
                float v11 = sacc[nt][3]*scale*__expf(f1 + a1v - mm1);
                if (c0 > r0) v00 = 0.f;
                if (c1 > r0) v01 = 0.f;
                if (c0 > r1) v10 = 0.f;
                if (c1 > r1) v11 = 0.f;
                den0 += v00 + v01;
                den1 += v10 + v11;
                int wcl = wn*16 + nt*4 + lk;
                Qs[r0*PW + wcl] = bf2pack(v00, v01);
                Qs[r1*PW + wcl] = bf2pack(v10, v11);
            }
        }
        __syncthreads();

        #pragma unroll
        for (int ks2=0; ks2<4; ks2++){
            uint32_t af[4];
            af[0] = Qs[r0*PW + ks2*8 + lk];
            af[1] = Qs[r1*PW + ks2*8 + lk];
            af[2] = Qs[r0*PW + ks2*8 + lk + 4];
            af[3] = Qs[r1*PW + ks2*8 + lk + 4];
            int krow = (ks2<<4) + lr + ((g8&1)<<3);
            #pragma unroll
            for (int nt=0; nt<8; nt++){
                int cd = wn*8 + nt;
                uint32_t addr = smaddr(&Vs[krow*VW + ((cd ^ (krow&7))<<2)]);
                uint32_t b0, b1;
                asm volatile("ldmatrix.sync.aligned.m8n8.x2.trans.shared.b16 {%0,%1}, [%2];\n"
                    : "=r"(b0),"=r"(b1) : "r"(addr));
                mma_bf16(oacc[nt], af, b0, b1);
            }
        }
    }

    den0 += __shfl_xor_sync(0xffffffffu, den0, 1);
    den0 += __shfl_xor_sync(0xffffffffu, den0, 2);
    den1 += __shfl_xor_sync(0xffffffffu, den1, 1);
    den1 += __shfl_xor_sync(0xffffffffu, den1, 2);
    if (lk == 0){ den2[wn*64 + r0] = den0; den2[wn*64 + r1] = den1; }
    __syncthreads();
    float dt0 = den2[r0] + den2[64 + r0];
    float dt1 = den2[r1] + den2[64 + r1];
    float inv0 = 1.f / (fmaxf(fabsf(dt0), __expf(-mt[r0])) + 1e-6f);
    float inv1 = 1.f / (fmaxf(fabsf(dt1), __expf(-mt[r1])) + 1e-6f);

    float hv0[16], hv1[16];
    #pragma unroll
    for (int nt=0; nt<8; nt++){
        hv0[nt*2]   = oacc[nt][0]*inv0;
        hv0[nt*2+1] = oacc[nt][1]*inv0;
        hv1[nt*2]   = oacc[nt][2]*inv1;
        hv1[nt*2+1] = oacc[nt][3]*inv1;
    }

    float s0 = 0.f, s1 = 0.f, q0 = 0.f, q1 = 0.f;
    #pragma unroll
    for (int i=0;i<16;i++){
        s0 += hv0[i]; q0 += hv0[i]*hv0[i];
        s1 += hv1[i]; q1 += hv1[i]*hv1[i];
    }
    #pragma unroll
    for (int o=1;o<4;o<<=1){
        s0 += __shfl_xor_sync(0xffffffffu, s0, o);
        q0 += __shfl_xor_sync(0xffffffffu, q0, o);
        s1 += __shfl_xor_sync(0xffffffffu, s1, o);
        q1 += __shfl_xor_sync(0xffffffffu, q1, o);
    }
    __syncthreads();
    if (lk == 0){
        den2[wn*64 + r0] = s0; den2[wn*64 + r1] = s1;
        dsq[wn*64 + r0]  = q0; dsq[wn*64 + r1]  = q1;
    }
    __syncthreads();
    float mu0 = (den2[r0] + den2[64 + r0]) * (1.f/128.f);
    float mu1 = (den2[r1] + den2[64 + r1]) * (1.f/128.f);
    float e20 = (dsq[r0] + dsq[64 + r0]) * (1.f/128.f);
    float e21 = (dsq[r1] + dsq[64 + r1]) * (1.f/128.f);
    float is0 = rsqrtf(e20 - mu0*mu0 + 1e-5f);
    float is1 = rsqrtf(e21 - mu1*mu1 + 1e-5f);

    size_t tok0 = (size_t)(b*SEQ + t0 + r0), tok1 = (size_t)(b*SEQ + t0 + r1);
    #pragma unroll
    for (int nt=0; nt<8; nt++){
        int dc = wn*64 + nt*8 + (lk<<1);
        int c = hh*128 + dc;
        float2 gg = *(const float2*)&gng[c];
        float2 gb = *(const float2*)&gnb[c];
        float2 sk = *(const float2*)&skip[c];
        float2 x0 = *(const float2*)&xc[tok0*512 + c];
        float2 x1 = *(const float2*)&xc[tok1*512 + c];
        float2 z0 = *(const float2*)&up[tok0*1024 + 512 + c];
        float2 z1 = *(const float2*)&up[tok1*1024 + 512 + c];
        float y00 = (hv0[nt*2]  -mu0)*is0*gg.x + gb.x + sk.x*x0.x;
        float y01 = (hv0[nt*2+1]-mu0)*is0*gg.y + gb.y + sk.y*x0.y;
        float y10 = (hv1[nt*2]  -mu1)*is1*gg.x + gb.x + sk.x*x1.x;
        float y11 = (hv1[nt*2+1]-mu1)*is1*gg.y + gb.y + sk.y*x1.y;
        y00 *= z0.x / (1.f + expf(-z0.x));
        y01 *= z0.y / (1.f + expf(-z0.y));
        y10 *= z1.x / (1.f + expf(-z1.x));
        y11 *= z1.y / (1.f + expf(-z1.y));
        *(__nv_bfloat162*)&out[tok0*512 + c] = __floats2bfloat162_rn(y00, y01);
        *(__nv_bfloat162*)&out[tok1*512 + c] = __floats2bfloat162_rn(y10, y11);
    }
}

// ---------------- final ----------------
__global__ void final_kernel(const float* __restrict__ h, const float* __restrict__ g,
                             const float* __restrict__ b, const float* __restrict__ Wf,
                             const float* __restrict__ bf, float* __restrict__ out){
    __shared__ float sh[8];
    __shared__ float sv;
    int bb = blockIdx.x, tid = threadIdx.x;
    float vv = h[((size_t)(bb*SEQ + SEQ-1))*256 + tid];
    float s = warp_sum(vv);
    if (!(tid&31)) sh[tid>>5] = s;
    __syncthreads();
    if (tid==0){ float t=0; for(int i=0;i<8;i++) t+=sh[i]; sv = t*(1.f/256.f); }
    __syncthreads();
    float mu = sv;
    float d = vv - mu;
    float s2 = warp_sum(d*d);
    if (!(tid&31)) sh[tid>>5] = s2;
    __syncthreads();
    if (tid==0){ float t=0; for(int i=0;i<8;i++) t+=sh[i]; sv = t*(1.f/256.f); }
    __syncthreads();
    float yn = d*rsqrtf(sv + 1e-5f)*g[tid] + b[tid];
    float p = yn * Wf[tid];
    float s3 = warp_sum(p);
    __syncthreads();
    if (!(tid&31)) sh[tid>>5] = s3;
    __syncthreads();
    if (tid==0){ float t=0; for(int i=0;i<8;i++) t+=sh[i]; out[bb] = t + bf[0]; }
}

// ---------------- launch ----------------
extern "C" void kernel_launch(void* const* d_in, const int* in_sizes, int n_in,
                              void* d_out, int out_size){
    const float* x    = (const float*)d_in[0];
    const float* tf   = (const float*)d_in[1];
    const float* Wp   = (const float*)d_in[2];
    const float* bp   = (const float*)d_in[3];
    const float* ln_g = (const float*)d_in[4];
    const float* ln_b = (const float*)d_in[5];
    const float* Wup  = (const float*)d_in[6];
    const float* bup  = (const float*)d_in[7];
    const float* cw   = (const float*)d_in[8];
    const float* cb   = (const float*)d_in[9];
    const float* Wq   = (const float*)d_in[10];
    const float* Wk   = (const float*)d_in[11];
    const float* Wv   = (const float*)d_in[12];
    const float* Wif  = (const float*)d_in[13];
    const float* bif  = (const float*)d_in[14];
    const float* gng  = (const float*)d_in[15];
    const float* gnb  = (const float*)d_in[16];
    const float* skip = (const float*)d_in[17];
    const float* Wdn  = (const float*)d_in[18];
    const float* bdn  = (const float*)d_in[19];
    const float* lnfg = (const float*)d_in[20];
    const float* lnfb = (const float*)d_in[21];
    const float* Wf   = (const float*)d_in[22];
    const float* bf   = (const float*)d_in[23];

    float *h,*up,*xc,*giT,*gfT,*Fc,*a,*m,*wcol,*amaxT,*Wg;
    __nv_bfloat16 *hnbf,*xcbf,*upbf,*qbf,*kbf,*vbf,*att2bf,*wupbf,*wqbf,*wkbf,*wvbf,*wdnbf;
    cudaGetSymbolAddress((void**)&h,    g_h);
    cudaGetSymbolAddress((void**)&up,   g_up);
    cudaGetSymbolAddress((void**)&xc,   g_xc);
    cudaGetSymbolAddress((void**)&giT,  g_giT);
    cudaGetSymbolAddress((void**)&gfT,  g_gfT);
    cudaGetSymbolAddress((void**)&Fc,   g_Fc);
    cudaGetSymbolAddress((void**)&a,    g_a);
    cudaGetSymbolAddress((void**)&m,    g_m);
    cudaGetSymbolAddress((void**)&wcol, g_wcol);
    cudaGetSymbolAddress((void**)&amaxT,g_amaxT);
    cudaGetSymbolAddress((void**)&Wg,   g_Wg);
    cudaGetSymbolAddress((void**)&hnbf, g_hn_bf);
    cudaGetSymbolAddress((void**)&xcbf, g_xc_bf);
    cudaGetSymbolAddress((void**)&upbf, g_up_bf);
    cudaGetSymbolAddress((void**)&qbf,  g_q_bf);
    cudaGetSymbolAddress((void**)&kbf,  g_k_bf);
    cudaGetSymbolAddress((void**)&vbf,  g_v_bf);
    cudaGetSymbolAddress((void**)&att2bf, g_att2_bf);
    cudaGetSymbolAddress((void**)&wupbf, g_wup_bf);
    cudaGetSymbolAddress((void**)&wqbf,  g_wq_bf);
    cudaGetSymbolAddress((void**)&wkbf,  g_wk_bf);
    cudaGetSymbolAddress((void**)&wvbf,  g_wv_bf);
    cudaGetSymbolAddress((void**)&wdnbf, g_wdn_bf);

    int attn_smem = (64*QKW + 64*QKW + 64*VW + 64 + 64 + 64 + 128 + 128) * 4;
    int gemm_smem = 65536;
    int gemm64_smem = 49152;
    static int attr_set = 0;
    if (!attr_set){
        cudaFuncSetAttribute(attn_bf16, cudaFuncAttributeMaxDynamicSharedMemorySize, attn_smem);
        cudaFuncSetAttribute(gemm_bf16, cudaFuncAttributeMaxDynamicSharedMemorySize, gemm_smem);
        cudaFuncSetAttribute(gemm_bf16_m64, cudaFuncAttributeMaxDynamicSharedMemorySize, gemm64_smem);
        attr_set = 1;
    }

    int n0 = NL*DMODEL*1024, n1 = NL*DI*DI, n4 = NL*DI*DMODEL;
    int ntot = n0 + 3*n1 + n4;
    f2bf5_kernel<<<(ntot/2 + 255)/256, 256>>>(Wup, wupbf, n0,
                                              Wq, wqbf, n1,
                                              Wk, wkbf, n1,
                                              Wv, wvbf, n1,
                                              Wdn, wdnbf, n4);
    gatew_kernel<<<NL*1024*8/256, 256>>>(Wq, Wk, Wv, Wif, Wg);

    embed_kernel<<<TOK*256/256, 256>>>(x, tf, Wp, bp, h);

    for (int l=0; l<NL; l++){
        ln_kernel<<<TOK/8, 256>>>(h, ln_g + l*256, ln_b + l*256, hnbf);
        gemm_bf16<<<dim3(1024/128, TOK/128, 1), 256, gemm_smem>>>(
            hnbf, 256, wupbf + (size_t)l*256*1024, 1024,
            up, 1024, bup + l*1024, nullptr, 256,
            upbf, 512, nullptr, nullptr, nullptr, nullptr, nullptr);
        conv_gates8_kernel<<<TOK/8, 256>>>(up, cw + l*4*512, cb + l*512,
                                           Wg + (size_t)l*8192, bif + l*8,
                                           xc, xcbf, giT, gfT);
        gemm_bf16<<<dim3(512/128, TOK/128, 3), 256, gemm_smem>>>(
            xcbf, 512, wqbf + (size_t)l*512*512, 512,
            nullptr, 512, nullptr, nullptr, 512, qbf, 512,
            upbf,
            wkbf + (size_t)l*512*512, kbf,
            wvbf + (size_t)l*512*512, vbf);
        scan_kernel4<<<32, 32>>>(giT, gfT, Fc, a, m, wcol, amaxT);
        attn_bf16<<<dim3(BATCH*NH, SEQ/64), 256, attn_smem>>>(qbf, kbf, vbf, Fc, a, m,
                                                  wcol, amaxT,
                                                  xc, up, gng + l*512, gnb + l*512, skip + l*512,
                                                  att2bf);
        gemm_bf16_m64<<<dim3(256/128, TOK/64, 1), 256, gemm64_smem>>>(
            att2bf, 512, wdnbf + (size_t)l*512*256, 256,
            h, 256, bdn + l*256, h, 512);
    }
    final_kernel<<<BATCH, 256>>>(h, lnfg, lnfb, Wf, bf, (float*)d_out);
}

// round 15
// speedup vs baseline: 1.4369x; 1.0976x over previous
#include <cuda_runtime.h>
#include <cuda_bf16.h>
#include <cstdint>
#include <cstddef>

#define SEQ 1024
#define BATCH 8
#define TOK (BATCH*SEQ)
#define DMODEL 256
#define DI 512
#define NH 4
#define DHH 128
#define NL 4

// ---------------- scratch (device globals; no allocation allowed) ----------------
__device__ float g_h[TOK*DMODEL];
__device__ float g_up[TOK*1024];
__device__ float g_xc[TOK*DI];
__device__ float g_giT[BATCH*NH*SEQ];
__device__ float g_gfT[BATCH*NH*SEQ];
__device__ float g_Fc[BATCH*NH*SEQ];
__device__ float g_a[BATCH*NH*SEQ];
__device__ float g_m[BATCH*NH*SEQ];
__device__ float g_wcol[BATCH*NH*SEQ];
__device__ float g_amaxT[BATCH*NH*16];
__device__ float g_mq[BATCH*NH*16];
__device__ float g_Wg[NL*1024*8];

__device__ __nv_bfloat16 g_hn_bf[TOK*DMODEL];
__device__ __nv_bfloat16 g_xc_bf[TOK*DI];
__device__ __nv_bfloat16 g_up_bf[TOK*DI];
__device__ __nv_bfloat16 g_q_bf[TOK*DI];
__device__ __nv_bfloat16 g_k_bf[TOK*DI];
__device__ __nv_bfloat16 g_v_bf[TOK*DI];
__device__ __nv_bfloat16 g_att2_bf[TOK*DI];
__device__ __nv_bfloat16 g_wup_bf[NL*DMODEL*1024];
__device__ __nv_bfloat16 g_wq_bf[NL*DI*DI];
__device__ __nv_bfloat16 g_wk_bf[NL*DI*DI];
__device__ __nv_bfloat16 g_wv_bf[NL*DI*DI];
__device__ __nv_bfloat16 g_wdn_bf[NL*DI*DMODEL];

__device__ __forceinline__ float warp_sum(float v){
    #pragma unroll
    for (int o=16;o;o>>=1) v += __shfl_xor_sync(0xffffffffu, v, o);
    return v;
}

__device__ __forceinline__ uint32_t bf2pack(float x, float y){
    __nv_bfloat162 t = __floats2bfloat162_rn(x, y);
    return *(uint32_t*)&t;
}

__device__ __forceinline__ void mma_bf16(float* c, const uint32_t* a, uint32_t b0, uint32_t b1){
    asm volatile(
      "mma.sync.aligned.m16n8k16.row.col.f32.bf16.bf16.f32 "
      "{%0,%1,%2,%3}, {%4,%5,%6,%7}, {%8,%9}, {%0,%1,%2,%3};\n"
      : "+f"(c[0]), "+f"(c[1]), "+f"(c[2]), "+f"(c[3])
      : "r"(a[0]), "r"(a[1]), "r"(a[2]), "r"(a[3]), "r"(b0), "r"(b1));
}

__device__ __forceinline__ uint32_t smaddr(const void* p){
    return (uint32_t)__cvta_generic_to_shared(p);
}
#define CPA16(dst,src) asm volatile("cp.async.cg.shared.global [%0], [%1], 16;\n"::"r"(dst),"l"(src))
#define CPCOMMIT() asm volatile("cp.async.commit_group;\n")
#define CPWAIT(n) asm volatile("cp.async.wait_group %0;\n"::"n"(n))

// ---------------- merged f32 -> bf16 convert for all 5 weight tensors ----------------
__global__ void f2bf5_kernel(const float* __restrict__ i0, __nv_bfloat16* __restrict__ o0, int n0,
                             const float* __restrict__ i1, __nv_bfloat16* __restrict__ o1, int n1,
                             const float* __restrict__ i2, __nv_bfloat16* __restrict__ o2, int n2,
                             const float* __restrict__ i3, __nv_bfloat16* __restrict__ o3, int n3,
                             const float* __restrict__ i4, __nv_bfloat16* __restrict__ o4, int n4){
    int i = (blockIdx.x*blockDim.x + threadIdx.x)*2;
    const float* in; __nv_bfloat16* out;
    if (i < n0){ in=i0; out=o0; }
    else if ((i-=n0) < n1){ in=i1; out=o1; }
    else if ((i-=n1) < n2){ in=i2; out=o2; }
    else if ((i-=n2) < n3){ in=i3; out=o3; }
    else if ((i-=n3) < n4){ in=i4; out=o4; }
    else return;
    float2 v = *(const float2*)(in+i);
    *(__nv_bfloat162*)(out+i) = __floats2bfloat162_rn(v.x, v.y);
}

// ---------------- composite gate weights ----------------
__global__ void gatew_kernel(const float* __restrict__ Wq, const float* __restrict__ Wk,
                             const float* __restrict__ Wv, const float* __restrict__ Wif,
                             float* __restrict__ Wg){
    int idx = blockIdx.x*blockDim.x + threadIdx.x;
    int l = idx >> 13; int r = idx & 8191;
    int c = r >> 3; int j = r & 7;
    const float* Wifl = Wif + (size_t)l*1536*8;
    float acc = 0.f;
    if (c < 512){
        const float* wq = Wq + ((size_t)l*512 + c)*512;
        const float* wk = Wk + ((size_t)l*512 + c)*512;
        #pragma unroll 4
        for (int i=0;i<512;i++)
            acc += wq[i]*Wifl[i*8+j] + wk[i]*Wifl[(512+i)*8+j];
    } else {
        const float* wv = Wv + ((size_t)l*512 + (c-512))*512;
        #pragma unroll 4
        for (int i=0;i<512;i++)
            acc += wv[i]*Wifl[(1024+i)*8+j];
    }
    Wg[(size_t)l*8192 + c*8 + j] = acc;
}

// ---------------- embed ----------------
__global__ void embed_kernel(const float* __restrict__ x, const float* __restrict__ tf,
                             const float* __restrict__ Wp, const float* __restrict__ bp,
                             float* __restrict__ h){
    int idx = blockIdx.x*blockDim.x + threadIdx.x;
    int j = idx & 255; int tok = idx >> 8;
    float acc = bp[j] + x[tok]*Wp[j];
    #pragma unroll
    for (int f=0; f<4; f++) acc += tf[tok*4+f]*Wp[(1+f)*256+j];
    h[idx] = acc;
}

// ---------------- layernorm, bf16 out ----------------
__global__ void ln_kernel(const float* __restrict__ x, const float* __restrict__ g,
                          const float* __restrict__ b, __nv_bfloat16* __restrict__ y){
    int row = blockIdx.x*8 + (threadIdx.x>>5);
    int lane = threadIdx.x & 31;
    const float* xr = x + (size_t)row*256;
    float4 v0 = *(const float4*)(xr + lane*4);
    float4 v1 = *(const float4*)(xr + 128 + lane*4);
    float s  = v0.x+v0.y+v0.z+v0.w + v1.x+v1.y+v1.z+v1.w;
    float sq = v0.x*v0.x+v0.y*v0.y+v0.z*v0.z+v0.w*v0.w
             + v1.x*v1.x+v1.y*v1.y+v1.z*v1.z+v1.w*v1.w;
    #pragma unroll
    for (int o=16;o;o>>=1){
        s  += __shfl_xor_sync(0xffffffffu, s,  o);
        sq += __shfl_xor_sync(0xffffffffu, sq, o);
    }
    float mu = s * (1.f/256.f);
    float var = sq * (1.f/256.f) - mu*mu;
    float is = rsqrtf(var + 1e-5f);
    float4 g0 = *(const float4*)(g + lane*4);
    float4 g1 = *(const float4*)(g + 128 + lane*4);
    float4 b0 = *(const float4*)(b + lane*4);
    float4 b1 = *(const float4*)(b + 128 + lane*4);
    __nv_bfloat16* yr = y + (size_t)row*256;
    *(__nv_bfloat162*)&yr[lane*4]       = __floats2bfloat162_rn((v0.x-mu)*is*g0.x + b0.x, (v0.y-mu)*is*g0.y + b0.y);
    *(__nv_bfloat162*)&yr[lane*4+2]     = __floats2bfloat162_rn((v0.z-mu)*is*g0.z + b0.z, (v0.w-mu)*is*g0.w + b0.w);
    *(__nv_bfloat162*)&yr[128+lane*4]   = __floats2bfloat162_rn((v1.x-mu)*is*g1.x + b1.x, (v1.y-mu)*is*g1.y + b1.y);
    *(__nv_bfloat162*)&yr[128+lane*4+2] = __floats2bfloat162_rn((v1.z-mu)*is*g1.z + b1.z, (v1.w-mu)*is*g1.w + b1.w);
}

// ---------------- bf16 tensor-core GEMM: CTA 128x128x64, 8 warps 2x4 ----------------
__global__ __launch_bounds__(256, 2) void gemm_bf16(
    const __nv_bfloat16* __restrict__ A, int lda,
    const __nv_bfloat16* __restrict__ B, int ldb,
    float* __restrict__ C, int ldc,
    const float* __restrict__ bias,
    const float* __restrict__ resid,
    int K,
    __nv_bfloat16* __restrict__ Cbf, int bfcap,
    const __nv_bfloat16* __restrict__ A2,
    const __nv_bfloat16* __restrict__ B2,
    __nv_bfloat16* __restrict__ Cbf2,
    const __nv_bfloat16* __restrict__ B3,
    __nv_bfloat16* __restrict__ Cbf3)
{
    extern __shared__ __nv_bfloat16 sm[];
    __nv_bfloat16* As = sm;            // 2 x 128 x 64
    __nv_bfloat16* Bs = sm + 16384;    // 2 bufs x 2 halves x 64 x 64
    if (blockIdx.z == 1){ B = B2; Cbf = Cbf2; }
    else if (blockIdx.z == 2){ A = A2; B = B3; Cbf = Cbf3; }
    int tid = threadIdx.x, lane = tid&31, wid = tid>>5;
    int wm = wid>>2, wn = wid&3;
    int m0 = blockIdx.y*128, n0 = blockIdx.x*128;

    int ar = tid >> 1;
    int ac0 = (tid & 1) << 2;
    int br = tid >> 2;
    int bc0 = (tid & 3) << 1;
    const __nv_bfloat16* Ag = A + (size_t)(m0+ar)*lda;
    const __nv_bfloat16* Bg = B + (size_t)br*ldb + n0;

    int KC = K >> 6;
    {
        #pragma unroll
        for (int c=0;c<4;c++){
            int ch = ac0+c;
            CPA16(smaddr(&As[ar*64 + ((ch ^ (ar&7))<<3)]), Ag + (ch<<3));
        }
        #pragma unroll
        for (int hf=0; hf<2; hf++)
          #pragma unroll
          for (int c=0;c<2;c++){
            int ch = bc0+c;
            CPA16(smaddr(&Bs[hf*4096 + br*64 + ((ch ^ (br&7))<<3)]), Bg + hf*64 + (ch<<3));
        }
        CPCOMMIT();
    }

    float acc[4][4][4] = {};
    int g = lane>>3, lr = lane&7;
    int bhalf = wn>>1, bco = (wn&1)<<2;

    for (int kc=0; kc<KC; kc++){
        int cur = kc & 1;
        if (kc+1 < KC){
            int nb = (kc+1)&1, k0 = (kc+1)<<6;
            #pragma unroll
            for (int c=0;c<4;c++){
                int ch = ac0+c;
                CPA16(smaddr(&As[nb*8192 + ar*64 + ((ch ^ (ar&7))<<3)]), Ag + k0 + (ch<<3));
            }
            #pragma unroll
            for (int hf=0; hf<2; hf++)
              #pragma unroll
              for (int c=0;c<2;c++){
                int ch = bc0+c;
                CPA16(smaddr(&Bs[nb*8192 + hf*4096 + br*64 + ((ch ^ (br&7))<<3)]),
                      Bg + (size_t)k0*ldb + hf*64 + (ch<<3));
            }
            CPCOMMIT();
            CPWAIT(1);
        } else {
            CPWAIT(0);
        }
        __syncthreads();

        const __nv_bfloat16* Ab = As + cur*8192;
        const __nv_bfloat16* Bb = Bs + cur*8192 + bhalf*4096;
        #pragma unroll
        for (int ks=0; ks<4; ks++){
            uint32_t af[4][4];
            #pragma unroll
            for (int mt=0; mt<4; mt++){
                int arow = wm*64 + mt*16 + lr + ((g&1)<<3);
                int ch = (ks<<1) + (g>>1);
                uint32_t addr = smaddr(&Ab[arow*64 + ((ch ^ (arow&7))<<3)]);
                asm volatile("ldmatrix.sync.aligned.m8n8.x4.shared.b16 {%0,%1,%2,%3}, [%4];\n"
                    : "=r"(af[mt][0]),"=r"(af[mt][1]),"=r"(af[mt][2]),"=r"(af[mt][3]) : "r"(addr));
            }
            uint32_t bf[4][2];
            int krow = (ks<<4) + lr + ((g&1)<<3);
            #pragma unroll
            for (int nt=0; nt<4; nt++){
                int ch = bco + nt;
                uint32_t addr = smaddr(&Bb[krow*64 + ((ch ^ (krow&7))<<3)]);
                asm volatile("ldmatrix.sync.aligned.m8n8.x2.trans.shared.b16 {%0,%1}, [%2];\n"
                    : "=r"(bf[nt][0]),"=r"(bf[nt][1]) : "r"(addr));
            }
            #pragma unroll
            for (int mt=0;mt<4;mt++)
              #pragma unroll
              for (int nt=0;nt<4;nt++)
                mma_bf16(acc[mt][nt], af[mt], bf[nt][0], bf[nt][1]);
        }
        __syncthreads();
    }

    #pragma unroll
    for (int mt=0;mt<4;mt++){
        #pragma unroll
        for (int nt=0;nt<4;nt++){
            int row0 = m0 + wm*64 + mt*16 + (lane>>2);
            int col  = n0 + wn*32 + nt*8 + ((lane&3)<<1);
            float bx=0.f, by=0.f;
            if (bias){ bx = bias[col]; by = bias[col+1]; }
            float2 r0v = make_float2(0.f,0.f), r1v = make_float2(0.f,0.f);
            if (resid){
                r0v = *(const float2*)&resid[(size_t)row0*ldc + col];
                r1v = *(const float2*)&resid[(size_t)(row0+8)*ldc + col];
            }
            float v00 = acc[mt][nt][0]+bx+r0v.x, v01 = acc[mt][nt][1]+by+r0v.y;
            float v10 = acc[mt][nt][2]+bx+r1v.x, v11 = acc[mt][nt][3]+by+r1v.y;
            if (C){
                *(float2*)&C[(size_t)row0*ldc + col]     = make_float2(v00, v01);
                *(float2*)&C[(size_t)(row0+8)*ldc + col] = make_float2(v10, v11);
            }
            if (Cbf && col < bfcap){
                *(__nv_bfloat162*)&Cbf[(size_t)row0*bfcap + col]     = __floats2bfloat162_rn(v00, v01);
                *(__nv_bfloat162*)&Cbf[(size_t)(row0+8)*bfcap + col] = __floats2bfloat162_rn(v10, v11);
            }
        }
    }
}

// ---------------- bf16 GEMM, CTA 64x128x64 (down-GEMM; better grid fill) ----------------
__global__ __launch_bounds__(256, 2) void gemm_bf16_m64(
    const __nv_bfloat16* __restrict__ A, int lda,
    const __nv_bfloat16* __restrict__ B, int ldb,
    float* __restrict__ C, int ldc,
    const float* __restrict__ bias,
    const float* __restrict__ resid,
    int K)
{
    extern __shared__ __nv_bfloat16 sm[];
    __nv_bfloat16* As = sm;            // 2 x 64 x 64
    __nv_bfloat16* Bs = sm + 8192;     // 2 bufs x 2 halves x 64 x 64
    int tid = threadIdx.x, lane = tid&31, wid = tid>>5;
    int wm = wid>>2, wn = wid&3;
    int m0 = blockIdx.y*64, n0 = blockIdx.x*128;

    int ar = tid >> 2;
    int ac0 = (tid & 3) << 1;
    const __nv_bfloat16* Ag = A + (size_t)(m0+ar)*lda;
    const __nv_bfloat16* Bg = B + (size_t)ar*ldb + n0;

    int KC = K >> 6;
    {
        #pragma unroll
        for (int c=0;c<2;c++){
            int ch = ac0+c;
            CPA16(smaddr(&As[ar*64 + ((ch ^ (ar&7))<<3)]), Ag + (ch<<3));
        }
        #pragma unroll
        for (int hf=0; hf<2; hf++)
          #pragma unroll
          for (int c=0;c<2;c++){
            int ch = ac0+c;
            CPA16(smaddr(&Bs[hf*4096 + ar*64 + ((ch ^ (ar&7))<<3)]), Bg + hf*64 + (ch<<3));
        }
        CPCOMMIT();
    }

    float acc[2][4][4] = {};
    int g = lane>>3, lr = lane&7;
    int bhalf = wn>>1, bco = (wn&1)<<2;

    for (int kc=0; kc<KC; kc++){
        int cur = kc & 1;
        if (kc+1 < KC){
            int nb = (kc+1)&1, k0 = (kc+1)<<6;
            #pragma unroll
            for (int c=0;c<2;c++){
                int ch = ac0+c;
                CPA16(smaddr(&As[nb*4096 + ar*64 + ((ch ^ (ar&7))<<3)]), Ag + k0 + (ch<<3));
            }
            #pragma unroll
            for (int hf=0; hf<2; hf++)
              #pragma unroll
              for (int c=0;c<2;c++){
                int ch = ac0+c;
                CPA16(smaddr(&Bs[nb*8192 + hf*4096 + ar*64 + ((ch ^ (ar&7))<<3)]),
                      Bg + (size_t)k0*ldb + hf*64 + (ch<<3));
            }
            CPCOMMIT();
            CPWAIT(1);
        } else {
            CPWAIT(0);
        }
        __syncthreads();

        const __nv_bfloat16* Ab = As + cur*4096;
        const __nv_bfloat16* Bb = Bs + cur*8192 + bhalf*4096;
        #pragma unroll
        for (int ks=0; ks<4; ks++){
            uint32_t af[2][4];
            #pragma unroll
            for (int mt=0; mt<2; mt++){
                int arow = wm*32 + mt*16 + lr + ((g&1)<<3);
                int ch = (ks<<1) + (g>>1);
                uint32_t addr = smaddr(&Ab[arow*64 + ((ch ^ (arow&7))<<3)]);
                asm volatile("ldmatrix.sync.aligned.m8n8.x4.shared.b16 {%0,%1,%2,%3}, [%4];\n"
                    : "=r"(af[mt][0]),"=r"(af[mt][1]),"=r"(af[mt][2]),"=r"(af[mt][3]) : "r"(addr));
            }
            uint32_t bf[4][2];
            int krow = (ks<<4) + lr + ((g&1)<<3);
            #pragma unroll
            for (int nt=0; nt<4; nt++){
                int ch = bco + nt;
                uint32_t addr = smaddr(&Bb[krow*64 + ((ch ^ (krow&7))<<3)]);
                asm volatile("ldmatrix.sync.aligned.m8n8.x2.trans.shared.b16 {%0,%1}, [%2];\n"
                    : "=r"(bf[nt][0]),"=r"(bf[nt][1]) : "r"(addr));
            }
            #pragma unroll
            for (int mt=0;mt<2;mt++)
              #pragma unroll
              for (int nt=0;nt<4;nt++)
                mma_bf16(acc[mt][nt], af[mt], bf[nt][0], bf[nt][1]);
        }
        __syncthreads();
    }

    #pragma unroll
    for (int mt=0;mt<2;mt++){
        #pragma unroll
        for (int nt=0;nt<4;nt++){
            int row0 = m0 + wm*32 + mt*16 + (lane>>2);
            int col  = n0 + wn*32 + nt*8 + ((lane&3)<<1);
            float bx=0.f, by=0.f;
            if (bias){ bx = bias[col]; by = bias[col+1]; }
            float2 r0v = make_float2(0.f,0.f), r1v = make_float2(0.f,0.f);
            if (resid){
                r0v = *(const float2*)&resid[(size_t)row0*ldc + col];
                r1v = *(const float2*)&resid[(size_t)(row0+8)*ldc + col];
            }
            *(float2*)&C[(size_t)row0*ldc + col] =
                make_float2(acc[mt][nt][0]+bx+r0v.x, acc[mt][nt][1]+by+r0v.y);
            *(float2*)&C[(size_t)(row0+8)*ldc + col] =
                make_float2(acc[mt][nt][2]+bx+r1v.x, acc[mt][nt][3]+by+r1v.y);
        }
    }
}

// ---------------- fused causal conv + silu + composite gates, 8 tokens/block ----------------
__global__ __launch_bounds__(256) void conv_gates8_kernel(
    const float* __restrict__ up, const float* __restrict__ cw, const float* __restrict__ cb,
    const float* __restrict__ Wg, const float* __restrict__ bif,
    float* __restrict__ xc, __nv_bfloat16* __restrict__ xcbf,
    float* __restrict__ giT, float* __restrict__ gfT)
{
    __shared__ float ups[11][512];
    __shared__ float xcs[8][512];
    int tok0 = blockIdx.x << 3;
    int t0 = tok0 & 1023;
    int tid = threadIdx.x;

    for (int idx = tid; idx < 11*512; idx += 256){
        int r = idx >> 9, c = idx & 511;
        int tt = t0 - 3 + r;
        float v = 0.f;
        if (tt >= 0) v = up[(size_t)(tok0 - 3 + r)*1024 + c];
        ups[r][c] = v;
    }
    __syncthreads();

    for (int idx = tid; idx < 8*512; idx += 256){
        int j = idx >> 9, c = idx & 511;
        float acc = cb[c]
                  + cw[c]*ups[j][c] + cw[512+c]*ups[j+1][c]
                  + cw[1024+c]*ups[j+2][c] + cw[1536+c]*ups[j+3][c];
        float sv = acc/(1.f+expf(-acc));
        xcs[j][c] = sv;
        xc[(size_t)(tok0+j)*512 + c] = sv;
        xcbf[(size_t)(tok0+j)*512 + c] = __float2bfloat16(sv);
    }
    __syncthreads();

    int wj = tid>>5, lane = tid&31;
    float acc[8] = {};
    for (int i = lane; i < 512; i += 32){
        float xcv = xcs[wj][i];
        float xmv = ups[wj+3][i];
        float4 w0 = *(const float4*)&Wg[i*8];
        float4 w1 = *(const float4*)&Wg[i*8+4];
        float4 w2 = *(const float4*)&Wg[(512+i)*8];
        float4 w3 = *(const float4*)&Wg[(512+i)*8+4];
        acc[0] += xcv*w0.x + xmv*w2.x;
        acc[1] += xcv*w0.y + xmv*w2.y;
        acc[2] += xcv*w0.z + xmv*w2.z;
        acc[3] += xcv*w0.w + xmv*w2.w;
        acc[4] += xcv*w1.x + xmv*w3.x;
        acc[5] += xcv*w1.y + xmv*w3.y;
        acc[6] += xcv*w1.z + xmv*w3.z;
        acc[7] += xcv*w1.w + xmv*w3.w;
    }
    #pragma unroll
    for (int w=0;w<8;w++) acc[w] = warp_sum(acc[w]);
    if (!lane){
        int tok = tok0 + wj;
        int b = tok >> 10, s = tok & 1023;
        #pragma unroll
        for (int w=0;w<4;w++) giT[(size_t)(b*4+w)*1024 + s] = acc[w] + bif[w];
        #pragma unroll
        for (int w=4;w<8;w++) gfT[(size_t)(b*4+w-4)*1024 + s] = acc[w] + bif[w];
    }
}

// ---------------- gate scan + per-tile col weights + per-qtile row bound ----------------
__global__ void scan_kernel4(const float* __restrict__ giT, const float* __restrict__ gfT,
                             float* __restrict__ Fc, float* __restrict__ a, float* __restrict__ m,
                             float* __restrict__ wcol, float* __restrict__ amaxT,
                             float* __restrict__ mq){
    __shared__ float ash[1024];
    int bh = blockIdx.x, lane = threadIdx.x;
    const float* gih = giT + (size_t)bh*1024;
    const float* gfh = gfT + (size_t)bh*1024;
    const float scale = 0.08838834764831845f;
    float cfc = 0.f, cmax = -1e30f;
    float ipc = gih[lane], fpc = gfh[lane];
    for (int c=0;c<32;c++){
        float ip = ipc, fp = fpc;
        if (c+1 < 32){ ipc = gih[(c+1)*32+lane]; fpc = gfh[(c+1)*32+lane]; }
        float lf = fminf(fp, 0.f) - log1pf(expf(-fabsf(fp)));
        float x = lf;
        #pragma unroll
        for (int o=1;o<32;o<<=1){ float y = __shfl_up_sync(0xffffffffu, x, o); if (lane>=o) x += y; }
        float fc = cfc + x;
        float av = ip - fc;
        float mx = av;
        #pragma unroll
        for (int o=1;o<32;o<<=1){ float y = __shfl_up_sync(0xffffffffu, mx, o); if (lane>=o) mx = fmaxf(mx, y); }
        float cm = fmaxf(cmax, mx);
        int pos = c*32 + lane;
        int off = bh*SEQ + pos;
        Fc[off] = fc; a[off] = av; m[off] = fc + cm;
        // fct - mt = -cm (non-increasing in t), so max over a 64-row tile is at its first row
        if ((pos & 63) == 0) mq[bh*16 + (pos>>6)] = -cm;
        ash[pos] = av;
        cfc += __shfl_sync(0xffffffffu, x, 31);
        cmax = fmaxf(cmax, __shfl_sync(0xffffffffu, mx, 31));
    }
    __syncwarp();
    for (int tile=0;tile<16;tile++){
        float v0 = ash[tile*64 + lane];
        float v1 = ash[tile*64 + 32 + lane];
        float mx = fmaxf(v0, v1);
        #pragma unroll
        for (int o=16;o;o>>=1) mx = fmaxf(mx, __shfl_xor_sync(0xffffffffu, mx, o));
        if (lane == 0) amaxT[bh*16 + tile] = mx;
        wcol[bh*SEQ + tile*64 + lane]      = scale*__expf(v0 - mx);
        wcol[bh*SEQ + tile*64 + 32 + lane] = scale*__expf(v1 - mx);
    }
}

// ---------------- mLSTM attention + decay-bound tile skipping + fused epilogue ----------------
#define QKW 68
#define VW  64
#define PW  36
__global__ __launch_bounds__(256) void attn_bf16(
    const __nv_bfloat16* __restrict__ q, const __nv_bfloat16* __restrict__ k,
    const __nv_bfloat16* __restrict__ v,
    const float* __restrict__ Fcv, const float* __restrict__ av, const float* __restrict__ mv,
    const float* __restrict__ wcol, const float* __restrict__ amaxT,
    const float* __restrict__ mq,
    const float* __restrict__ xc, const float* __restrict__ up,
    const float* __restrict__ gng, const float* __restrict__ gnb,
    const float* __restrict__ skip,
    __nv_bfloat16* __restrict__ out)
{
    extern __shared__ uint32_t smu[];
    uint32_t* Qs = smu;
    uint32_t* Ks = Qs + 64*QKW;
    uint32_t* Vs = Ks + 64*QKW;
    float* fct  = (float*)(Vs + 64*VW);
    float* mt   = fct + 64;
    float* as_  = mt + 64;
    float* den2 = as_ + 64;
    float* dsq  = den2 + 128;

    int bh = blockIdx.x; int b = bh>>2, hh = bh&3;
    int it = (int)(gridDim.y - 1) - (int)blockIdx.y;
    int t0 = it<<6;
    int tid = threadIdx.x, lane = tid&31, wid = tid>>5;
    int wm = wid>>1, wn = wid&1;
    int ls = lane>>2, lk = lane&3;
    int g8 = lane>>3, lr = lane&7;
    const float scale = 0.08838834764831845f;

    const __nv_bfloat16* qg = q + ((size_t)(b*SEQ + t0))*512 + hh*128;
    #pragma unroll
    for (int r=0;r<4;r++){
        int idx = tid + (r<<8);
        int row = idx>>4, c16 = idx&15;
        uint4 val = *(const uint4*)(qg + (size_t)row*512 + (c16<<3));
        *(uint4*)&Qs[row*QKW + (c16<<2)] = val;
    }
    if (tid < 64){ int tg = bh*SEQ + t0 + tid; fct[tid] = Fcv[tg]; mt[tid] = mv[tg]; }
    __syncthreads();

    uint32_t qf[8][4];
    int r0 = wm*16 + ls, r1 = r0 + 8;
    #pragma unroll
    for (int ks=0; ks<8; ks++){
        qf[ks][0] = Qs[r0*QKW + ks*8 + lk];
        qf[ks][1] = Qs[r1*QKW + ks*8 + lk];
        qf[ks][2] = Qs[r0*QKW + ks*8 + lk + 4];
        qf[ks][3] = Qs[r1*QKW + ks*8 + lk + 4];
    }

    float oacc[8][4];
    #pragma unroll
    for (int i=0;i<8;i++){ oacc[i][0]=0.f; oacc[i][1]=0.f; oacc[i][2]=0.f; oacc[i][3]=0.f; }
    float den0 = 0.f, den1 = 0.f;
    float mqv = mq[bh*16 + it];

    for (int js=0; js<=it; js++){
        bool diag = (js == it);
        // rigorous decay bound: every element weight <= exp(mqv + amaxT[js]) * scale
        if (!diag && mqv + amaxT[bh*16 + js] < -30.f) continue;
        int s0 = js<<6;
        __syncthreads();
        const __nv_bfloat16* kg = k + ((size_t)(b*SEQ + s0))*512 + hh*128;
        const __nv_bfloat16* vg = v + ((size_t)(b*SEQ + s0))*512 + hh*128;
        #pragma unroll
        for (int r=0;r<4;r++){
            int idx = tid + (r<<8);
            int row = idx>>4, c16 = idx&15;
            uint4 kv = *(const uint4*)(kg + (size_t)row*512 + (c16<<3));
            uint4 vv = *(const uint4*)(vg + (size_t)row*512 + (c16<<3));
            *(uint4*)&Ks[row*QKW + (c16<<2)] = kv;
            *(uint4*)&Vs[row*VW + ((c16 ^ (row&7))<<2)] = vv;
        }
        if (tid < 64)
            as_[tid] = diag ? av[bh*SEQ + s0 + tid] : wcol[bh*SEQ + s0 + tid];
        __syncthreads();

        float sacc[4][4] = {};
        #pragma unroll
        for (int ks=0; ks<8; ks++){
            #pragma unroll
            for (int nt=0; nt<4; nt++){
                int sc = wn*32 + nt*8 + ls;
                uint32_t b0 = Ks[sc*QKW + ks*8 + lk];
                uint32_t b1 = Ks[sc*QKW + ks*8 + lk + 4];
                mma_bf16(sacc[nt], qf[ks], b0, b1);
            }
        }

        float f0 = fct[r0], mm0 = mt[r0], f1 = fct[r1], mm1 = mt[r1];
        if (!diag){
            float amx = amaxT[bh*16 + js];
            float w0 = __expf(f0 - mm0 + amx);
            float w1 = __expf(f1 - mm1 + amx);
            #pragma unroll
            for (int nt=0; nt<4; nt++){
                int c0 = wn*32 + nt*8 + (lk<<1);
                float wc0 = as_[c0], wc1 = as_[c0+1];
                float v00 = sacc[nt][0]*w0*wc0;
                float v01 = sacc[nt][1]*w0*wc1;
                float v10 = sacc[nt][2]*w1*wc0;
                float v11 = sacc[nt][3]*w1*wc1;
                den0 += v00 + v01;
                den1 += v10 + v11;
                int wcl = wn*16 + nt*4 + lk;
                Qs[r0*PW + wcl] = bf2pack(v00, v01);
                Qs[r1*PW + wcl] = bf2pack(v10, v11);
            }
        } else {
            #pragma unroll
            for (int nt=0; nt<4; nt++){
                int c0 = wn*32 + nt*8 + (lk<<1);
                int c1 = c0 + 1;
                float a0v = as_[c0], a1v = as_[c1];
                float v00 = sacc[nt][0]*scale*__expf(f0 + a0v - mm0);
                float v01 = sacc[nt][1]*scale*__expf(f0 + a1v - mm0);
                float v10 = sacc[nt][2]*scale*__expf(f1 + a0v - mm1);
                float v11 = sacc[nt][3]*scale*__expf(f1 + a1v - mm1);
                if (c0 > r0) v00 = 0.f;
                if (c1 > r0) v01 = 0.f;
                if (c0 > r1) v10 = 0.f;
                if (c1 > r1) v11 = 0.f;
                den0 += v00 + v01;
                den1 += v10 + v11;
                int wcl = wn*16 + nt*4 + lk;
                Qs[r0*PW + wcl] = bf2pack(v00, v01);
                Qs[r1*PW + wcl] = bf2pack(v10, v11);
            }
        }
        __syncthreads();

        #pragma unroll
        for (int ks2=0; ks2<4; ks2++){
            uint32_t af[4];
            af[0] = Qs[r0*PW + ks2*8 + lk];
            af[1] = Qs[r1*PW + ks2*8 + lk];
            af[2] = Qs[r0*PW + ks2*8 + lk + 4];
            af[3] = Qs[r1*PW + ks2*8 + lk + 4];
            int krow = (ks2<<4) + lr + ((g8&1)<<3);
            #pragma unroll
            for (int nt=0; nt<8; nt++){
                int cd = wn*8 + nt;
                uint32_t addr = smaddr(&Vs[krow*VW + ((cd ^ (krow&7))<<2)]);
                uint32_t b0, b1;
                asm volatile("ldmatrix.sync.aligned.m8n8.x2.trans.shared.b16 {%0,%1}, [%2];\n"
                    : "=r"(b0),"=r"(b1) : "r"(addr));
                mma_bf16(oacc[nt], af, b0, b1);
            }
        }
    }

    den0 += __shfl_xor_sync(0xffffffffu, den0, 1);
    den0 += __shfl_xor_sync(0xffffffffu, den0, 2);
    den1 += __shfl_xor_sync(0xffffffffu, den1, 1);
    den1 += __shfl_xor_sync(0xffffffffu, den1, 2);
    __syncthreads();
    if (lk == 0){ den2[wn*64 + r0] = den0; den2[wn*64 + r1] = den1; }
    __syncthreads();
    float dt0 = den2[r0] + den2[64 + r0];
    float dt1 = den2[r1] + den2[64 + r1];
    float inv0 = 1.f / (fmaxf(fabsf(dt0), __expf(-mt[r0])) + 1e-6f);
    float inv1 = 1.f / (fmaxf(fabsf(dt1), __expf(-mt[r1])) + 1e-6f);

    float hv0[16], hv1[16];
    #pragma unroll
    for (int nt=0; nt<8; nt++){
        hv0[nt*2]   = oacc[nt][0]*inv0;
        hv0[nt*2+1] = oacc[nt][1]*inv0;
        hv1[nt*2]   = oacc[nt][2]*inv1;
        hv1[nt*2+1] = oacc[nt][3]*inv1;
    }

    float s0 = 0.f, s1 = 0.f, q0 = 0.f, q1 = 0.f;
    #pragma unroll
    for (int i=0;i<16;i++){
        s0 += hv0[i]; q0 += hv0[i]*hv0[i];
        s1 += hv1[i]; q1 += hv1[i]*hv1[i];
    }
    #pragma unroll
    for (int o=1;o<4;o<<=1){
        s0 += __shfl_xor_sync(0xffffffffu, s0, o);
        q0 += __shfl_xor_sync(0xffffffffu, q0, o);
        s1 += __shfl_xor_sync(0xffffffffu, s1, o);
        q1 += __shfl_xor_sync(0xffffffffu, q1, o);
    }
    __syncthreads();
    if (lk == 0){
        den2[wn*64 + r0] = s0; den2[wn*64 + r1] = s1;
        dsq[wn*64 + r0]  = q0; dsq[wn*64 + r1]  = q1;
    }
    __syncthreads();
    float mu0 = (den2[r0] + den2[64 + r0]) * (1.f/128.f);
    float mu1 = (den2[r1] + den2[64 + r1]) * (1.f/128.f);
    float e20 = (dsq[r0] + dsq[64 + r0]) * (1.f/128.f);
    float e21 = (dsq[r1] + dsq[64 + r1]) * (1.f/128.f);
    float is0 = rsqrtf(e20 - mu0*mu0 + 1e-5f);
    float is1 = rsqrtf(e21 - mu1*mu1 + 1e-5f);

    size_t tok0 = (size_t)(b*SEQ + t0 + r0), tok1 = (size_t)(b*SEQ + t0 + r1);
    #pragma unroll
    for (int nt=0; nt<8; nt++){
        int dc = wn*64 + nt*8 + (lk<<1);
        int c = hh*128 + dc;
        float2 gg = *(const float2*)&gng[c];
        float2 gb = *(const float2*)&gnb[c];
        float2 sk = *(const float2*)&skip[c];
        float2 x0 = *(const float2*)&xc[tok0*512 + c];
        float2 x1 = *(const float2*)&xc[tok1*512 + c];
        float2 z0 = *(const float2*)&up[tok0*1024 + 512 + c];
        float2 z1 = *(const float2*)&up[tok1*1024 + 512 + c];
        float y00 = (hv0[nt*2]  -mu0)*is0*gg.x + gb.x + sk.x*x0.x;
        float y01 = (hv0[nt*2+1]-mu0)*is0*gg.y + gb.y + sk.y*x0.y;
        float y10 = (hv1[nt*2]  -mu1)*is1*gg.x + gb.x + sk.x*x1.x;
        float y11 = (hv1[nt*2+1]-mu1)*is1*gg.y + gb.y + sk.y*x1.y;
        y00 *= z0.x / (1.f + expf(-z0.x));
        y01 *= z0.y / (1.f + expf(-z0.y));
        y10 *= z1.x / (1.f + expf(-z1.x));
        y11 *= z1.y / (1.f + expf(-z1.y));
        *(__nv_bfloat162*)&out[tok0*512 + c] = __floats2bfloat162_rn(y00, y01);
        *(__nv_bfloat162*)&out[tok1*512 + c] = __floats2bfloat162_rn(y10, y11);
    }
}

// ---------------- final ----------------
__global__ void final_kernel(const float* __restrict__ h, const float* __restrict__ g,
                             const float* __restrict__ b, const float* __restrict__ Wf,
                             const float* __restrict__ bf, float* __restrict__ out){
    __shared__ float sh[8];
    __shared__ float sv;
    int bb = blockIdx.x, tid = threadIdx.x;
    float vv = h[((size_t)(bb*SEQ + SEQ-1))*256 + tid];
    float s = warp_sum(vv);
    if (!(tid&31)) sh[tid>>5] = s;
    __syncthreads();
    if (tid==0){ float t=0; for(int i=0;i<8;i++) t+=sh[i]; sv = t*(1.f/256.f); }
    __syncthreads();
    float mu = sv;
    float d = vv - mu;
    float s2 = warp_sum(d*d);
    if (!(tid&31)) sh[tid>>5] = s2;
    __syncthreads();
    if (tid==0){ float t=0; for(int i=0;i<8;i++) t+=sh[i]; sv = t*(1.f/256.f); }
    __syncthreads();
    float yn = d*rsqrtf(sv + 1e-5f)*g[tid] + b[tid];
    float p = yn * Wf[tid];
    float s3 = warp_sum(p);
    __syncthreads();
    if (!(tid&31)) sh[tid>>5] = s3;
    __syncthreads();
    if (tid==0){ float t=0; for(int i=0;i<8;i++) t+=sh[i]; out[bb] = t + bf[0]; }
}

// ---------------- launch ----------------
extern "C" void kernel_launch(void* const* d_in, const int* in_sizes, int n_in,
                              void* d_out, int out_size){
    const float* x    = (const float*)d_in[0];
    const float* tf   = (const float*)d_in[1];
    const float* Wp   = (const float*)d_in[2];
    const float* bp   = (const float*)d_in[3];
    const float* ln_g = (const float*)d_in[4];
    const float* ln_b = (const float*)d_in[5];
    const float* Wup  = (const float*)d_in[6];
    const float* bup  = (const float*)d_in[7];
    const float* cw   = (const float*)d_in[8];
    const float* cb   = (const float*)d_in[9];
    const float* Wq   = (const float*)d_in[10];
    const float* Wk   = (const float*)d_in[11];
    const float* Wv   = (const float*)d_in[12];
    const float* Wif  = (const float*)d_in[13];
    const float* bif  = (const float*)d_in[14];
    const float* gng  = (const float*)d_in[15];
    const float* gnb  = (const float*)d_in[16];
    const float* skip = (const float*)d_in[17];
    const float* Wdn  = (const float*)d_in[18];
    const float* bdn  = (const float*)d_in[19];
    const float* lnfg = (const float*)d_in[20];
    const float* lnfb = (const float*)d_in[21];
    const float* Wf   = (const float*)d_in[22];
    const float* bf   = (const float*)d_in[23];

    float *h,*up,*xc,*giT,*gfT,*Fc,*a,*m,*wcol,*amaxT,*mqp,*Wg;
    __nv_bfloat16 *hnbf,*xcbf,*upbf,*qbf,*kbf,*vbf,*att2bf,*wupbf,*wqbf,*wkbf,*wvbf,*wdnbf;
    cudaGetSymbolAddress((void**)&h,    g_h);
    cudaGetSymbolAddress((void**)&up,   g_up);
    cudaGetSymbolAddress((void**)&xc,   g_xc);
    cudaGetSymbolAddress((void**)&giT,  g_giT);
    cudaGetSymbolAddress((void**)&gfT,  g_gfT);
    cudaGetSymbolAddress((void**)&Fc,   g_Fc);
    cudaGetSymbolAddress((void**)&a,    g_a);
    cudaGetSymbolAddress((void**)&m,    g_m);
    cudaGetSymbolAddress((void**)&wcol, g_wcol);
    cudaGetSymbolAddress((void**)&amaxT,g_amaxT);
    cudaGetSymbolAddress((void**)&mqp,  g_mq);
    cudaGetSymbolAddress((void**)&Wg,   g_Wg);
    cudaGetSymbolAddress((void**)&hnbf, g_hn_bf);
    cudaGetSymbolAddress((void**)&xcbf, g_xc_bf);
    cudaGetSymbolAddress((void**)&upbf, g_up_bf);
    cudaGetSymbolAddress((void**)&qbf,  g_q_bf);
    cudaGetSymbolAddress((void**)&kbf,  g_k_bf);
    cudaGetSymbolAddress((void**)&vbf,  g_v_bf);
    cudaGetSymbolAddress((void**)&att2bf, g_att2_bf);
    cudaGetSymbolAddress((void**)&wupbf, g_wup_bf);
    cudaGetSymbolAddress((void**)&wqbf,  g_wq_bf);
    cudaGetSymbolAddress((void**)&wkbf,  g_wk_bf);
    cudaGetSymbolAddress((void**)&wvbf,  g_wv_bf);
    cudaGetSymbolAddress((void**)&wdnbf, g_wdn_bf);

    int attn_smem = (64*QKW + 64*QKW + 64*VW + 64 + 64 + 64 + 128 + 128) * 4;
    int gemm_smem = 65536;
    int gemm64_smem = 49152;
    static int attr_set = 0;
    if (!attr_set){
        cudaFuncSetAttribute(attn_bf16, cudaFuncAttributeMaxDynamicSharedMemorySize, attn_smem);
        cudaFuncSetAttribute(gemm_bf16, cudaFuncAttributeMaxDynamicSharedMemorySize, gemm_smem);
        cudaFuncSetAttribute(gemm_bf16_m64, cudaFuncAttributeMaxDynamicSharedMemorySize, gemm64_smem);
        attr_set = 1;
    }

    int n0 = NL*DMODEL*1024, n1 = NL*DI*DI, n4 = NL*DI*DMODEL;
    int ntot = n0 + 3*n1 + n4;
    f2bf5_kernel<<<(ntot/2 + 255)/256, 256>>>(Wup, wupbf, n0,
                                              Wq, wqbf, n1,
                                              Wk, wkbf, n1,
                                              Wv, wvbf, n1,
                                              Wdn, wdnbf, n4);
    gatew_kernel<<<NL*1024*8/256, 256>>>(Wq, Wk, Wv, Wif, Wg);

    embed_kernel<<<TOK*256/256, 256>>>(x, tf, Wp, bp, h);

    for (int l=0; l<NL; l++){
        ln_kernel<<<TOK/8, 256>>>(h, ln_g + l*256, ln_b + l*256, hnbf);
        gemm_bf16<<<dim3(1024/128, TOK/128, 1), 256, gemm_smem>>>(
            hnbf, 256, wupbf + (size_t)l*256*1024, 1024,
            up, 1024, bup + l*1024, nullptr, 256,
            upbf, 512, nullptr, nullptr, nullptr, nullptr, nullptr);
        conv_gates8_kernel<<<TOK/8, 256>>>(up, cw + l*4*512, cb + l*512,
                                           Wg + (size_t)l*8192, bif + l*8,
                                           xc, xcbf, giT, gfT);
        gemm_bf16<<<dim3(512/128, TOK/128, 3), 256, gemm_smem>>>(
            xcbf, 512, wqbf + (size_t)l*512*512, 512,
            nullptr, 512, nullptr, nullptr, 512, qbf, 512,
            upbf,
            wkbf + (size_t)l*512*512, kbf,
            wvbf + (size_t)l*512*512, vbf);
        scan_kernel4<<<32, 32>>>(giT, gfT, Fc, a, m, wcol, amaxT, mqp);
        attn_bf16<<<dim3(BATCH*NH, SEQ/64), 256, attn_smem>>>(qbf, kbf, vbf, Fc, a, m,
                                                  wcol, amaxT, mqp,
                                                  xc, up, gng + l*512, gnb + l*512, skip + l*512,
                                                  att2bf);
        gemm_bf16_m64<<<dim3(256/128, TOK/64, 1), 256, gemm64_smem>>>(
            att2bf, 512, wdnbf + (size_t)l*512*256, 256,
            h, 256, bdn + l*256, h, 512);
    }
    final_kernel<<<BATCH, 256>>>(h, lnfg, lnfb, Wf, bf, (float*)d_out);
}

// round 16
// speedup vs baseline: 1.4501x; 1.0092x over previous
#include <cuda_runtime.h>
#include <cuda_bf16.h>
#include <cstdint>
#include <cstddef>

#define SEQ 1024
#define BATCH 8
#define TOK (BATCH*SEQ)
#define DMODEL 256
#define DI 512
#define NH 4
#define DHH 128
#define NL 4

// ---------------- scratch (device globals; no allocation allowed) ----------------
__device__ float g_h[TOK*DMODEL];
__device__ float g_up[TOK*1024];
__device__ float g_giT[BATCH*NH*SEQ];
__device__ float g_gfT[BATCH*NH*SEQ];
__device__ float g_Fc[BATCH*NH*SEQ];
__device__ float g_a[BATCH*NH*SEQ];
__device__ float g_m[BATCH*NH*SEQ];
__device__ float g_wcol[BATCH*NH*SEQ];
__device__ float g_amaxT[BATCH*NH*16];
__device__ float g_mq[BATCH*NH*16];
__device__ float g_Wg[NL*1024*8];

__device__ __nv_bfloat16 g_hn_bf[TOK*DMODEL];
__device__ __nv_bfloat16 g_xc_bf[TOK*DI];
__device__ __nv_bfloat16 g_up_bf[TOK*DI];
__device__ __nv_bfloat16 g_upz_bf[TOK*DI];
__device__ __nv_bfloat16 g_q_bf[TOK*DI];
__device__ __nv_bfloat16 g_k_bf[TOK*DI];
__device__ __nv_bfloat16 g_v_bf[TOK*DI];
__device__ __nv_bfloat16 g_att2_bf[TOK*DI];
__device__ __nv_bfloat16 g_wup_bf[NL*DMODEL*1024];
__device__ __nv_bfloat16 g_wq_bf[NL*DI*DI];
__device__ __nv_bfloat16 g_wk_bf[NL*DI*DI];
__device__ __nv_bfloat16 g_wv_bf[NL*DI*DI];
__device__ __nv_bfloat16 g_wdn_bf[NL*DI*DMODEL];

__device__ __forceinline__ float warp_sum(float v){
    #pragma unroll
    for (int o=16;o;o>>=1) v += __shfl_xor_sync(0xffffffffu, v, o);
    return v;
}

__device__ __forceinline__ uint32_t bf2pack(float x, float y){
    __nv_bfloat162 t = __floats2bfloat162_rn(x, y);
    return *(uint32_t*)&t;
}

__device__ __forceinline__ void mma_bf16(float* c, const uint32_t* a, uint32_t b0, uint32_t b1){
    asm volatile(
      "mma.sync.aligned.m16n8k16.row.col.f32.bf16.bf16.f32 "
      "{%0,%1,%2,%3}, {%4,%5,%6,%7}, {%8,%9}, {%0,%1,%2,%3};\n"
      : "+f"(c[0]), "+f"(c[1]), "+f"(c[2]), "+f"(c[3])
      : "r"(a[0]), "r"(a[1]), "r"(a[2]), "r"(a[3]), "r"(b0), "r"(b1));
}

__device__ __forceinline__ uint32_t smaddr(const void* p){
    return (uint32_t)__cvta_generic_to_shared(p);
}
#define CPA16(dst,src) asm volatile("cp.async.cg.shared.global [%0], [%1], 16;\n"::"r"(dst),"l"(src))
#define CPCOMMIT() asm volatile("cp.async.commit_group;\n")
#define CPWAIT(n) asm volatile("cp.async.wait_group %0;\n"::"n"(n))

// ---------------- merged f32 -> bf16 convert for all 5 weight tensors ----------------
__global__ void f2bf5_kernel(const float* __restrict__ i0, __nv_bfloat16* __restrict__ o0, int n0,
                             const float* __restrict__ i1, __nv_bfloat16* __restrict__ o1, int n1,
                             const float* __restrict__ i2, __nv_bfloat16* __restrict__ o2, int n2,
                             const float* __restrict__ i3, __nv_bfloat16* __restrict__ o3, int n3,
                             const float* __restrict__ i4, __nv_bfloat16* __restrict__ o4, int n4){
    int i = (blockIdx.x*blockDim.x + threadIdx.x)*2;
    const float* in; __nv_bfloat16* out;
    if (i < n0){ in=i0; out=o0; }
    else if ((i-=n0) < n1){ in=i1; out=o1; }
    else if ((i-=n1) < n2){ in=i2; out=o2; }
    else if ((i-=n2) < n3){ in=i3; out=o3; }
    else if ((i-=n3) < n4){ in=i4; out=o4; }
    else return;
    float2 v = *(const float2*)(in+i);
    *(__nv_bfloat162*)(out+i) = __floats2bfloat162_rn(v.x, v.y);
}

// ---------------- composite gate weights ----------------
__global__ void gatew_kernel(const float* __restrict__ Wq, const float* __restrict__ Wk,
                             const float* __restrict__ Wv, const float* __restrict__ Wif,
                             float* __restrict__ Wg){
    int idx = blockIdx.x*blockDim.x + threadIdx.x;
    int l = idx >> 13; int r = idx & 8191;
    int c = r >> 3; int j = r & 7;
    const float* Wifl = Wif + (size_t)l*1536*8;
    float acc = 0.f;
    if (c < 512){
        const float* wq = Wq + ((size_t)l*512 + c)*512;
        const float* wk = Wk + ((size_t)l*512 + c)*512;
        #pragma unroll 4
        for (int i=0;i<512;i++)
            acc += wq[i]*Wifl[i*8+j] + wk[i]*Wifl[(512+i)*8+j];
    } else {
        const float* wv = Wv + ((size_t)l*512 + (c-512))*512;
        #pragma unroll 4
        for (int i=0;i<512;i++)
            acc += wv[i]*Wifl[(1024+i)*8+j];
    }
    Wg[(size_t)l*8192 + c*8 + j] = acc;
}

// ---------------- embed ----------------
__global__ void embed_kernel(const float* __restrict__ x, const float* __restrict__ tf,
                             const float* __restrict__ Wp, const float* __restrict__ bp,
                             float* __restrict__ h){
    int idx = blockIdx.x*blockDim.x + threadIdx.x;
    int j = idx & 255; int tok = idx >> 8;
    float acc = bp[j] + x[tok]*Wp[j];
    #pragma unroll
    for (int f=0; f<4; f++) acc += tf[tok*4+f]*Wp[(1+f)*256+j];
    h[idx] = acc;
}

// ---------------- layernorm, bf16 out ----------------
__global__ void ln_kernel(const float* __restrict__ x, const float* __restrict__ g,
                          const float* __restrict__ b, __nv_bfloat16* __restrict__ y){
    int row = blockIdx.x*8 + (threadIdx.x>>5);
    int lane = threadIdx.x & 31;
    const float* xr = x + (size_t)row*256;
    float4 v0 = *(const float4*)(xr + lane*4);
    float4 v1 = *(const float4*)(xr + 128 + lane*4);
    float s  = v0.x+v0.y+v0.z+v0.w + v1.x+v1.y+v1.z+v1.w;
    float sq = v0.x*v0.x+v0.y*v0.y+v0.z*v0.z+v0.w*v0.w
             + v1.x*v1.x+v1.y*v1.y+v1.z*v1.z+v1.w*v1.w;
    #pragma unroll
    for (int o=16;o;o>>=1){
        s  += __shfl_xor_sync(0xffffffffu, s,  o);
        sq += __shfl_xor_sync(0xffffffffu, sq, o);
    }
    float mu = s * (1.f/256.f);
    float var = sq * (1.f/256.f) - mu*mu;
    float is = rsqrtf(var + 1e-5f);
    float4 g0 = *(const float4*)(g + lane*4);
    float4 g1 = *(const float4*)(g + 128 + lane*4);
    float4 b0 = *(const float4*)(b + lane*4);
    float4 b1 = *(const float4*)(b + 128 + lane*4);
    __nv_bfloat16* yr = y + (size_t)row*256;
    *(__nv_bfloat162*)&yr[lane*4]       = __floats2bfloat162_rn((v0.x-mu)*is*g0.x + b0.x, (v0.y-mu)*is*g0.y + b0.y);
    *(__nv_bfloat162*)&yr[lane*4+2]     = __floats2bfloat162_rn((v0.z-mu)*is*g0.z + b0.z, (v0.w-mu)*is*g0.w + b0.w);
    *(__nv_bfloat162*)&yr[128+lane*4]   = __floats2bfloat162_rn((v1.x-mu)*is*g1.x + b1.x, (v1.y-mu)*is*g1.y + b1.y);
    *(__nv_bfloat162*)&yr[128+lane*4+2] = __floats2bfloat162_rn((v1.z-mu)*is*g1.z + b1.z, (v1.w-mu)*is*g1.w + b1.w);
}

// ---------------- bf16 tensor-core GEMM: CTA 128x128x64, 8 warps 2x4 ----------------
// fp32 C written only for col < cfpcap; Cbfz gets cols >= 512 as bf16 (stride 512).
__global__ __launch_bounds__(256, 2) void gemm_bf16(
    const __nv_bfloat16* __restrict__ A, int lda,
    const __nv_bfloat16* __restrict__ B, int ldb,
    float* __restrict__ C, int ldc,
    const float* __restrict__ bias,
    const float* __restrict__ resid,
    int K,
    __nv_bfloat16* __restrict__ Cbf, int bfcap,
    const __nv_bfloat16* __restrict__ A2,
    const __nv_bfloat16* __restrict__ B2,
    __nv_bfloat16* __restrict__ Cbf2,
    const __nv_bfloat16* __restrict__ B3,
    __nv_bfloat16* __restrict__ Cbf3,
    __nv_bfloat16* __restrict__ Cbfz,
    int cfpcap)
{
    extern __shared__ __nv_bfloat16 sm[];
    __nv_bfloat16* As = sm;            // 2 x 128 x 64
    __nv_bfloat16* Bs = sm + 16384;    // 2 bufs x 2 halves x 64 x 64
    if (blockIdx.z == 1){ B = B2; Cbf = Cbf2; }
    else if (blockIdx.z == 2){ A = A2; B = B3; Cbf = Cbf3; }
    int tid = threadIdx.x, lane = tid&31, wid = tid>>5;
    int wm = wid>>2, wn = wid&3;
    int m0 = blockIdx.y*128, n0 = blockIdx.x*128;

    int ar = tid >> 1;
    int ac0 = (tid & 1) << 2;
    int br = tid >> 2;
    int bc0 = (tid & 3) << 1;
    const __nv_bfloat16* Ag = A + (size_t)(m0+ar)*lda;
    const __nv_bfloat16* Bg = B + (size_t)br*ldb + n0;

    int KC = K >> 6;
    {
        #pragma unroll
        for (int c=0;c<4;c++){
            int ch = ac0+c;
            CPA16(smaddr(&As[ar*64 + ((ch ^ (ar&7))<<3)]), Ag + (ch<<3));
        }
        #pragma unroll
        for (int hf=0; hf<2; hf++)
          #pragma unroll
          for (int c=0;c<2;c++){
            int ch = bc0+c;
            CPA16(smaddr(&Bs[hf*4096 + br*64 + ((ch ^ (br&7))<<3)]), Bg + hf*64 + (ch<<3));
        }
        CPCOMMIT();
    }

    float acc[4][4][4] = {};
    int g = lane>>3, lr = lane&7;
    int bhalf = wn>>1, bco = (wn&1)<<2;

    for (int kc=0; kc<KC; kc++){
        int cur = kc & 1;
        if (kc+1 < KC){
            int nb = (kc+1)&1, k0 = (kc+1)<<6;
            #pragma unroll
            for (int c=0;c<4;c++){
                int ch = ac0+c;
                CPA16(smaddr(&As[nb*8192 + ar*64 + ((ch ^ (ar&7))<<3)]), Ag + k0 + (ch<<3));
            }
            #pragma unroll
            for (int hf=0; hf<2; hf++)
              #pragma unroll
              for (int c=0;c<2;c++){
                int ch = bc0+c;
                CPA16(smaddr(&Bs[nb*8192 + hf*4096 + br*64 + ((ch ^ (br&7))<<3)]),
                      Bg + (size_t)k0*ldb + hf*64 + (ch<<3));
            }
            CPCOMMIT();
            CPWAIT(1);
        } else {
            CPWAIT(0);
        }
        __syncthreads();

        const __nv_bfloat16* Ab = As + cur*8192;
        const __nv_bfloat16* Bb = Bs + cur*8192 + bhalf*4096;
        #pragma unroll
        for (int ks=0; ks<4; ks++){
            uint32_t af[4][4];
            #pragma unroll
            for (int mt=0; mt<4; mt++){
                int arow = wm*64 + mt*16 + lr + ((g&1)<<3);
                int ch = (ks<<1) + (g>>1);
                uint32_t addr = smaddr(&Ab[arow*64 + ((ch ^ (arow&7))<<3)]);
                asm volatile("ldmatrix.sync.aligned.m8n8.x4.shared.b16 {%0,%1,%2,%3}, [%4];\n"
                    : "=r"(af[mt][0]),"=r"(af[mt][1]),"=r"(af[mt][2]),"=r"(af[mt][3]) : "r"(addr));
            }
            uint32_t bf[4][2];
            int krow = (ks<<4) + lr + ((g&1)<<3);
            #pragma unroll
            for (int nt=0; nt<4; nt++){
                int ch = bco + nt;
                uint32_t addr = smaddr(&Bb[krow*64 + ((ch ^ (krow&7))<<3)]);
                asm volatile("ldmatrix.sync.aligned.m8n8.x2.trans.shared.b16 {%0,%1}, [%2];\n"
                    : "=r"(bf[nt][0]),"=r"(bf[nt][1]) : "r"(addr));
            }
            #pragma unroll
            for (int mt=0;mt<4;mt++)
              #pragma unroll
              for (int nt=0;nt<4;nt++)
                mma_bf16(acc[mt][nt], af[mt], bf[nt][0], bf[nt][1]);
        }
        __syncthreads();
    }

    #pragma unroll
    for (int mt=0;mt<4;mt++){
        #pragma unroll
        for (int nt=0;nt<4;nt++){
            int row0 = m0 + wm*64 + mt*16 + (lane>>2);
            int col  = n0 + wn*32 + nt*8 + ((lane&3)<<1);
            float bx=0.f, by=0.f;
            if (bias){ bx = bias[col]; by = bias[col+1]; }
            float2 r0v = make_float2(0.f,0.f), r1v = make_float2(0.f,0.f);
            if (resid){
                r0v = *(const float2*)&resid[(size_t)row0*ldc + col];
                r1v = *(const float2*)&resid[(size_t)(row0+8)*ldc + col];
            }
            float v00 = acc[mt][nt][0]+bx+r0v.x, v01 = acc[mt][nt][1]+by+r0v.y;
            float v10 = acc[mt][nt][2]+bx+r1v.x, v11 = acc[mt][nt][3]+by+r1v.y;
            if (C && col < cfpcap){
                *(float2*)&C[(size_t)row0*ldc + col]     = make_float2(v00, v01);
                *(float2*)&C[(size_t)(row0+8)*ldc + col] = make_float2(v10, v11);
            }
            if (Cbf && col < bfcap){
                *(__nv_bfloat162*)&Cbf[(size_t)row0*bfcap + col]     = __floats2bfloat162_rn(v00, v01);
                *(__nv_bfloat162*)&Cbf[(size_t)(row0+8)*bfcap + col] = __floats2bfloat162_rn(v10, v11);
            }
            if (Cbfz && col >= 512){
                int zc = col - 512;
                *(__nv_bfloat162*)&Cbfz[(size_t)row0*512 + zc]     = __floats2bfloat162_rn(v00, v01);
                *(__nv_bfloat162*)&Cbfz[(size_t)(row0+8)*512 + zc] = __floats2bfloat162_rn(v10, v11);
            }
        }
    }
}

// ---------------- bf16 GEMM, CTA 64x128x64 (down-GEMM; better grid fill) ----------------
__global__ __launch_bounds__(256, 2) void gemm_bf16_m64(
    const __nv_bfloat16* __restrict__ A, int lda,
    const __nv_bfloat16* __restrict__ B, int ldb,
    float* __restrict__ C, int ldc,
    const float* __restrict__ bias,
    const float* __restrict__ resid,
    int K)
{
    extern __shared__ __nv_bfloat16 sm[];
    __nv_bfloat16* As = sm;            // 2 x 64 x 64
    __nv_bfloat16* Bs = sm + 8192;     // 2 bufs x 2 halves x 64 x 64
    int tid = threadIdx.x, lane = tid&31, wid = tid>>5;
    int wm = wid>>2, wn = wid&3;
    int m0 = blockIdx.y*64, n0 = blockIdx.x*128;

    int ar = tid >> 2;
    int ac0 = (tid & 3) << 1;
    const __nv_bfloat16* Ag = A + (size_t)(m0+ar)*lda;
    const __nv_bfloat16* Bg = B + (size_t)ar*ldb + n0;

    int KC = K >> 6;
    {
        #pragma unroll
        for (int c=0;c<2;c++){
            int ch = ac0+c;
            CPA16(smaddr(&As[ar*64 + ((ch ^ (ar&7))<<3)]), Ag + (ch<<3));
        }
        #pragma unroll
        for (int hf=0; hf<2; hf++)
          #pragma unroll
          for (int c=0;c<2;c++){
            int ch = ac0+c;
            CPA16(smaddr(&Bs[hf*4096 + ar*64 + ((ch ^ (ar&7))<<3)]), Bg + hf*64 + (ch<<3));
        }
        CPCOMMIT();
    }

    float acc[2][4][4] = {};
    int g = lane>>3, lr = lane&7;
    int bhalf = wn>>1, bco = (wn&1)<<2;

    for (int kc=0; kc<KC; kc++){
        int cur = kc & 1;
        if (kc+1 < KC){
            int nb = (kc+1)&1, k0 = (kc+1)<<6;
            #pragma unroll
            for (int c=0;c<2;c++){
                int ch = ac0+c;
                CPA16(smaddr(&As[nb*4096 + ar*64 + ((ch ^ (ar&7))<<3)]), Ag + k0 + (ch<<3));
            }
            #pragma unroll
            for (int hf=0; hf<2; hf++)
              #pragma unroll
              for (int c=0;c<2;c++){
                int ch = ac0+c;
                CPA16(smaddr(&Bs[nb*8192 + hf*4096 + ar*64 + ((ch ^ (ar&7))<<3)]),
                      Bg + (size_t)k0*ldb + hf*64 + (ch<<3));
            }
            CPCOMMIT();
            CPWAIT(1);
        } else {
            CPWAIT(0);
        }
        __syncthreads();

        const __nv_bfloat16* Ab = As + cur*4096;
        const __nv_bfloat16* Bb = Bs + cur*8192 + bhalf*4096;
        #pragma unroll
        for (int ks=0; ks<4; ks++){
            uint32_t af[2][4];
            #pragma unroll
            for (int mt=0; mt<2; mt++){
                int arow = wm*32 + mt*16 + lr + ((g&1)<<3);
                int ch = (ks<<1) + (g>>1);
                uint32_t addr = smaddr(&Ab[arow*64 + ((ch ^ (arow&7))<<3)]);
                asm volatile("ldmatrix.sync.aligned.m8n8.x4.shared.b16 {%0,%1,%2,%3}, [%4];\n"
                    : "=r"(af[mt][0]),"=r"(af[mt][1]),"=r"(af[mt][2]),"=r"(af[mt][3]) : "r"(addr));
            }
            uint32_t bf[4][2];
            int krow = (ks<<4) + lr + ((g&1)<<3);
            #pragma unroll
            for (int nt=0; nt<4; nt++){
                int ch = bco + nt;
                uint32_t addr = smaddr(&Bb[krow*64 + ((ch ^ (krow&7))<<3)]);
                asm volatile("ldmatrix.sync.aligned.m8n8.x2.trans.shared.b16 {%0,%1}, [%2];\n"
                    : "=r"(bf[nt][0]),"=r"(bf[nt][1]) : "r"(addr));
            }
            #pragma unroll
            for (int mt=0;mt<2;mt++)
              #pragma unroll
              for (int nt=0;nt<4;nt++)
                mma_bf16(acc[mt][nt], af[mt], bf[nt][0], bf[nt][1]);
        }
        __syncthreads();
    }

    #pragma unroll
    for (int mt=0;mt<2;mt++){
        #pragma unroll
        for (int nt=0;nt<4;nt++){
            int row0 = m0 + wm*32 + mt*16 + (lane>>2);
            int col  = n0 + wn*32 + nt*8 + ((lane&3)<<1);
            float bx=0.f, by=0.f;
            if (bias){ bx = bias[col]; by = bias[col+1]; }
            float2 r0v = make_float2(0.f,0.f), r1v = make_float2(0.f,0.f);
            if (resid){
                r0v = *(const float2*)&resid[(size_t)row0*ldc + col];
                r1v = *(const float2*)&resid[(size_t)(row0+8)*ldc + col];
            }
            *(float2*)&C[(size_t)row0*ldc + col] =
                make_float2(acc[mt][nt][0]+bx+r0v.x, acc[mt][nt][1]+by+r0v.y);
            *(float2*)&C[(size_t)(row0+8)*ldc + col] =
                make_float2(acc[mt][nt][2]+bx+r1v.x, acc[mt][nt][3]+by+r1v.y);
        }
    }
}

// ---------------- fused causal conv + silu + composite gates, 8 tokens/block ----------------
__global__ __launch_bounds__(256) void conv_gates8_kernel(
    const float* __restrict__ up, const float* __restrict__ cw, const float* __restrict__ cb,
    const float* __restrict__ Wg, const float* __restrict__ bif,
    __nv_bfloat16* __restrict__ xcbf,
    float* __restrict__ giT, float* __restrict__ gfT)
{
    __shared__ float ups[11][512];
    __shared__ float xcs[8][512];
    int tok0 = blockIdx.x << 3;
    int t0 = tok0 & 1023;
    int tid = threadIdx.x;

    for (int idx = tid; idx < 11*512; idx += 256){
        int r = idx >> 9, c = idx & 511;
        int tt = t0 - 3 + r;
        float v = 0.f;
        if (tt >= 0) v = up[(size_t)(tok0 - 3 + r)*1024 + c];
        ups[r][c] = v;
    }
    __syncthreads();

    for (int idx = tid; idx < 8*512; idx += 256){
        int j = idx >> 9, c = idx & 511;
        float acc = cb[c]
                  + cw[c]*ups[j][c] + cw[512+c]*ups[j+1][c]
                  + cw[1024+c]*ups[j+2][c] + cw[1536+c]*ups[j+3][c];
        float sv = acc/(1.f+expf(-acc));
        xcs[j][c] = sv;
        xcbf[(size_t)(tok0+j)*512 + c] = __float2bfloat16(sv);
    }
    __syncthreads();

    int wj = tid>>5, lane = tid&31;
    float acc[8] = {};
    for (int i = lane; i < 512; i += 32){
        float xcv = xcs[wj][i];
        float xmv = ups[wj+3][i];
        float4 w0 = *(const float4*)&Wg[i*8];
        float4 w1 = *(const float4*)&Wg[i*8+4];
        float4 w2 = *(const float4*)&Wg[(512+i)*8];
        float4 w3 = *(const float4*)&Wg[(512+i)*8+4];
        acc[0] += xcv*w0.x + xmv*w2.x;
        acc[1] += xcv*w0.y + xmv*w2.y;
        acc[2] += xcv*w0.z + xmv*w2.z;
        acc[3] += xcv*w0.w + xmv*w2.w;
        acc[4] += xcv*w1.x + xmv*w3.x;
        acc[5] += xcv*w1.y + xmv*w3.y;
        acc[6] += xcv*w1.z + xmv*w3.z;
        acc[7] += xcv*w1.w + xmv*w3.w;
    }
    #pragma unroll
    for (int w=0;w<8;w++) acc[w] = warp_sum(acc[w]);
    if (!lane){
        int tok = tok0 + wj;
        int b = tok >> 10, s = tok & 1023;
        #pragma unroll
        for (int w=0;w<4;w++) giT[(size_t)(b*4+w)*1024 + s] = acc[w] + bif[w];
        #pragma unroll
        for (int w=4;w<8;w++) gfT[(size_t)(b*4+w-4)*1024 + s] = acc[w] + bif[w];
    }
}

// ---------------- gate scan + per-tile col weights + per-qtile row bound ----------------
__global__ void scan_kernel4(const float* __restrict__ giT, const float* __restrict__ gfT,
                             float* __restrict__ Fc, float* __restrict__ a, float* __restrict__ m,
                             float* __restrict__ wcol, float* __restrict__ amaxT,
                             float* __restrict__ mq){
    __shared__ float ash[1024];
    int bh = blockIdx.x, lane = threadIdx.x;
    const float* gih = giT + (size_t)bh*1024;
    const float* gfh = gfT + (size_t)bh*1024;
    const float scale = 0.08838834764831845f;
    float cfc = 0.f, cmax = -1e30f;
    float ipc = gih[lane], fpc = gfh[lane];
    for (int c=0;c<32;c++){
        float ip = ipc, fp = fpc;
        if (c+1 < 32){ ipc = gih[(c+1)*32+lane]; fpc = gfh[(c+1)*32+lane]; }
        float lf = fminf(fp, 0.f) - log1pf(expf(-fabsf(fp)));
        float x = lf;
        #pragma unroll
        for (int o=1;o<32;o<<=1){ float y = __shfl_up_sync(0xffffffffu, x, o); if (lane>=o) x += y; }
        float fc = cfc + x;
        float av = ip - fc;
        float mx = av;
        #pragma unroll
        for (int o=1;o<32;o<<=1){ float y = __shfl_up_sync(0xffffffffu, mx, o); if (lane>=o) mx = fmaxf(mx, y); }
        float cm = fmaxf(cmax, mx);
        int pos = c*32 + lane;
        int off = bh*SEQ + pos;
        Fc[off] = fc; a[off] = av; m[off] = fc + cm;
        if ((pos & 63) == 0) mq[bh*16 + (pos>>6)] = -cm;
        ash[pos] = av;
        cfc += __shfl_sync(0xffffffffu, x, 31);
        cmax = fmaxf(cmax, __shfl_sync(0xffffffffu, mx, 31));
    }
    __syncwarp();
    for (int tile=0;tile<16;tile++){
        float v0 = ash[tile*64 + lane];
        float v1 = ash[tile*64 + 32 + lane];
        float mx = fmaxf(v0, v1);
        #pragma unroll
        for (int o=16;o;o>>=1) mx = fmaxf(mx, __shfl_xor_sync(0xffffffffu, mx, o));
        if (lane == 0) amaxT[bh*16 + tile] = mx;
        wcol[bh*SEQ + tile*64 + lane]      = scale*__expf(v0 - mx);
        wcol[bh*SEQ + tile*64 + 32 + lane] = scale*__expf(v1 - mx);
    }
}

// ---------------- mLSTM attention + decay-bound tile skipping + fused epilogue ----------------
#define QKW 68
#define VW  64
#define PW  36
__global__ __launch_bounds__(256) void attn_bf16(
    const __nv_bfloat16* __restrict__ q, const __nv_bfloat16* __restrict__ k,
    const __nv_bfloat16* __restrict__ v,
    const float* __restrict__ Fcv, const float* __restrict__ av, const float* __restrict__ mv,
    const float* __restrict__ wcol, const float* __restrict__ amaxT,
    const float* __restrict__ mq,
    const __nv_bfloat16* __restrict__ xcbf, const __nv_bfloat16* __restrict__ upz,
    const float* __restrict__ gng, const float* __restrict__ gnb,
    const float* __restrict__ skip,
    __nv_bfloat16* __restrict__ out)
{
    extern __shared__ uint32_t smu[];
    uint32_t* Qs = smu;
    uint32_t* Ks = Qs + 64*QKW;
    uint32_t* Vs = Ks + 64*QKW;
    float* fct  = (float*)(Vs + 64*VW);
    float* mt   = fct + 64;
    float* as_  = mt + 64;
    float* den2 = as_ + 64;
    float* dsq  = den2 + 128;

    int bh = blockIdx.x; int b = bh>>2, hh = bh&3;
    int it = (int)(gridDim.y - 1) - (int)blockIdx.y;
    int t0 = it<<6;
    int tid = threadIdx.x, lane = tid&31, wid = tid>>5;
    int wm = wid>>1, wn = wid&1;
    int ls = lane>>2, lk = lane&3;
    int g8 = lane>>3, lr = lane&7;
    const float scale = 0.08838834764831845f;

    const __nv_bfloat16* qg = q + ((size_t)(b*SEQ + t0))*512 + hh*128;
    #pragma unroll
    for (int r=0;r<4;r++){
        int idx = tid + (r<<8);
        int row = idx>>4, c16 = idx&15;
        uint4 val = *(const uint4*)(qg + (size_t)row*512 + (c16<<3));
        *(uint4*)&Qs[row*QKW + (c16<<2)] = val;
    }
    if (tid < 64){ int tg = bh*SEQ + t0 + tid; fct[tid] = Fcv[tg]; mt[tid] = mv[tg]; }
    __syncthreads();

    uint32_t qf[8][4];
    int r0 = wm*16 + ls, r1 = r0 + 8;
    #pragma unroll
    for (int ks=0; ks<8; ks++){
        qf[ks][0] = Qs[r0*QKW + ks*8 + lk];
        qf[ks][1] = Qs[r1*QKW + ks*8 + lk];
        qf[ks][2] = Qs[r0*QKW + ks*8 + lk + 4];
        qf[ks][3] = Qs[r1*QKW + ks*8 + lk + 4];
    }

    float oacc[8][4];
    #pragma unroll
    for (int i=0;i<8;i++){ oacc[i][0]=0.f; oacc[i][1]=0.f; oacc[i][2]=0.f; oacc[i][3]=0.f; }
    float den0 = 0.f, den1 = 0.f;
    float mqv = mq[bh*16 + it];

    for (int js=0; js<=it; js++){
        bool diag = (js == it);
        // rigorous decay bound: every element weight <= exp(mqv + amaxT[js]) * scale
        if (!diag && mqv + amaxT[bh*16 + js] < -20.f) continue;
        int s0 = js<<6;
        __syncthreads();
        const __nv_bfloat16* kg = k + ((size_t)(b*SEQ + s0))*512 + hh*128;
        const __nv_bfloat16* vg = v + ((size_t)(b*SEQ + s0))*512 + hh*128;
        #pragma unroll
        for (int r=0;r<4;r++){
            int idx = tid + (r<<8);
            int row = idx>>4, c16 = idx&15;
            uint4 kv = *(const uint4*)(kg + (size_t)row*512 + (c16<<3));
            uint4 vv = *(const uint4*)(vg + (size_t)row*512 + (c16<<3));
            *(uint4*)&Ks[row*QKW + (c16<<2)] = kv;
            *(uint4*)&Vs[row*VW + ((c16 ^ (row&7))<<2)] = vv;
        }
        if (tid < 64)
            as_[tid] = diag ? av[bh*SEQ + s0 + tid] : wcol[bh*SEQ + s0 + tid];
        __syncthreads();

        float sacc[4][4] = {};
        #pragma unroll
        for (int ks=0; ks<8; ks++){
            #pragma unroll
            for (int nt=0; nt<4; nt++){
                int sc = wn*32 + nt*8 + ls;
                uint32_t b0 = Ks[sc*QKW + ks*8 + lk];
                uint32_t b1 = Ks[sc*QKW + ks*8 + lk + 4];
                mma_bf16(sacc[nt], qf[ks], b0, b1);
            }
        }

        float f0 = fct[r0], mm0 = mt[r0], f1 = fct[r1], mm1 = mt[r1];
        if (!diag){
            float amx = amaxT[bh*16 + js];
            float w0 = __expf(f0 - mm0 + amx);
            float w1 = __expf(f1 - mm1 + amx);
            #pragma unroll
            for (int nt=0; nt<4; nt++){
                int c0 = wn*32 + nt*8 + (lk<<1);
                float wc0 = as_[c0], wc1 = as_[c0+1];
                float v00 = sacc[nt][0]*w0*wc0;
                float v01 = sacc[nt][1]*w0*wc1;
                float v10 = sacc[nt][2]*w1*wc0;
                float v11 = sacc[nt][3]*w1*wc1;
                den0 += v00 + v01;
                den1 += v10 + v11;
                int wcl = wn*16 + nt*4 + lk;
                Qs[r0*PW + wcl] = bf2pack(v00, v01);
                Qs[r1*PW + wcl] = bf2pack(v10, v11);
            }
        } else {
            #pragma unroll
            for (int nt=0; nt<4; nt++){
                int c0 = wn*32 + nt*8 + (lk<<1);
                int c1 = c0 + 1;
                float a0v = as_[c0], a1v = as_[c1];
                float v00 = sacc[nt][0]*scale*__expf(f0 + a0v - mm0);
                float v01 = sacc[nt][1]*scale*__expf(f0 + a1v - mm0);
                float v10 = sacc[nt][2]*scale*__expf(f1 + a0v - mm1);
                float v11 = sacc[nt][3]*scale*__expf(f1 + a1v - mm1);
                if (c0 > r0) v00 = 0.f;
                if (c1 > r0) v01 = 0.f;
                if (c0 > r1) v10 = 0.f;
                if (c1 > r1) v11 = 0.f;
                den0 += v00 + v01;
                den1 += v10 + v11;
                int wcl = wn*16 + nt*4 + lk;
                Qs[r0*PW + wcl] = bf2pack(v00, v01);
                Qs[r1*PW + wcl] = bf2pack(v10, v11);
            }
        }
        __syncthreads();

        #pragma unroll
        for (int ks2=0; ks2<4; ks2++){
            uint32_t af[4];
            af[0] = Qs[r0*PW + ks2*8 + lk];
            af[1] = Qs[r1*PW + ks2*8 + lk];
            af[2] = Qs[r0*PW + ks2*8 + lk + 4];
            af[3] = Qs[r1*PW + ks2*8 + lk + 4];
            int krow = (ks2<<4) + lr + ((g8&1)<<3);
            #pragma unroll
            for (int nt=0; nt<8; nt++){
                int cd = wn*8 + nt;
                uint32_t addr = smaddr(&Vs[krow*VW + ((cd ^ (krow&7))<<2)]);
                uint32_t b0, b1;
                asm volatile("ldmatrix.sync.aligned.m8n8.x2.trans.shared.b16 {%0,%1}, [%2];\n"
                    : "=r"(b0),"=r"(b1) : "r"(addr));
                mma_bf16(oacc[nt], af, b0, b1);
            }
        }
    }

    den0 += __shfl_xor_sync(0xffffffffu, den0, 1);
    den0 += __shfl_xor_sync(0xffffffffu, den0, 2);
    den1 += __shfl_xor_sync(0xffffffffu, den1, 1);
    den1 += __shfl_xor_sync(0xffffffffu, den1, 2);
    __syncthreads();
    if (lk == 0){ den2[wn*64 + r0] = den0; den2[wn*64 + r1] = den1; }
    __syncthreads();
    float dt0 = den2[r0] + den2[64 + r0];
    float dt1 = den2[r1] + den2[64 + r1];
    float inv0 = 1.f / (fmaxf(fabsf(dt0), __expf(-mt[r0])) + 1e-6f);
    float inv1 = 1.f / (fmaxf(fabsf(dt1), __expf(-mt[r1])) + 1e-6f);

    float hv0[16], hv1[16];
    #pragma unroll
    for (int nt=0; nt<8; nt++){
        hv0[nt*2]   = oacc[nt][0]*inv0;
        hv0[nt*2+1] = oacc[nt][1]*inv0;
        hv1[nt*2]   = oacc[nt][2]*inv1;
        hv1[nt*2+1] = oacc[nt][3]*inv1;
    }

    float s0 = 0.f, s1 = 0.f, q0 = 0.f, q1 = 0.f;
    #pragma unroll
    for (int i=0;i<16;i++){
        s0 += hv0[i]; q0 += hv0[i]*hv0[i];
        s1 += hv1[i]; q1 += hv1[i]*hv1[i];
    }
    #pragma unroll
    for (int o=1;o<4;o<<=1){
        s0 += __shfl_xor_sync(0xffffffffu, s0, o);
        q0 += __shfl_xor_sync(0xffffffffu, q0, o);
        s1 += __shfl_xor_sync(0xffffffffu, s1, o);
        q1 += __shfl_xor_sync(0xffffffffu, q1, o);
    }
    __syncthreads();
    if (lk == 0){
        den2[wn*64 + r0] = s0; den2[wn*64 + r1] = s1;
        dsq[wn*64 + r0]  = q0; dsq[wn*64 + r1]  = q1;
    }
    __syncthreads();
    float mu0 = (den2[r0] + den2[64 + r0]) * (1.f/128.f);
    float mu1 = (den2[r1] + den2[64 + r1]) * (1.f/128.f);
    float e20 = (dsq[r0] + dsq[64 + r0]) * (1.f/128.f);
    float e21 = (dsq[r1] + dsq[64 + r1]) * (1.f/128.f);
    float is0 = rsqrtf(e20 - mu0*mu0 + 1e-5f);
    float is1 = rsqrtf(e21 - mu1*mu1 + 1e-5f);

    size_t tok0 = (size_t)(b*SEQ + t0 + r0), tok1 = (size_t)(b*SEQ + t0 + r1);
    #pragma unroll
    for (int nt=0; nt<8; nt++){
        int dc = wn*64 + nt*8 + (lk<<1);
        int c = hh*128 + dc;
        float2 gg = *(const float2*)&gng[c];
        float2 gb = *(const float2*)&gnb[c];
        float2 sk = *(const float2*)&skip[c];
        float2 x0 = __bfloat1622float2(*(const __nv_bfloat162*)&xcbf[tok0*512 + c]);
        float2 x1 = __bfloat1622float2(*(const __nv_bfloat162*)&xcbf[tok1*512 + c]);
        float2 z0 = __bfloat1622float2(*(const __nv_bfloat162*)&upz[tok0*512 + c]);
        float2 z1 = __bfloat1622float2(*(const __nv_bfloat162*)&upz[tok1*512 + c]);
        float y00 = (hv0[nt*2]  -mu0)*is0*gg.x + gb.x + sk.x*x0.x;
        float y01 = (hv0[nt*2+1]-mu0)*is0*gg.y + gb.y + sk.y*x0.y;
        float y10 = (hv1[nt*2]  -mu1)*is1*gg.x + gb.x + sk.x*x1.x;
        float y11 = (hv1[nt*2+1]-mu1)*is1*gg.y + gb.y + sk.y*x1.y;
        y00 *= z0.x / (1.f + expf(-z0.x));
        y01 *= z0.y / (1.f + expf(-z0.y));
        y10 *= z1.x / (1.f + expf(-z1.x));
        y11 *= z1.y / (1.f + expf(-z1.y));
        *(__nv_bfloat162*)&out[tok0*512 + c] = __floats2bfloat162_rn(y00, y01);
        *(__nv_bfloat162*)&out[tok1*512 + c] = __floats2bfloat162_rn(y10, y11);
    }
}

// ---------------- final ----------------
__global__ void final_kernel(const float* __restrict__ h, const float* __restrict__ g,
                             const float* __restrict__ b, const float* __restrict__ Wf,
                             const float* __restrict__ bf, float* __restrict__ out){
    __shared__ float sh[8];
    __shared__ float sv;
    int bb = blockIdx.x, tid = threadIdx.x;
    float vv = h[((size_t)(bb*SEQ + SEQ-1))*256 + tid];
    float s = warp_sum(vv);
    if (!(tid&31)) sh[tid>>5] = s;
    __syncthreads();
    if (tid==0){ float t=0; for(int i=0;i<8;i++) t+=sh[i]; sv = t*(1.f/256.f); }
    __syncthreads();
    float mu = sv;
    float d = vv - mu;
    float s2 = warp_sum(d*d);
    if (!(tid&31)) sh[tid>>5] = s2;
    __syncthreads();
    if (tid==0){ float t=0; for(int i=0;i<8;i++) t+=sh[i]; sv = t*(1.f/256.f); }
    __syncthreads();
    float yn = d*rsqrtf(sv + 1e-5f)*g[tid] + b[tid];
    float p = yn * Wf[tid];
    float s3 = warp_sum(p);
    __syncthreads();
    if (!(tid&31)) sh[tid>>5] = s3;
    __syncthreads();
    if (tid==0){ float t=0; for(int i=0;i<8;i++) t+=sh[i]; out[bb] = t + bf[0]; }
}

// ---------------- launch ----------------
extern "C" void kernel_launch(void* const* d_in, const int* in_sizes, int n_in,
                              void* d_out, int out_size){
    const float* x    = (const float*)d_in[0];
    const float* tf   = (const float*)d_in[1];
    const float* Wp   = (const float*)d_in[2];
    const float* bp   = (const float*)d_in[3];
    const float* ln_g = (const float*)d_in[4];
    const float* ln_b = (const float*)d_in[5];
    const float* Wup  = (const float*)d_in[6];
    const float* bup  = (const float*)d_in[7];
    const float* cw   = (const float*)d_in[8];
    const float* cb   = (const float*)d_in[9];
    const float* Wq   = (const float*)d_in[10];
    const float* Wk   = (const float*)d_in[11];
    const float* Wv   = (const float*)d_in[12];
    const float* Wif  = (const float*)d_in[13];
    const float* bif  = (const float*)d_in[14];
    const float* gng  = (const float*)d_in[15];
    const float* gnb  = (const float*)d_in[16];
    const float* skip = (const float*)d_in[17];
    const float* Wdn  = (const float*)d_in[18];
    const float* bdn  = (const float*)d_in[19];
    const float* lnfg = (const float*)d_in[20];
    const float* lnfb = (const float*)d_in[21];
    const float* Wf   = (const float*)d_in[22];
    const float* bf   = (const float*)d_in[23];

    float *h,*up,*giT,*gfT,*Fc,*a,*m,*wcol,*amaxT,*mqp,*Wg;
    __nv_bfloat16 *hnbf,*xcbf,*upbf,*upzbf,*qbf,*kbf,*vbf,*att2bf,*wupbf,*wqbf,*wkbf,*wvbf,*wdnbf;
    cudaGetSymbolAddress((void**)&h,    g_h);
    cudaGetSymbolAddress((void**)&up,   g_up);
    cudaGetSymbolAddress((void**)&giT,  g_giT);
    cudaGetSymbolAddress((void**)&gfT,  g_gfT);
    cudaGetSymbolAddress((void**)&Fc,   g_Fc);
    cudaGetSymbolAddress((void**)&a,    g_a);
    cudaGetSymbolAddress((void**)&m,    g_m);
    cudaGetSymbolAddress((void**)&wcol, g_wcol);
    cudaGetSymbolAddress((void**)&amaxT,g_amaxT);
    cudaGetSymbolAddress((void**)&mqp,  g_mq);
    cudaGetSymbolAddress((void**)&Wg,   g_Wg);
    cudaGetSymbolAddress((void**)&hnbf, g_hn_bf);
    cudaGetSymbolAddress((void**)&xcbf, g_xc_bf);
    cudaGetSymbolAddress((void**)&upbf, g_up_bf);
    cudaGetSymbolAddress((void**)&upzbf,g_upz_bf);
    cudaGetSymbolAddress((void**)&qbf,  g_q_bf);
    cudaGetSymbolAddress((void**)&kbf,  g_k_bf);
    cudaGetSymbolAddress((void**)&vbf,  g_v_bf);
    cudaGetSymbolAddress((void**)&att2bf, g_att2_bf);
    cudaGetSymbolAddress((void**)&wupbf, g_wup_bf);
    cudaGetSymbolAddress((void**)&wqbf,  g_wq_bf);
    cudaGetSymbolAddress((void**)&wkbf,  g_wk_bf);
    cudaGetSymbolAddress((void**)&wvbf,  g_wv_bf);
    cudaGetSymbolAddress((void**)&wdnbf, g_wdn_bf);

    int attn_smem = (64*QKW + 64*QKW + 64*VW + 64 + 64 + 64 + 128 + 128) * 4;
    int gemm_smem = 65536;
    int gemm64_smem = 49152;
    static int attr_set = 0;
    if (!attr_set){
        cudaFuncSetAttribute(attn_bf16, cudaFuncAttributeMaxDynamicSharedMemorySize, attn_smem);
        cudaFuncSetAttribute(gemm_bf16, cudaFuncAttributeMaxDynamicSharedMemorySize, gemm_smem);
        cudaFuncSetAttribute(gemm_bf16_m64, cudaFuncAttributeMaxDynamicSharedMemorySize, gemm64_smem);
        attr_set = 1;
    }

    int n0 = NL*DMODEL*1024, n1 = NL*DI*DI, n4 = NL*DI*DMODEL;
    int ntot = n0 + 3*n1 + n4;
    f2bf5_kernel<<<(ntot/2 + 255)/256, 256>>>(Wup, wupbf, n0,
                                              Wq, wqbf, n1,
                                              Wk, wkbf, n1,
                                              Wv, wvbf, n1,
                                              Wdn, wdnbf, n4);
    gatew_kernel<<<NL*1024*8/256, 256>>>(Wq, Wk, Wv, Wif, Wg);

    embed_kernel<<<TOK*256/256, 256>>>(x, tf, Wp, bp, h);

    for (int l=0; l<NL; l++){
        ln_kernel<<<TOK/8, 256>>>(h, ln_g + l*256, ln_b + l*256, hnbf);
        // up-GEMM: fp32 only cols<512 (conv/gates need precision); xm half bf16 to upbf; z half bf16 to upzbf
        gemm_bf16<<<dim3(1024/128, TOK/128, 1), 256, gemm_smem>>>(
            hnbf, 256, wupbf + (size_t)l*256*1024, 1024,
            up, 1024, bup + l*1024, nullptr, 256,
            upbf, 512, nullptr, nullptr, nullptr, nullptr, nullptr,
            upzbf, 512);
        conv_gates8_kernel<<<TOK/8, 256>>>(up, cw + l*4*512, cb + l*512,
                                           Wg + (size_t)l*8192, bif + l*8,
                                           xcbf, giT, gfT);
        gemm_bf16<<<dim3(512/128, TOK/128, 3), 256, gemm_smem>>>(
            xcbf, 512, wqbf + (size_t)l*512*512, 512,
            nullptr, 512, nullptr, nullptr, 512, qbf, 512,
            upbf,
            wkbf + (size_t)l*512*512, kbf,
            wvbf + (size_t)l*512*512, vbf,
            nullptr, 1024);
        scan_kernel4<<<32, 32>>>(giT, gfT, Fc, a, m, wcol, amaxT, mqp);
        attn_bf16<<<dim3(BATCH*NH, SEQ/64), 256, attn_smem>>>(qbf, kbf, vbf, Fc, a, m,
                                                  wcol, amaxT, mqp,
                                                  xcbf, upzbf, gng + l*512, gnb + l*512, skip + l*512,
                                                  att2bf);
        gemm_bf16_m64<<<dim3(256/128, TOK/64, 1), 256, gemm64_smem>>>(
            att2bf, 512, wdnbf + (size_t)l*512*256, 256,
            h, 256, bdn + l*256, h, 512);
    }
    final_kernel<<<BATCH, 256>>>(h, lnfg, lnfb, Wf, bf, (float*)d_out);
}

// round 17
// speedup vs baseline: 1.4584x; 1.0057x over previous
#include <cuda_runtime.h>
#include <cuda_bf16.h>
#include <cstdint>
#include <cstddef>

#define SEQ 1024
#define BATCH 8
#define TOK (BATCH*SEQ)
#define DMODEL 256
#define DI 512
#define NH 4
#define DHH 128
#define NL 4

// ---------------- scratch (device globals; no allocation allowed) ----------------
__device__ float g_h[TOK*DMODEL];
__device__ float g_up[TOK*1024];
__device__ float g_giT[BATCH*NH*SEQ];
__device__ float g_gfT[BATCH*NH*SEQ];
__device__ float g_Fc[BATCH*NH*SEQ];
__device__ float g_a[BATCH*NH*SEQ];
__device__ float g_m[BATCH*NH*SEQ];
__device__ float g_wcol[BATCH*NH*SEQ];
__device__ float g_amaxT[BATCH*NH*16];
__device__ float g_mq[BATCH*NH*16];
__device__ float g_Wg[NL*1024*8];

__device__ __nv_bfloat16 g_hn_bf[TOK*DMODEL];
__device__ __nv_bfloat16 g_xc_bf[TOK*DI];
__device__ __nv_bfloat16 g_up_bf[TOK*DI];
__device__ __nv_bfloat16 g_upz_bf[TOK*DI];
__device__ __nv_bfloat16 g_q_bf[TOK*DI];
__device__ __nv_bfloat16 g_k_bf[TOK*DI];
__device__ __nv_bfloat16 g_v_bf[TOK*DI];
__device__ __nv_bfloat16 g_att2_bf[TOK*DI];
__device__ __nv_bfloat16 g_wup_bf[NL*DMODEL*1024];
__device__ __nv_bfloat16 g_wq_bf[NL*DI*DI];
__device__ __nv_bfloat16 g_wk_bf[NL*DI*DI];
__device__ __nv_bfloat16 g_wv_bf[NL*DI*DI];
__device__ __nv_bfloat16 g_wdn_bf[NL*DI*DMODEL];

__device__ __forceinline__ float warp_sum(float v){
    #pragma unroll
    for (int o=16;o;o>>=1) v += __shfl_xor_sync(0xffffffffu, v, o);
    return v;
}

__device__ __forceinline__ uint32_t bf2pack(float x, float y){
    __nv_bfloat162 t = __floats2bfloat162_rn(x, y);
    return *(uint32_t*)&t;
}

__device__ __forceinline__ void mma_bf16(float* c, const uint32_t* a, uint32_t b0, uint32_t b1){
    asm volatile(
      "mma.sync.aligned.m16n8k16.row.col.f32.bf16.bf16.f32 "
      "{%0,%1,%2,%3}, {%4,%5,%6,%7}, {%8,%9}, {%0,%1,%2,%3};\n"
      : "+f"(c[0]), "+f"(c[1]), "+f"(c[2]), "+f"(c[3])
      : "r"(a[0]), "r"(a[1]), "r"(a[2]), "r"(a[3]), "r"(b0), "r"(b1));
}

__device__ __forceinline__ uint32_t smaddr(const void* p){
    return (uint32_t)__cvta_generic_to_shared(p);
}
#define CPA16(dst,src) asm volatile("cp.async.cg.shared.global [%0], [%1], 16;\n"::"r"(dst),"l"(src))
#define CPCOMMIT() asm volatile("cp.async.commit_group;\n")
#define CPWAIT(n) asm volatile("cp.async.wait_group %0;\n"::"n"(n))

// ---------------- merged f32 -> bf16 convert for all 5 weight tensors ----------------
__global__ void f2bf5_kernel(const float* __restrict__ i0, __nv_bfloat16* __restrict__ o0, int n0,
                             const float* __restrict__ i1, __nv_bfloat16* __restrict__ o1, int n1,
                             const float* __restrict__ i2, __nv_bfloat16* __restrict__ o2, int n2,
                             const float* __restrict__ i3, __nv_bfloat16* __restrict__ o3, int n3,
                             const float* __restrict__ i4, __nv_bfloat16* __restrict__ o4, int n4){
    int i = (blockIdx.x*blockDim.x + threadIdx.x)*2;
    const float* in; __nv_bfloat16* out;
    if (i < n0){ in=i0; out=o0; }
    else if ((i-=n0) < n1){ in=i1; out=o1; }
    else if ((i-=n1) < n2){ in=i2; out=o2; }
    else if ((i-=n2) < n3){ in=i3; out=o3; }
    else if ((i-=n3) < n4){ in=i4; out=o4; }
    else return;
    float2 v = *(const float2*)(in+i);
    *(__nv_bfloat162*)(out+i) = __floats2bfloat162_rn(v.x, v.y);
}

// ---------------- composite gate weights ----------------
__global__ void gatew_kernel(const float* __restrict__ Wq, const float* __restrict__ Wk,
                             const float* __restrict__ Wv, const float* __restrict__ Wif,
                             float* __restrict__ Wg){
    int idx = blockIdx.x*blockDim.x + threadIdx.x;
    int l = idx >> 13; int r = idx & 8191;
    int c = r >> 3; int j = r & 7;
    const float* Wifl = Wif + (size_t)l*1536*8;
    float acc = 0.f;
    if (c < 512){
        const float* wq = Wq + ((size_t)l*512 + c)*512;
        const float* wk = Wk + ((size_t)l*512 + c)*512;
        #pragma unroll 4
        for (int i=0;i<512;i++)
            acc += wq[i]*Wifl[i*8+j] + wk[i]*Wifl[(512+i)*8+j];
    } else {
        const float* wv = Wv + ((size_t)l*512 + (c-512))*512;
        #pragma unroll 4
        for (int i=0;i<512;i++)
            acc += wv[i]*Wifl[(1024+i)*8+j];
    }
    Wg[(size_t)l*8192 + c*8 + j] = acc;
}

// ---------------- embed ----------------
__global__ void embed_kernel(const float* __restrict__ x, const float* __restrict__ tf,
                             const float* __restrict__ Wp, const float* __restrict__ bp,
                             float* __restrict__ h){
    int idx = blockIdx.x*blockDim.x + threadIdx.x;
    int j = idx & 255; int tok = idx >> 8;
    float acc = bp[j] + x[tok]*Wp[j];
    #pragma unroll
    for (int f=0; f<4; f++) acc += tf[tok*4+f]*Wp[(1+f)*256+j];
    h[idx] = acc;
}

// ---------------- layernorm, bf16 out (layer 0 only) ----------------
__global__ void ln_kernel(const float* __restrict__ x, const float* __restrict__ g,
                          const float* __restrict__ b, __nv_bfloat16* __restrict__ y){
    int row = blockIdx.x*8 + (threadIdx.x>>5);
    int lane = threadIdx.x & 31;
    const float* xr = x + (size_t)row*256;
    float4 v0 = *(const float4*)(xr + lane*4);
    float4 v1 = *(const float4*)(xr + 128 + lane*4);
    float s  = v0.x+v0.y+v0.z+v0.w + v1.x+v1.y+v1.z+v1.w;
    float sq = v0.x*v0.x+v0.y*v0.y+v0.z*v0.z+v0.w*v0.w
             + v1.x*v1.x+v1.y*v1.y+v1.z*v1.z+v1.w*v1.w;
    #pragma unroll
    for (int o=16;o;o>>=1){
        s  += __shfl_xor_sync(0xffffffffu, s,  o);
        sq += __shfl_xor_sync(0xffffffffu, sq, o);
    }
    float mu = s * (1.f/256.f);
    float var = sq * (1.f/256.f) - mu*mu;
    float is = rsqrtf(var + 1e-5f);
    float4 g0 = *(const float4*)(g + lane*4);
    float4 g1 = *(const float4*)(g + 128 + lane*4);
    float4 b0 = *(const float4*)(b + lane*4);
    float4 b1 = *(const float4*)(b + 128 + lane*4);
    __nv_bfloat16* yr = y + (size_t)row*256;
    *(__nv_bfloat162*)&yr[lane*4]       = __floats2bfloat162_rn((v0.x-mu)*is*g0.x + b0.x, (v0.y-mu)*is*g0.y + b0.y);
    *(__nv_bfloat162*)&yr[lane*4+2]     = __floats2bfloat162_rn((v0.z-mu)*is*g0.z + b0.z, (v0.w-mu)*is*g0.w + b0.w);
    *(__nv_bfloat162*)&yr[128+lane*4]   = __floats2bfloat162_rn((v1.x-mu)*is*g1.x + b1.x, (v1.y-mu)*is*g1.y + b1.y);
    *(__nv_bfloat162*)&yr[128+lane*4+2] = __floats2bfloat162_rn((v1.z-mu)*is*g1.z + b1.z, (v1.w-mu)*is*g1.w + b1.w);
}

// ---------------- bf16 tensor-core GEMM: CTA 128x128x64, 8 warps 2x4 ----------------
__global__ __launch_bounds__(256, 2) void gemm_bf16(
    const __nv_bfloat16* __restrict__ A, int lda,
    const __nv_bfloat16* __restrict__ B, int ldb,
    float* __restrict__ C, int ldc,
    const float* __restrict__ bias,
    const float* __restrict__ resid,
    int K,
    __nv_bfloat16* __restrict__ Cbf, int bfcap,
    const __nv_bfloat16* __restrict__ A2,
    const __nv_bfloat16* __restrict__ B2,
    __nv_bfloat16* __restrict__ Cbf2,
    const __nv_bfloat16* __restrict__ B3,
    __nv_bfloat16* __restrict__ Cbf3,
    __nv_bfloat16* __restrict__ Cbfz,
    int cfpcap)
{
    extern __shared__ __nv_bfloat16 sm[];
    __nv_bfloat16* As = sm;            // 2 x 128 x 64
    __nv_bfloat16* Bs = sm + 16384;    // 2 bufs x 2 halves x 64 x 64
    if (blockIdx.z == 1){ B = B2; Cbf = Cbf2; }
    else if (blockIdx.z == 2){ A = A2; B = B3; Cbf = Cbf3; }
    int tid = threadIdx.x, lane = tid&31, wid = tid>>5;
    int wm = wid>>2, wn = wid&3;
    int m0 = blockIdx.y*128, n0 = blockIdx.x*128;

    int ar = tid >> 1;
    int ac0 = (tid & 1) << 2;
    int br = tid >> 2;
    int bc0 = (tid & 3) << 1;
    const __nv_bfloat16* Ag = A + (size_t)(m0+ar)*lda;
    const __nv_bfloat16* Bg = B + (size_t)br*ldb + n0;

    int KC = K >> 6;
    {
        #pragma unroll
        for (int c=0;c<4;c++){
            int ch = ac0+c;
            CPA16(smaddr(&As[ar*64 + ((ch ^ (ar&7))<<3)]), Ag + (ch<<3));
        }
        #pragma unroll
        for (int hf=0; hf<2; hf++)
          #pragma unroll
          for (int c=0;c<2;c++){
            int ch = bc0+c;
            CPA16(smaddr(&Bs[hf*4096 + br*64 + ((ch ^ (br&7))<<3)]), Bg + hf*64 + (ch<<3));
        }
        CPCOMMIT();
    }

    float acc[4][4][4] = {};
    int g = lane>>3, lr = lane&7;
    int bhalf = wn>>1, bco = (wn&1)<<2;

    for (int kc=0; kc<KC; kc++){
        int cur = kc & 1;
        if (kc+1 < KC){
            int nb = (kc+1)&1, k0 = (kc+1)<<6;
            #pragma unroll
            for (int c=0;c<4;c++){
                int ch = ac0+c;
                CPA16(smaddr(&As[nb*8192 + ar*64 + ((ch ^ (ar&7))<<3)]), Ag + k0 + (ch<<3));
            }
            #pragma unroll
            for (int hf=0; hf<2; hf++)
              #pragma unroll
              for (int c=0;c<2;c++){
                int ch = bc0+c;
                CPA16(smaddr(&Bs[nb*8192 + hf*4096 + br*64 + ((ch ^ (br&7))<<3)]),
                      Bg + (size_t)k0*ldb + hf*64 + (ch<<3));
            }
            CPCOMMIT();
            CPWAIT(1);
        } else {
            CPWAIT(0);
        }
        __syncthreads();

        const __nv_bfloat16* Ab = As + cur*8192;
        const __nv_bfloat16* Bb = Bs + cur*8192 + bhalf*4096;
        #pragma unroll
        for (int ks=0; ks<4; ks++){
            uint32_t af[4][4];
            #pragma unroll
            for (int mt=0; mt<4; mt++){
                int arow = wm*64 + mt*16 + lr + ((g&1)<<3);
                int ch = (ks<<1) + (g>>1);
                uint32_t addr = smaddr(&Ab[arow*64 + ((ch ^ (arow&7))<<3)]);
                asm volatile("ldmatrix.sync.aligned.m8n8.x4.shared.b16 {%0,%1,%2,%3}, [%4];\n"
                    : "=r"(af[mt][0]),"=r"(af[mt][1]),"=r"(af[mt][2]),"=r"(af[mt][3]) : "r"(addr));
            }
            uint32_t bf[4][2];
            int krow = (ks<<4) + lr + ((g&1)<<3);
            #pragma unroll
            for (int nt=0; nt<4; nt++){
                int ch = bco + nt;
                uint32_t addr = smaddr(&Bb[krow*64 + ((ch ^ (krow&7))<<3)]);
                asm volatile("ldmatrix.sync.aligned.m8n8.x2.trans.shared.b16 {%0,%1}, [%2];\n"
                    : "=r"(bf[nt][0]),"=r"(bf[nt][1]) : "r"(addr));
            }
            #pragma unroll
            for (int mt=0;mt<4;mt++)
              #pragma unroll
              for (int nt=0;nt<4;nt++)
                mma_bf16(acc[mt][nt], af[mt], bf[nt][0], bf[nt][1]);
        }
        __syncthreads();
    }

    #pragma unroll
    for (int mt=0;mt<4;mt++){
        #pragma unroll
        for (int nt=0;nt<4;nt++){
            int row0 = m0 + wm*64 + mt*16 + (lane>>2);
            int col  = n0 + wn*32 + nt*8 + ((lane&3)<<1);
            float bx=0.f, by=0.f;
            if (bias){ bx = bias[col]; by = bias[col+1]; }
            float2 r0v = make_float2(0.f,0.f), r1v = make_float2(0.f,0.f);
            if (resid){
                r0v = *(const float2*)&resid[(size_t)row0*ldc + col];
                r1v = *(const float2*)&resid[(size_t)(row0+8)*ldc + col];
            }
            float v00 = acc[mt][nt][0]+bx+r0v.x, v01 = acc[mt][nt][1]+by+r0v.y;
            float v10 = acc[mt][nt][2]+bx+r1v.x, v11 = acc[mt][nt][3]+by+r1v.y;
            if (C && col < cfpcap){
                *(float2*)&C[(size_t)row0*ldc + col]     = make_float2(v00, v01);
                *(float2*)&C[(size_t)(row0+8)*ldc + col] = make_float2(v10, v11);
            }
            if (Cbf && col < bfcap){
                *(__nv_bfloat162*)&Cbf[(size_t)row0*bfcap + col]     = __floats2bfloat162_rn(v00, v01);
                *(__nv_bfloat162*)&Cbf[(size_t)(row0+8)*bfcap + col] = __floats2bfloat162_rn(v10, v11);
            }
            if (Cbfz && col >= 512){
                int zc = col - 512;
                *(__nv_bfloat162*)&Cbfz[(size_t)row0*512 + zc]     = __floats2bfloat162_rn(v00, v01);
                *(__nv_bfloat162*)&Cbfz[(size_t)(row0+8)*512 + zc] = __floats2bfloat162_rn(v10, v11);
            }
        }
    }
}

// ---------------- down-GEMM 64x256x64 with fused next-layer LayerNorm epilogue ----------------
// C = A@B + bias + C (residual), full 256-col rows per CTA -> in-register row LN -> hn (bf16).
__global__ __launch_bounds__(256, 2) void gemm_down_ln(
    const __nv_bfloat16* __restrict__ A,
    const __nv_bfloat16* __restrict__ B,
    float* __restrict__ C,
    const float* __restrict__ bias,
    const float* __restrict__ lng, const float* __restrict__ lnb,
    __nv_bfloat16* __restrict__ hn)
{
    extern __shared__ __nv_bfloat16 sm[];
    __nv_bfloat16* As = sm;            // 2 x 64 x 64
    __nv_bfloat16* Bs = sm + 8192;     // 2 stages x 4 quarters x 64 x 64
    int tid = threadIdx.x, lane = tid&31, wid = tid>>5;
    int wm = wid>>2, wn = wid&3;       // 2 x 4 ; wn owns a full 64-col quarter
    int m0 = blockIdx.y*64;

    int ar = tid >> 2;
    int ac0 = (tid & 3) << 1;
    const __nv_bfloat16* Ag = A + (size_t)(m0+ar)*512;
    const __nv_bfloat16* Bg = B + (size_t)ar*256;

    {
        #pragma unroll
        for (int c=0;c<2;c++){
            int ch = ac0+c;
            CPA16(smaddr(&As[ar*64 + ((ch ^ (ar&7))<<3)]), Ag + (ch<<3));
        }
        #pragma unroll
        for (int q=0;q<4;q++)
          #pragma unroll
          for (int c=0;c<2;c++){
            int ch = ac0+c;
            CPA16(smaddr(&Bs[q*4096 + ar*64 + ((ch ^ (ar&7))<<3)]), Bg + q*64 + (ch<<3));
        }
        CPCOMMIT();
    }

    float acc[2][8][4] = {};
    int g = lane>>3, lr = lane&7;
    int ls = lane>>2, lk = lane&3;

    for (int kc=0; kc<8; kc++){
        int cur = kc & 1;
        if (kc+1 < 8){
            int nb = (kc+1)&1, k0 = (kc+1)<<6;
            #pragma unroll
            for (int c=0;c<2;c++){
                int ch = ac0+c;
                CPA16(smaddr(&As[nb*4096 + ar*64 + ((ch ^ (ar&7))<<3)]), Ag + k0 + (ch<<3));
            }
            #pragma unroll
            for (int q=0;q<4;q++)
              #pragma unroll
              for (int c=0;c<2;c++){
                int ch = ac0+c;
                CPA16(smaddr(&Bs[nb*16384 + q*4096 + ar*64 + ((ch ^ (ar&7))<<3)]),
                      Bg + (size_t)k0*256 + q*64 + (ch<<3));
            }
            CPCOMMIT();
            CPWAIT(1);
        } else {
            CPWAIT(0);
        }
        __syncthreads();

        const __nv_bfloat16* Ab = As + cur*4096;
        const __nv_bfloat16* Bb = Bs + cur*16384 + wn*4096;
        #pragma unroll
        for (int ks=0; ks<4; ks++){
            uint32_t af[2][4];
            #pragma unroll
            for (int mt=0; mt<2; mt++){
                int arow = wm*32 + mt*16 + lr + ((g&1)<<3);
                int ch = (ks<<1) + (g>>1);
                uint32_t addr = smaddr(&Ab[arow*64 + ((ch ^ (arow&7))<<3)]);
                asm volatile("ldmatrix.sync.aligned.m8n8.x4.shared.b16 {%0,%1,%2,%3}, [%4];\n"
                    : "=r"(af[mt][0]),"=r"(af[mt][1]),"=r"(af[mt][2]),"=r"(af[mt][3]) : "r"(addr));
            }
            int krow = (ks<<4) + lr + ((g&1)<<3);
            #pragma unroll
            for (int nt=0; nt<8; nt++){
                uint32_t b0, b1;
                uint32_t addr = smaddr(&Bb[krow*64 + ((nt ^ (krow&7))<<3)]);
                asm volatile("ldmatrix.sync.aligned.m8n8.x2.trans.shared.b16 {%0,%1}, [%2];\n"
                    : "=r"(b0),"=r"(b1) : "r"(addr));
                #pragma unroll
                for (int mt=0;mt<2;mt++)
                    mma_bf16(acc[mt][nt], af[mt], b0, b1);
            }
        }
        __syncthreads();
    }

    // ---- epilogue: v = acc + bias + resid; store C fp32; keep v in acc ----
    #pragma unroll
    for (int mt=0;mt<2;mt++){
        #pragma unroll
        for (int nt=0;nt<8;nt++){
            int row0 = m0 + wm*32 + mt*16 + ls;
            int col  = wn*64 + nt*8 + (lk<<1);
            float bx = bias[col], by = bias[col+1];
            float2 r0v = *(const float2*)&C[(size_t)row0*256 + col];
            float2 r1v = *(const float2*)&C[(size_t)(row0+8)*256 + col];
            acc[mt][nt][0] += bx + r0v.x;
            acc[mt][nt][1] += by + r0v.y;
            acc[mt][nt][2] += bx + r1v.x;
            acc[mt][nt][3] += by + r1v.y;
            *(float2*)&C[(size_t)row0*256 + col]     = make_float2(acc[mt][nt][0], acc[mt][nt][1]);
            *(float2*)&C[(size_t)(row0+8)*256 + col] = make_float2(acc[mt][nt][2], acc[mt][nt][3]);
        }
    }

    if (hn){
        __syncthreads();                 // smem reuse for LN reduction
        float* red = (float*)sm;         // [512]: sums [wn*64+row], sumsq at +256
        float s[4] = {0,0,0,0}, qq[4] = {0,0,0,0};
        #pragma unroll
        for (int nt=0;nt<8;nt++){
            s[0] += acc[0][nt][0]+acc[0][nt][1]; qq[0] += acc[0][nt][0]*acc[0][nt][0]+acc[0][nt][1]*acc[0][nt][1];
            s[1] += acc[0][nt][2]+acc[0][nt][3]; qq[1] += acc[0][nt][2]*acc[0][nt][2]+acc[0][nt][3]*acc[0][nt][3];
            s[2] += acc[1][nt][0]+acc[1][nt][1]; qq[2] += acc[1][nt][0]*acc[1][nt][0]+acc[1][nt][1]*acc[1][nt][1];
            s[3] += acc[1][nt][2]+acc[1][nt][3]; qq[3] += acc[1][nt][2]*acc[1][nt][2]+acc[1][nt][3]*acc[1][nt][3];
        }
        #pragma unroll
        for (int o=1;o<4;o<<=1){
            #pragma unroll
            for (int i2=0;i2<4;i2++){
                s[i2]  += __shfl_xor_sync(0xffffffffu, s[i2],  o);
                qq[i2] += __shfl_xor_sync(0xffffffffu, qq[i2], o);
            }
        }
        if (lk == 0){
            int rb = wm*32 + ls;
            red[wn*64 + rb]        = s[0];  red[256 + wn*64 + rb]        = qq[0];
            red[wn*64 + rb + 8]    = s[1];  red[256 + wn*64 + rb + 8]    = qq[1];
            red[wn*64 + rb + 16]   = s[2];  red[256 + wn*64 + rb + 16]   = qq[2];
            red[wn*64 + rb + 24]   = s[3];  red[256 + wn*64 + rb + 24]   = qq[3];
        }
        __syncthreads();
        float mu[4], iss[4];
        #pragma unroll
        for (int slot=0;slot<4;slot++){
            int lrow = wm*32 + (slot>>1)*16 + ls + ((slot&1)<<3);
            float su  = red[lrow] + red[64+lrow] + red[128+lrow] + red[192+lrow];
            float sq2 = red[256+lrow] + red[320+lrow] + red[384+lrow] + red[448+lrow];
            float m_ = su*(1.f/256.f);
            mu[slot] = m_;
            iss[slot] = rsqrtf(sq2*(1.f/256.f) - m_*m_ + 1e-5f);
        }
        #pragma unroll
        for (int mt=0;mt<2;mt++){
            #pragma unroll
            for (int nt=0;nt<8;nt++){
                int row0 = m0 + wm*32 + mt*16 + ls;
                int col  = wn*64 + nt*8 + (lk<<1);
                float2 gg = *(const float2*)&lng[col];
                float2 bb = *(const float2*)&lnb[col];
                int sA = mt*2, sB = mt*2+1;
                *(__nv_bfloat162*)&hn[(size_t)row0*256 + col] = __floats2bfloat162_rn(
                    (acc[mt][nt][0]-mu[sA])*iss[sA]*gg.x + bb.x,
                    (acc[mt][nt][1]-mu[sA])*iss[sA]*gg.y + bb.y);
                *(__nv_bfloat162*)&hn[(size_t)(row0+8)*256 + col] = __floats2bfloat162_rn(
                    (acc[mt][nt][2]-mu[sB])*iss[sB]*gg.x + bb.x,
                    (acc[mt][nt][3]-mu[sB])*iss[sB]*gg.y + bb.y);
            }
        }
    }
}

// ---------------- fused causal conv + silu + composite gates, 8 tokens/block ----------------
__global__ __launch_bounds__(256) void conv_gates8_kernel(
    const float* __restrict__ up, const float* __restrict__ cw, const float* __restrict__ cb,
    const float* __restrict__ Wg, const float* __restrict__ bif,
    __nv_bfloat16* __restrict__ xcbf,
    float* __restrict__ giT, float* __restrict__ gfT)
{
    __shared__ float ups[11][512];
    __shared__ float xcs[8][512];
    int tok0 = blockIdx.x << 3;
    int t0 = tok0 & 1023;
    int tid = threadIdx.x;

    for (int idx = tid; idx < 11*512; idx += 256){
        int r = idx >> 9, c = idx & 511;
        int tt = t0 - 3 + r;
        float v = 0.f;
        if (tt >= 0) v = up[(size_t)(tok0 - 3 + r)*1024 + c];
        ups[r][c] = v;
    }
    __syncthreads();

    for (int idx = tid; idx < 8*512; idx += 256){
        int j = idx >> 9, c = idx & 511;
        float acc = cb[c]
                  + cw[c]*ups[j][c] + cw[512+c]*ups[j+1][c]
                  + cw[1024+c]*ups[j+2][c] + cw[1536+c]*ups[j+3][c];
        float sv = acc/(1.f+expf(-acc));
        xcs[j][c] = sv;
        xcbf[(size_t)(tok0+j)*512 + c] = __float2bfloat16(sv);
    }
    __syncthreads();

    int wj = tid>>5, lane = tid&31;
    float acc[8] = {};
    for (int i = lane; i < 512; i += 32){
        float xcv = xcs[wj][i];
        float xmv = ups[wj+3][i];
        float4 w0 = *(const float4*)&Wg[i*8];
        float4 w1 = *(const float4*)&Wg[i*8+4];
        float4 w2 = *(const float4*)&Wg[(512+i)*8];
        float4 w3 = *(const float4*)&Wg[(512+i)*8+4];
        acc[0] += xcv*w0.x + xmv*w2.x;
        acc[1] += xcv*w0.y + xmv*w2.y;
        acc[2] += xcv*w0.z + xmv*w2.z;
        acc[3] += xcv*w0.w + xmv*w2.w;
        acc[4] += xcv*w1.x + xmv*w3.x;
        acc[5] += xcv*w1.y + xmv*w3.y;
        acc[6] += xcv*w1.z + xmv*w3.z;
        acc[7] += xcv*w1.w + xmv*w3.w;
    }
    #pragma unroll
    for (int w=0;w<8;w++) acc[w] = warp_sum(acc[w]);
    if (!lane){
        int tok = tok0 + wj;
        int b = tok >> 10, s = tok & 1023;
        #pragma unroll
        for (int w=0;w<4;w++) giT[(size_t)(b*4+w)*1024 + s] = acc[w] + bif[w];
        #pragma unroll
        for (int w=4;w<8;w++) gfT[(size_t)(b*4+w-4)*1024 + s] = acc[w] + bif[w];
    }
}

// ---------------- gate scan + per-tile col weights + per-qtile row bound ----------------
__global__ void scan_kernel4(const float* __restrict__ giT, const float* __restrict__ gfT,
                             float* __restrict__ Fc, float* __restrict__ a, float* __restrict__ m,
                             float* __restrict__ wcol, float* __restrict__ amaxT,
                             float* __restrict__ mq){
    __shared__ float ash[1024];
    int bh = blockIdx.x, lane = threadIdx.x;
    const float* gih = giT + (size_t)bh*1024;
    const float* gfh = gfT + (size_t)bh*1024;
    const float scale = 0.08838834764831845f;
    float cfc = 0.f, cmax = -1e30f;
    float ipc = gih[lane], fpc = gfh[lane];
    for (int c=0;c<32;c++){
        float ip = ipc, fp = fpc;
        if (c+1 < 32){ ipc = gih[(c+1)*32+lane]; fpc = gfh[(c+1)*32+lane]; }
        float lf = fminf(fp, 0.f) - log1pf(expf(-fabsf(fp)));
        float x = lf;
        #pragma unroll
        for (int o=1;o<32;o<<=1){ float y = __shfl_up_sync(0xffffffffu, x, o); if (lane>=o) x += y; }
        float fc = cfc + x;
        float av = ip - fc;
        float mx = av;
        #pragma unroll
        for (int o=1;o<32;o<<=1){ float y = __shfl_up_sync(0xffffffffu, mx, o); if (lane>=o) mx = fmaxf(mx, y); }
        float cm = fmaxf(cmax, mx);
        int pos = c*32 + lane;
        int off = bh*SEQ + pos;
        Fc[off] = fc; a[off] = av; m[off] = fc + cm;
        if ((pos & 63) == 0) mq[bh*16 + (pos>>6)] = -cm;
        ash[pos] = av;
        cfc += __shfl_sync(0xffffffffu, x, 31);
        cmax = fmaxf(cmax, __shfl_sync(0xffffffffu, mx, 31));
    }
    __syncwarp();
    for (int tile=0;tile<16;tile++){
        float v0 = ash[tile*64 + lane];
        float v1 = ash[tile*64 + 32 + lane];
        float mx = fmaxf(v0, v1);
        #pragma unroll
        for (int o=16;o;o>>=1) mx = fmaxf(mx, __shfl_xor_sync(0xffffffffu, mx, o));
        if (lane == 0) amaxT[bh*16 + tile] = mx;
        wcol[bh*SEQ + tile*64 + lane]      = scale*__expf(v0 - mx);
        wcol[bh*SEQ + tile*64 + 32 + lane] = scale*__expf(v1 - mx);
    }
}

// ---------------- mLSTM attention + decay-bound tile skipping + fused epilogue ----------------
#define QKW 68
#define VW  64
#define PW  36
__global__ __launch_bounds__(256) void attn_bf16(
    const __nv_bfloat16* __restrict__ q, const __nv_bfloat16* __restrict__ k,
    const __nv_bfloat16* __restrict__ v,
    const float* __restrict__ Fcv, const float* __restrict__ av, const float* __restrict__ mv,
    const float* __restrict__ wcol, const float* __restrict__ amaxT,
    const float* __restrict__ mq,
    const __nv_bfloat16* __restrict__ xcbf, const __nv_bfloat16* __restrict__ upz,
    const float* __restrict__ gng, const float* __restrict__ gnb,
    const float* __restrict__ skip,
    __nv_bfloat16* __restrict__ out)
{
    extern __shared__ uint32_t smu[];
    uint32_t* Qs = smu;
    uint32_t* Ks = Qs + 64*QKW;
    uint32_t* Vs = Ks + 64*QKW;
    float* fct  = (float*)(Vs + 64*VW);
    float* mt   = fct + 64;
    float* as_  = mt + 64;
    float* den2 = as_ + 64;
    float* dsq  = den2 + 128;

    int bh = blockIdx.x; int b = bh>>2, hh = bh&3;
    int it = (int)(gridDim.y - 1) - (int)blockIdx.y;
    int t0 = it<<6;
    int tid = threadIdx.x, lane = tid&31, wid = tid>>5;
    int wm = wid>>1, wn = wid&1;
    int ls = lane>>2, lk = lane&3;
    int g8 = lane>>3, lr = lane&7;
    const float scale = 0.08838834764831845f;

    const __nv_bfloat16* qg = q + ((size_t)(b*SEQ + t0))*512 + hh*128;
    #pragma unroll
    for (int r=0;r<4;r++){
        int idx = tid + (r<<8);
        int row = idx>>4, c16 = idx&15;
        uint4 val = *(const uint4*)(qg + (size_t)row*512 + (c16<<3));
        *(uint4*)&Qs[row*QKW + (c16<<2)] = val;
    }
    if (tid < 64){ int tg = bh*SEQ + t0 + tid; fct[tid] = Fcv[tg]; mt[tid] = mv[tg]; }
    __syncthreads();

    uint32_t qf[8][4];
    int r0 = wm*16 + ls, r1 = r0 + 8;
    #pragma unroll
    for (int ks=0; ks<8; ks++){
        qf[ks][0] = Qs[r0*QKW + ks*8 + lk];
        qf[ks][1] = Qs[r1*QKW + ks*8 + lk];
        qf[ks][2] = Qs[r0*QKW + ks*8 + lk + 4];
        qf[ks][3] = Qs[r1*QKW + ks*8 + lk + 4];
    }

    float oacc[8][4];
    #pragma unroll
    for (int i=0;i<8;i++){ oacc[i][0]=0.f; oacc[i][1]=0.f; oacc[i][2]=0.f; oacc[i][3]=0.f; }
    float den0 = 0.f, den1 = 0.f;
    float mqv = mq[bh*16 + it];

    for (int js=0; js<=it; js++){
        bool diag = (js == it);
        if (!diag && mqv + amaxT[bh*16 + js] < -20.f) continue;
        int s0 = js<<6;
        __syncthreads();
        const __nv_bfloat16* kg = k + ((size_t)(b*SEQ + s0))*512 + hh*128;
        const __nv_bfloat16* vg = v + ((size_t)(b*SEQ + s0))*512 + hh*128;
        #pragma unroll
        for (int r=0;r<4;r++){
            int idx = tid + (r<<8);
            int row = idx>>4, c16 = idx&15;
            uint4 kv = *(const uint4*)(kg + (size_t)row*512 + (c16<<3));
            uint4 vv = *(const uint4*)(vg + (size_t)row*512 + (c16<<3));
            *(uint4*)&Ks[row*QKW + (c16<<2)] = kv;
            *(uint4*)&Vs[row*VW + ((c16 ^ (row&7))<<2)] = vv;
        }
        if (tid < 64)
            as_[tid] = diag ? av[bh*SEQ + s0 + tid] : wcol[bh*SEQ + s0 + tid];
        __syncthreads();

        float sacc[4][4] = {};
        #pragma unroll
        for (int ks=0; ks<8; ks++){
            #pragma unroll
            for (int nt=0; nt<4; nt++){
                int sc = wn*32 + nt*8 + ls;
                uint32_t b0 = Ks[sc*QKW + ks*8 + lk];
                uint32_t b1 = Ks[sc*QKW + ks*8 + lk + 4];
                mma_bf16(sacc[nt], qf[ks], b0, b1);
            }
        }

        float f0 = fct[r0], mm0 = mt[r0], f1 = fct[r1], mm1 = mt[r1];
        if (!diag){
            float amx = amaxT[bh*16 + js];
            float w0 = __expf(f0 - mm0 + amx);
            float w1 = __expf(f1 - mm1 + amx);
            #pragma unroll
            for (int nt=0; nt<4; nt++){
                int c0 = wn*32 + nt*8 + (lk<<1);
                float wc0 = as_[c0], wc1 = as_[c0+1];
                float v00 = sacc[nt][0]*w0*wc0;
                float v01 = sacc[nt][1]*w0*wc1;
                float v10 = sacc[nt][2]*w1*wc0;
                float v11 = sacc[nt][3]*w1*wc1;
                den0 += v00 + v01;
                den1 += v10 + v11;
                int wcl = wn*16 + nt*4 + lk;
                Qs[r0*PW + wcl] = bf2pack(v00, v01);
                Qs[r1*PW + wcl] = bf2pack(v10, v11);
            }
        } else {
            #pragma unroll
            for (int nt=0; nt<4; nt++){
                int c0 = wn*32 + nt*8 + (lk<<1);
                int c1 = c0 + 1;
                float a0v = as_[c0], a1v = as_[c1];
                float v00 = sacc[nt][0]*scale*__expf(f0 + a0v - mm0);
                float v01 = sacc[nt][1]*scale*__expf(f0 + a1v - mm0);
                float v10 = sacc[nt][2]*scale*__expf(f1 + a0v - mm1);
                float v11 = sacc[nt][3]*scale*__expf(f1 + a1v - mm1);
                if (c0 > r0) v00 = 0.f;
                if (c1 > r0) v01 = 0.f;
                if (c0 > r1) v10 = 0.f;
                if (c1 > r1) v11 = 0.f;
                den0 += v00 + v01;
                den1 += v10 + v11;
                int wcl = wn*16 + nt*4 + lk;
                Qs[r0*PW + wcl] = bf2pack(v00, v01);
                Qs[r1*PW + wcl] = bf2pack(v10, v11);
            }
        }
        __syncthreads();

        #pragma unroll
        for (int ks2=0; ks2<4; ks2++){
            uint32_t af[4];
            af[0] = Qs[r0*PW + ks2*8 + lk];
            af[1] = Qs[r1*PW + ks2*8 + lk];
            af[2] = Qs[r0*PW + ks2*8 + lk + 4];
            af[3] = Qs[r1*PW + ks2*8 + lk + 4];
            int krow = (ks2<<4) + lr + ((g8&1)<<3);
            #pragma unroll
            for (int nt=0; nt<8; nt++){
                int cd = wn*8 + nt;
                uint32_t addr = smaddr(&Vs[krow*VW + ((cd ^ (krow&7))<<2)]);
                uint32_t b0, b1;
                asm volatile("ldmatrix.sync.aligned.m8n8.x2.trans.shared.b16 {%0,%1}, [%2];\n"
                    : "=r"(b0),"=r"(b1) : "r"(addr));
                mma_bf16(oacc[nt], af, b0, b1);
            }
        }
    }

    den0 += __shfl_xor_sync(0xffffffffu, den0, 1);
    den0 += __shfl_xor_sync(0xffffffffu, den0, 2);
    den1 += __shfl_xor_sync(0xffffffffu, den1, 1);
    den1 += __shfl_xor_sync(0xffffffffu, den1, 2);
    __syncthreads();
    if (lk == 0){ den2[wn*64 + r0] = den0; den2[wn*64 + r1] = den1; }
    __syncthreads();
    float dt0 = den2[r0] + den2[64 + r0];
    float dt1 = den2[r1] + den2[64 + r1];
    float inv0 = 1.f / (fmaxf(fabsf(dt0), __expf(-mt[r0])) + 1e-6f);
    float inv1 = 1.f / (fmaxf(fabsf(dt1), __expf(-mt[r1])) + 1e-6f);

    float hv0[16], hv1[16];
    #pragma unroll
    for (int nt=0; nt<8; nt++){
        hv0[nt*2]   = oacc[nt][0]*inv0;
        hv0[nt*2+1] = oacc[nt][1]*inv0;
        hv1[nt*2]   = oacc[nt][2]*inv1;
        hv1[nt*2+1] = oacc[nt][3]*inv1;
    }

    float s0 = 0.f, s1 = 0.f, q0 = 0.f, q1 = 0.f;
    #pragma unroll
    for (int i=0;i<16;i++){
        s0 += hv0[i]; q0 += hv0[i]*hv0[i];
        s1 += hv1[i]; q1 += hv1[i]*hv1[i];
    }
    #pragma unroll
    for (int o=1;o<4;o<<=1){
        s0 += __shfl_xor_sync(0xffffffffu, s0, o);
        q0 += __shfl_xor_sync(0xffffffffu, q0, o);
        s1 += __shfl_xor_sync(0xffffffffu, s1, o);
        q1 += __shfl_xor_sync(0xffffffffu, q1, o);
    }
    __syncthreads();
    if (lk == 0){
        den2[wn*64 + r0] = s0; den2[wn*64 + r1] = s1;
        dsq[wn*64 + r0]  = q0; dsq[wn*64 + r1]  = q1;
    }
    __syncthreads();
    float mu0 = (den2[r0] + den2[64 + r0]) * (1.f/128.f);
    float mu1 = (den2[r1] + den2[64 + r1]) * (1.f/128.f);
    float e20 = (dsq[r0] + dsq[64 + r0]) * (1.f/128.f);
    float e21 = (dsq[r1] + dsq[64 + r1]) * (1.f/128.f);
    float is0 = rsqrtf(e20 - mu0*mu0 + 1e-5f);
    float is1 = rsqrtf(e21 - mu1*mu1 + 1e-5f);

    size_t tok0 = (size_t)(b*SEQ + t0 + r0), tok1 = (size_t)(b*SEQ + t0 + r1);
    #pragma unroll
    for (int nt=0; nt<8; nt++){
        int dc = wn*64 + nt*8 + (lk<<1);
        int c = hh*128 + dc;
        float2 gg = *(const float2*)&gng[c];
        float2 gb = *(const float2*)&gnb[c];
        float2 sk = *(const float2*)&skip[c];
        float2 x0 = __bfloat1622float2(*(const __nv_bfloat162*)&xcbf[tok0*512 + c]);
        float2 x1 = __bfloat1622float2(*(const __nv_bfloat162*)&xcbf[tok1*512 + c]);
        float2 z0 = __bfloat1622float2(*(const __nv_bfloat162*)&upz[tok0*512 + c]);
        float2 z1 = __bfloat1622float2(*(const __nv_bfloat162*)&upz[tok1*512 + c]);
        float y00 = (hv0[nt*2]  -mu0)*is0*gg.x + gb.x + sk.x*x0.x;
        float y01 = (hv0[nt*2+1]-mu0)*is0*gg.y + gb.y + sk.y*x0.y;
        float y10 = (hv1[nt*2]  -mu1)*is1*gg.x + gb.x + sk.x*x1.x;
        float y11 = (hv1[nt*2+1]-mu1)*is1*gg.y + gb.y + sk.y*x1.y;
        y00 *= z0.x / (1.f + expf(-z0.x));
        y01 *= z0.y / (1.f + expf(-z0.y));
        y10 *= z1.x / (1.f + expf(-z1.x));
        y11 *= z1.y / (1.f + expf(-z1.y));
        *(__nv_bfloat162*)&out[tok0*512 + c] = __floats2bfloat162_rn(y00, y01);
        *(__nv_bfloat162*)&out[tok1*512 + c] = __floats2bfloat162_rn(y10, y11);
    }
}

// ---------------- final ----------------
__global__ void final_kernel(const float* __restrict__ h, const float* __restrict__ g,
                             const float* __restrict__ b, const float* __restrict__ Wf,
                             const float* __restrict__ bf, float* __restrict__ out){
    __shared__ float sh[8];
    __shared__ float sv;
    int bb = blockIdx.x, tid = threadIdx.x;
    float vv = h[((size_t)(bb*SEQ + SEQ-1))*256 + tid];
    float s = warp_sum(vv);
    if (!(tid&31)) sh[tid>>5] = s;
    __syncthreads();
    if (tid==0){ float t=0; for(int i=0;i<8;i++) t+=sh[i]; sv = t*(1.f/256.f); }
    __syncthreads();
    float mu = sv;
    float d = vv - mu;
    float s2 = warp_sum(d*d);
    if (!(tid&31)) sh[tid>>5] = s2;
    __syncthreads();
    if (tid==0){ float t=0; for(int i=0;i<8;i++) t+=sh[i]; sv = t*(1.f/256.f); }
    __syncthreads();
    float yn = d*rsqrtf(sv + 1e-5f)*g[tid] + b[tid];
    float p = yn * Wf[tid];
    float s3 = warp_sum(p);
    __syncthreads();
    if (!(tid&31)) sh[tid>>5] = s3;
    __syncthreads();
    if (tid==0){ float t=0; for(int i=0;i<8;i++) t+=sh[i]; out[bb] = t + bf[0]; }
}

// ---------------- launch ----------------
extern "C" void kernel_launch(void* const* d_in, const int* in_sizes, int n_in,
                              void* d_out, int out_size){
    const float* x    = (const float*)d_in[0];
    const float* tf   = (const float*)d_in[1];
    const float* Wp   = (const float*)d_in[2];
    const float* bp   = (const float*)d_in[3];
    const float* ln_g = (const float*)d_in[4];
    const float* ln_b = (const float*)d_in[5];
    const float* Wup  = (const float*)d_in[6];
    const float* bup  = (const float*)d_in[7];
    const float* cw   = (const float*)d_in[8];
    const float* cb   = (const float*)d_in[9];
    const float* Wq   = (const float*)d_in[10];
    const float* Wk   = (const float*)d_in[11];
    const float* Wv   = (const float*)d_in[12];
    const float* Wif  = (const float*)d_in[13];
    const float* bif  = (const float*)d_in[14];
    const float* gng  = (const float*)d_in[15];
    const float* gnb  = (const float*)d_in[16];
    const float* skip = (const float*)d_in[17];
    const float* Wdn  = (const float*)d_in[18];
    const float* bdn  = (const float*)d_in[19];
    const float* lnfg = (const float*)d_in[20];
    const float* lnfb = (const float*)d_in[21];
    const float* Wf   = (const float*)d_in[22];
    const float* bf   = (const float*)d_in[23];

    float *h,*up,*giT,*gfT,*Fc,*a,*m,*wcol,*amaxT,*mqp,*Wg;
    __nv_bfloat16 *hnbf,*xcbf,*upbf,*upzbf,*qbf,*kbf,*vbf,*att2bf,*wupbf,*wqbf,*wkbf,*wvbf,*wdnbf;
    cudaGetSymbolAddress((void**)&h,    g_h);
    cudaGetSymbolAddress((void**)&up,   g_up);
    cudaGetSymbolAddress((void**)&giT,  g_giT);
    cudaGetSymbolAddress((void**)&gfT,  g_gfT);
    cudaGetSymbolAddress((void**)&Fc,   g_Fc);
    cudaGetSymbolAddress((void**)&a,    g_a);
    cudaGetSymbolAddress((void**)&m,    g_m);
    cudaGetSymbolAddress((void**)&wcol, g_wcol);
    cudaGetSymbolAddress((void**)&amaxT,g_amaxT);
    cudaGetSymbolAddress((void**)&mqp,  g_mq);
    cudaGetSymbolAddress((void**)&Wg,   g_Wg);
    cudaGetSymbolAddress((void**)&hnbf, g_hn_bf);
    cudaGetSymbolAddress((void**)&xcbf, g_xc_bf);
    cudaGetSymbolAddress((void**)&upbf, g_up_bf);
    cudaGetSymbolAddress((void**)&upzbf,g_upz_bf);
    cudaGetSymbolAddress((void**)&qbf,  g_q_bf);
    cudaGetSymbolAddress((void**)&kbf,  g_k_bf);
    cudaGetSymbolAddress((void**)&vbf,  g_v_bf);
    cudaGetSymbolAddress((void**)&att2bf, g_att2_bf);
    cudaGetSymbolAddress((void**)&wupbf, g_wup_bf);
    cudaGetSymbolAddress((void**)&wqbf,  g_wq_bf);
    cudaGetSymbolAddress((void**)&wkbf,  g_wk_bf);
    cudaGetSymbolAddress((void**)&wvbf,  g_wv_bf);
    cudaGetSymbolAddress((void**)&wdnbf, g_wdn_bf);

    int attn_smem = (64*QKW + 64*QKW + 64*VW + 64 + 64 + 64 + 128 + 128) * 4;
    int gemm_smem = 65536;
    int down_smem = 81920;
    static int attr_set = 0;
    if (!attr_set){
        cudaFuncSetAttribute(attn_bf16, cudaFuncAttributeMaxDynamicSharedMemorySize, attn_smem);
        cudaFuncSetAttribute(gemm_bf16, cudaFuncAttributeMaxDynamicSharedMemorySize, gemm_smem);
        cudaFuncSetAttribute(gemm_down_ln, cudaFuncAttributeMaxDynamicSharedMemorySize, down_smem);
        attr_set = 1;
    }

    int n0 = NL*DMODEL*1024, n1 = NL*DI*DI, n4 = NL*DI*DMODEL;
    int ntot = n0 + 3*n1 + n4;
    f2bf5_kernel<<<(ntot/2 + 255)/256, 256>>>(Wup, wupbf, n0,
                                              Wq, wqbf, n1,
                                              Wk, wkbf, n1,
                                              Wv, wvbf, n1,
                                              Wdn, wdnbf, n4);
    gatew_kernel<<<NL*1024*8/256, 256>>>(Wq, Wk, Wv, Wif, Wg);

    embed_kernel<<<TOK*256/256, 256>>>(x, tf, Wp, bp, h);
    ln_kernel<<<TOK/8, 256>>>(h, ln_g, ln_b, hnbf);

    for (int l=0; l<NL; l++){
        gemm_bf16<<<dim3(1024/128, TOK/128, 1), 256, gemm_smem>>>(
            hnbf, 256, wupbf + (size_t)l*256*1024, 1024,
            up, 1024, bup + l*1024, nullptr, 256,
            upbf, 512, nullptr, nullptr, nullptr, nullptr, nullptr,
            upzbf, 512);
        conv_gates8_kernel<<<TOK/8, 256>>>(up, cw + l*4*512, cb + l*512,
                                           Wg + (size_t)l*8192, bif + l*8,
                                           xcbf, giT, gfT);
        gemm_bf16<<<dim3(512/128, TOK/128, 3), 256, gemm_smem>>>(
            xcbf, 512, wqbf + (size_t)l*512*512, 512,
            nullptr, 512, nullptr, nullptr, 512, qbf, 512,
            upbf,
            wkbf + (size_t)l*512*512, kbf,
            wvbf + (size_t)l*512*512, vbf,
            nullptr, 1024);
        scan_kernel4<<<32, 32>>>(giT, gfT, Fc, a, m, wcol, amaxT, mqp);
        attn_bf16<<<dim3(BATCH*NH, SEQ/64), 256, attn_smem>>>(qbf, kbf, vbf, Fc, a, m,
                                                  wcol, amaxT, mqp,
                                                  xcbf, upzbf, gng + l*512, gnb + l*512, skip + l*512,
                                                  att2bf);
        // down-GEMM with fused next-layer LN (last layer: no LN, final_kernel handles it)
        gemm_down_ln<<<dim3(1, TOK/64), 256, down_smem>>>(
            att2bf, wdnbf + (size_t)l*512*256,
            h, bdn + l*256,
            (l < NL-1) ? (ln_g + (l+1)*256) : nullptr,
            (l < NL-1) ? (ln_b + (l+1)*256) : nullptr,
            (l < NL-1) ? hnbf : nullptr);
    }
    final_kernel<<<BATCH, 256>>>(h, lnfg, lnfb, Wf, bf, (float*)d_out);
}